// round 6
// baseline (speedup 1.0000x reference)
#include <cuda_runtime.h>
#include <cuda_bf16.h>
#include <cuda_fp16.h>
#include <mma.h>
#include <cstdint>

using namespace nvcuda;

#define NN 50000
#define NP 50048          // 391 * 128
#define NE 800000
#define ET 850000         // NE + NN self loops
#define NS 0.2f
#define NBLK 196          // ceil(NN/256)

// ---------------- scratch (device globals) -----------------------------------
__device__ __half g_h1h[NN * 128];
__device__ float  g_out1[NN * 128];
__device__ float  g_as1[NN * 4];
__device__ float  g_ad1[NN * 4];
__device__ __half g_h2h[NN * 64];
__device__ float  g_as2[NN];
__device__ float  g_ad2[NN];
__device__ int g_deg[NN];        // invariant: zero before/after every call
__device__ int g_off[NN + 1];
__device__ int g_cur[NN];
__device__ int g_srcidx[ET];
__device__ int g_bsum[NBLK];
__device__ int g_boff[NBLK];

__device__ __forceinline__ float lrelu(float v) { return v >= 0.f ? v : NS * v; }

// ---------------- CSR construction ------------------------------------------
__global__ void k_hist(const int* __restrict__ ei) {
    int i = blockIdx.x * blockDim.x + threadIdx.x;
    if (i >= NE / 4) return;
    int4 d4 = ((const int4*)(ei + NE))[i];
    atomicAdd(&g_deg[d4.x], 1);
    atomicAdd(&g_deg[d4.y], 1);
    atomicAdd(&g_deg[d4.z], 1);
    atomicAdd(&g_deg[d4.w], 1);
}

__global__ void k_scanA() {
    __shared__ int sh[256];
    int i = blockIdx.x * 256 + threadIdx.x;
    sh[threadIdx.x] = (i < NN) ? g_deg[i] + 1 : 0;   // +1 self loop
    __syncthreads();
#pragma unroll
    for (int o = 128; o >= 1; o >>= 1) {
        if (threadIdx.x < o) sh[threadIdx.x] += sh[threadIdx.x + o];
        __syncthreads();
    }
    if (threadIdx.x == 0) g_bsum[blockIdx.x] = sh[0];
}

__global__ void k_scanB() {
    __shared__ int sh[256];
    int t = threadIdx.x;
    int v = (t < NBLK) ? g_bsum[t] : 0;
    sh[t] = v;
    __syncthreads();
#pragma unroll
    for (int o = 1; o < 256; o <<= 1) {
        int tv = (t >= o) ? sh[t - o] : 0;
        __syncthreads();
        sh[t] += tv;
        __syncthreads();
    }
    if (t < NBLK) g_boff[t] = sh[t] - v;   // exclusive
    if (t == 0) g_off[NN] = ET;
}

__global__ void k_scanC() {
    __shared__ int sh[256];
    int t = threadIdx.x;
    int i = blockIdx.x * 256 + t;
    int v = (i < NN) ? g_deg[i] + 1 : 0;
    sh[t] = v;
    __syncthreads();
#pragma unroll
    for (int o = 1; o < 256; o <<= 1) {
        int tv = (t >= o) ? sh[t - o] : 0;
        __syncthreads();
        sh[t] += tv;
        __syncthreads();
    }
    if (i < NN) {
        int off = g_boff[blockIdx.x] + sh[t] - v;
        g_off[i] = off;
        g_srcidx[off] = i;      // self loop seeded first
        g_cur[i] = off + 1;
        g_deg[i] = 0;           // restore invariant for next call
    }
}

__global__ void k_fill(const int* __restrict__ ei) {
    int i = blockIdx.x * blockDim.x + threadIdx.x;
    if (i >= NE / 4) return;
    int4 s4 = ((const int4*)ei)[i];
    int4 d4 = ((const int4*)(ei + NE))[i];
    int p;
    p = atomicAdd(&g_cur[d4.x], 1); g_srcidx[p] = s4.x;
    p = atomicAdd(&g_cur[d4.y], 1); g_srcidx[p] = s4.y;
    p = atomicAdd(&g_cur[d4.z], 1); g_srcidx[p] = s4.z;
    p = atomicAdd(&g_cur[d4.w], 1); g_srcidx[p] = s4.w;
}

// ---------------- GEMM1: [h1 | as1 | ad1] = x @ [W1 | W1@P] -------------------
// 256 thr (8 warps), M-tile 128, N=144; W split to smem per CTA
#define LDA 136
#define LDW1 152
#define ST1 148
__global__ __launch_bounds__(256)
void k_gemm1_mma(const float* __restrict__ X, const float* __restrict__ W1,
                 const float* __restrict__ as1, const float* __restrict__ ad1) {
    extern __shared__ char raw[];
    __nv_bfloat16* sAh = (__nv_bfloat16*)raw;
    __nv_bfloat16* sAl = sAh + 128 * LDA;
    __nv_bfloat16* sWh = (__nv_bfloat16*)(raw + 4 * 128 * LDA);
    __nv_bfloat16* sWl = sWh + 128 * LDW1;
    float* stage = (float*)raw;
    int tid = threadIdx.x;
    int row0 = blockIdx.x * 128;

    // W tile: cols 0..127 = W1, 128..135 = W1@P (alpha), 136..143 = 0
    for (int i = tid; i < 128 * 144; i += 256) {
        int k = i / 144, n = i % 144;
        float val;
        if (n < 128) val = W1[k * 128 + n];
        else if (n < 136) {
            int c = n - 128, h = c >> 1;
            const float* a = (c & 1) ? ad1 : as1;
            float s = 0.f;
#pragma unroll
            for (int f = 0; f < 32; f++) s += W1[k * 128 + h * 32 + f] * a[h * 32 + f];
            val = s;
        } else val = 0.f;
        __nv_bfloat16 hi = __float2bfloat16(val);
        sWh[k * LDW1 + n] = hi;
        sWl[k * LDW1 + n] = __float2bfloat16(val - __bfloat162float(hi));
    }
    // A tile (fp32 -> bf16 hi/lo)
    for (int i = tid; i < 4096; i += 256) {
        int r = i >> 5, c4 = i & 31;
        float4 v = make_float4(0.f, 0.f, 0.f, 0.f);
        if (row0 + r < NN) v = ((const float4*)X)[(size_t)(row0 + r) * 32 + c4];
        int base = r * LDA + c4 * 4;
        float vv[4] = {v.x, v.y, v.z, v.w};
#pragma unroll
        for (int j = 0; j < 4; j++) {
            __nv_bfloat16 h = __float2bfloat16(vv[j]);
            sAh[base + j] = h;
            sAl[base + j] = __float2bfloat16(vv[j] - __bfloat162float(h));
        }
    }
    __syncthreads();

    int w = tid >> 5;
    wmma::fragment<wmma::accumulator, 16, 16, 16, float> c[9];
#pragma unroll
    for (int j = 0; j < 9; j++) wmma::fill_fragment(c[j], 0.f);

    for (int kk = 0; kk < 128; kk += 16) {
        wmma::fragment<wmma::matrix_a, 16, 16, 16, __nv_bfloat16, wmma::row_major> ah, al;
        wmma::load_matrix_sync(ah, sAh + (w * 16) * LDA + kk, LDA);
        wmma::load_matrix_sync(al, sAl + (w * 16) * LDA + kk, LDA);
#pragma unroll
        for (int j = 0; j < 9; j++) {
            wmma::fragment<wmma::matrix_b, 16, 16, 16, __nv_bfloat16, wmma::row_major> bh, bl;
            wmma::load_matrix_sync(bh, sWh + kk * LDW1 + j * 16, LDW1);
            wmma::load_matrix_sync(bl, sWl + kk * LDW1 + j * 16, LDW1);
            wmma::mma_sync(c[j], ah, bh, c[j]);
            wmma::mma_sync(c[j], al, bh, c[j]);
            wmma::mma_sync(c[j], ah, bl, c[j]);
        }
    }
    __syncthreads();   // reuse smem as stage
#pragma unroll
    for (int j = 0; j < 9; j++)
        wmma::store_matrix_sync(stage + (w * 16) * ST1 + j * 16, c[j], ST1, wmma::mem_row_major);
    __syncthreads();

    {
        int r = tid >> 1, half = tid & 1;
        int row = row0 + r;
        if (row < NN) {
            const float* sp = stage + r * ST1 + half * 64;
            uint4* dp = (uint4*)(g_h1h + (size_t)row * 128 + half * 64);
#pragma unroll
            for (int q = 0; q < 8; q++) {
                float4 a = *(const float4*)(sp + 8 * q);
                float4 b = *(const float4*)(sp + 8 * q + 4);
                __half2 h0 = __floats2half2_rn(a.x, a.y);
                __half2 h1 = __floats2half2_rn(a.z, a.w);
                __half2 h2 = __floats2half2_rn(b.x, b.y);
                __half2 h3 = __floats2half2_rn(b.z, b.w);
                uint4 u;
                u.x = *(uint32_t*)&h0; u.y = *(uint32_t*)&h1;
                u.z = *(uint32_t*)&h2; u.w = *(uint32_t*)&h3;
                dp[q] = u;
            }
        }
    }
    if (tid < 128) {
        int row = row0 + tid;
        if (row < NN) {
            const float* sp = stage + tid * ST1 + 128;
#pragma unroll
            for (int h = 0; h < 4; h++) {
                g_as1[row * 4 + h] = sp[2 * h];
                g_ad1[row * 4 + h] = sp[2 * h + 1];
            }
        }
    }
}

// ---------------- GEMM2: [h2 | as2 | ad2] = relu(out1) @ [W2 | W2@P2] ---------
#define LDW2 88
#define ST2 84
__global__ __launch_bounds__(256)
void k_gemm2_mma(const float* __restrict__ W2,
                 const float* __restrict__ as2, const float* __restrict__ ad2) {
    extern __shared__ char raw[];
    __nv_bfloat16* sAh = (__nv_bfloat16*)raw;
    __nv_bfloat16* sAl = sAh + 128 * LDA;
    __nv_bfloat16* sWh = (__nv_bfloat16*)(raw + 4 * 128 * LDA);
    __nv_bfloat16* sWl = sWh + 128 * LDW2;
    float* stage = (float*)raw;
    int tid = threadIdx.x;
    int row0 = blockIdx.x * 128;

    // W tile: cols 0..63 = W2, 64..65 = W2@P2, 66..79 = 0
    for (int i = tid; i < 128 * 80; i += 256) {
        int k = i / 80, n = i % 80;
        float val;
        if (n < 64) val = W2[k * 64 + n];
        else if (n < 66) {
            const float* a = (n & 1) ? ad2 : as2;
            float s = 0.f;
#pragma unroll
            for (int f = 0; f < 64; f++) s += W2[k * 64 + f] * a[f];
            val = s;
        } else val = 0.f;
        __nv_bfloat16 hi = __float2bfloat16(val);
        sWh[k * LDW2 + n] = hi;
        sWl[k * LDW2 + n] = __float2bfloat16(val - __bfloat162float(hi));
    }
    for (int i = tid; i < 4096; i += 256) {
        int r = i >> 5, c4 = i & 31;
        float4 v = make_float4(0.f, 0.f, 0.f, 0.f);
        if (row0 + r < NN) v = ((const float4*)g_out1)[(size_t)(row0 + r) * 32 + c4];
        int base = r * LDA + c4 * 4;
        float vv[4] = {fmaxf(v.x, 0.f), fmaxf(v.y, 0.f), fmaxf(v.z, 0.f), fmaxf(v.w, 0.f)};
#pragma unroll
        for (int j = 0; j < 4; j++) {
            __nv_bfloat16 h = __float2bfloat16(vv[j]);
            sAh[base + j] = h;
            sAl[base + j] = __float2bfloat16(vv[j] - __bfloat162float(h));
        }
    }
    __syncthreads();

    int w = tid >> 5;
    wmma::fragment<wmma::accumulator, 16, 16, 16, float> c[5];
#pragma unroll
    for (int j = 0; j < 5; j++) wmma::fill_fragment(c[j], 0.f);

    for (int kk = 0; kk < 128; kk += 16) {
        wmma::fragment<wmma::matrix_a, 16, 16, 16, __nv_bfloat16, wmma::row_major> ah, al;
        wmma::load_matrix_sync(ah, sAh + (w * 16) * LDA + kk, LDA);
        wmma::load_matrix_sync(al, sAl + (w * 16) * LDA + kk, LDA);
#pragma unroll
        for (int j = 0; j < 5; j++) {
            wmma::fragment<wmma::matrix_b, 16, 16, 16, __nv_bfloat16, wmma::row_major> bh, bl;
            wmma::load_matrix_sync(bh, sWh + kk * LDW2 + j * 16, LDW2);
            wmma::load_matrix_sync(bl, sWl + kk * LDW2 + j * 16, LDW2);
            wmma::mma_sync(c[j], ah, bh, c[j]);
            wmma::mma_sync(c[j], al, bh, c[j]);
            wmma::mma_sync(c[j], ah, bl, c[j]);
        }
    }
    __syncthreads();
#pragma unroll
    for (int j = 0; j < 5; j++)
        wmma::store_matrix_sync(stage + (w * 16) * ST2 + j * 16, c[j], ST2, wmma::mem_row_major);
    __syncthreads();

    {
        int r = tid >> 1, half = tid & 1;
        int row = row0 + r;
        if (row < NN) {
            const float* sp = stage + r * ST2 + half * 32;
            uint4* dp = (uint4*)(g_h2h + (size_t)row * 64 + half * 32);
#pragma unroll
            for (int q = 0; q < 4; q++) {
                float4 a = *(const float4*)(sp + 8 * q);
                float4 b = *(const float4*)(sp + 8 * q + 4);
                __half2 h0 = __floats2half2_rn(a.x, a.y);
                __half2 h1 = __floats2half2_rn(a.z, a.w);
                __half2 h2 = __floats2half2_rn(b.x, b.y);
                __half2 h3 = __floats2half2_rn(b.z, b.w);
                uint4 u;
                u.x = *(uint32_t*)&h0; u.y = *(uint32_t*)&h1;
                u.z = *(uint32_t*)&h2; u.w = *(uint32_t*)&h3;
                dp[q] = u;
            }
        }
    }
    if (tid < 128) {
        int row = row0 + tid;
        if (row < NN) {
            g_as2[row] = stage[tid * ST2 + 64];
            g_ad2[row] = stage[tid * ST2 + 65];
        }
    }
}

// ---------------- gather1: two-phase softmax aggregation (4 heads, fp16 h) ---
__global__ __launch_bounds__(256)
void k_gather1(const float* __restrict__ b1) {
    int n = blockIdx.x * 8 + (threadIdx.x >> 5);
    if (n >= NN) return;
    int lane = threadIdx.x & 31, h = lane >> 3;
    float adh = g_ad1[4 * n + h];
    int beg = g_off[n], end = g_off[n + 1];

    float4 mx = make_float4(-3.4e38f, -3.4e38f, -3.4e38f, -3.4e38f);
    for (int j = beg + lane; j < end; j += 32) {
        int s = g_srcidx[j];
        float4 a = *(const float4*)(g_as1 + 4 * s);
        mx.x = fmaxf(mx.x, a.x); mx.y = fmaxf(mx.y, a.y);
        mx.z = fmaxf(mx.z, a.z); mx.w = fmaxf(mx.w, a.w);
    }
#pragma unroll
    for (int o = 16; o >= 1; o >>= 1) {
        mx.x = fmaxf(mx.x, __shfl_xor_sync(0xffffffffu, mx.x, o));
        mx.y = fmaxf(mx.y, __shfl_xor_sync(0xffffffffu, mx.y, o));
        mx.z = fmaxf(mx.z, __shfl_xor_sync(0xffffffffu, mx.z, o));
        mx.w = fmaxf(mx.w, __shfl_xor_sync(0xffffffffu, mx.w, o));
    }
    float mh = (h == 0) ? mx.x : (h == 1) ? mx.y : (h == 2) ? mx.z : mx.w;
    mh = lrelu(mh + adh);

    float4 acc = make_float4(0.f, 0.f, 0.f, 0.f);
    float den = 0.f;
    int s0 = 0; float a0 = 0.f; uint2 u0 = make_uint2(0, 0);
    if (beg < end) {
        s0 = g_srcidx[beg];
        a0 = g_as1[4 * s0 + h];
        u0 = *(const uint2*)(g_h1h + (size_t)s0 * 128 + 4 * lane);
    }
    for (int j = beg; j < end; j++) {
        int s1 = 0; float a1 = 0.f; uint2 u1 = make_uint2(0, 0);
        if (j + 1 < end) {
            s1 = g_srcidx[j + 1];
            a1 = g_as1[4 * s1 + h];
            u1 = *(const uint2*)(g_h1h + (size_t)s1 * 128 + 4 * lane);
        }
        float w = __expf(lrelu(a0 + adh) - mh);
        den += w;
        float2 f0 = __half22float2(*(__half2*)&u0.x);
        float2 f1 = __half22float2(*(__half2*)&u0.y);
        acc.x += w * f0.x; acc.y += w * f0.y;
        acc.z += w * f1.x; acc.w += w * f1.y;
        s0 = s1; a0 = a1; u0 = u1;
    }
    float inv = 1.f / (den + 1e-16f);
    float4 bv = *(const float4*)(b1 + 4 * lane);
    *(float4*)(g_out1 + (size_t)n * 128 + 4 * lane) =
        make_float4(acc.x * inv + bv.x, acc.y * inv + bv.y,
                    acc.z * inv + bv.z, acc.w * inv + bv.w);
}

// ---------------- gather2: two-phase (1 head, fp16 h) -------------------------
__global__ __launch_bounds__(256)
void k_gather2(const float* __restrict__ b2, float* __restrict__ out) {
    int n = blockIdx.x * 8 + (threadIdx.x >> 5);
    if (n >= NN) return;
    int lane = threadIdx.x & 31;
    float adh = g_ad2[n];
    int beg = g_off[n], end = g_off[n + 1];

    float mx = -3.4e38f;
    for (int j = beg + lane; j < end; j += 32)
        mx = fmaxf(mx, g_as2[g_srcidx[j]]);
#pragma unroll
    for (int o = 16; o >= 1; o >>= 1)
        mx = fmaxf(mx, __shfl_xor_sync(0xffffffffu, mx, o));
    float mh = lrelu(mx + adh);

    float2 acc = make_float2(0.f, 0.f);
    float den = 0.f;
    int s0 = 0; float a0 = 0.f; uint32_t u0 = 0;
    if (beg < end) {
        s0 = g_srcidx[beg];
        a0 = g_as2[s0];
        u0 = *(const uint32_t*)(g_h2h + (size_t)s0 * 64 + 2 * lane);
    }
    for (int j = beg; j < end; j++) {
        int s1 = 0; float a1 = 0.f; uint32_t u1 = 0;
        if (j + 1 < end) {
            s1 = g_srcidx[j + 1];
            a1 = g_as2[s1];
            u1 = *(const uint32_t*)(g_h2h + (size_t)s1 * 64 + 2 * lane);
        }
        float w = __expf(lrelu(a0 + adh) - mh);
        den += w;
        float2 f = __half22float2(*(__half2*)&u0);
        acc.x += w * f.x; acc.y += w * f.y;
        s0 = s1; a0 = a1; u0 = u1;
    }
    float inv = 1.f / (den + 1e-16f);
    float2 bv = *(const float2*)(b2 + 2 * lane);
    *(float2*)(out + (size_t)n * 64 + 2 * lane) =
        make_float2(acc.x * inv + bv.x, acc.y * inv + bv.y);
}

// ---------------- launch ------------------------------------------------------
extern "C" void kernel_launch(void* const* d_in, const int* in_sizes, int n_in,
                              void* d_out, int out_size) {
    const float* x   = (const float*)d_in[0];
    const int*   ei  = (const int*)d_in[1];
    const float* W1  = (const float*)d_in[2];
    const float* as1 = (const float*)d_in[3];
    const float* ad1 = (const float*)d_in[4];
    const float* b1  = (const float*)d_in[5];
    const float* W2  = (const float*)d_in[6];
    const float* as2 = (const float*)d_in[7];
    const float* ad2 = (const float*)d_in[8];
    const float* b2  = (const float*)d_in[9];
    float* out = (float*)d_out;

    const int smem1 = 4 * 128 * LDA + 4 * 128 * LDW1;   // 69632 + 77824 = 147456
    const int smem2 = 4 * 128 * LDA + 4 * 128 * LDW2;   // 69632 + 45056 = 114688
    static bool attr_done = false;
    if (!attr_done) {
        cudaFuncSetAttribute(k_gemm1_mma, cudaFuncAttributeMaxDynamicSharedMemorySize, smem1);
        cudaFuncSetAttribute(k_gemm2_mma, cudaFuncAttributeMaxDynamicSharedMemorySize, smem2);
        attr_done = true;
    }

    // CSR build (g_deg is zero on entry; scanC restores it)
    k_hist<<<(NE / 4 + 255) / 256, 256>>>(ei);
    k_scanA<<<NBLK, 256>>>();
    k_scanB<<<1, 256>>>();
    k_scanC<<<NBLK, 256>>>();
    k_fill<<<(NE / 4 + 255) / 256, 256>>>(ei);

    // layer 1
    k_gemm1_mma<<<NP / 128, 256, smem1>>>(x, W1, as1, ad1);
    k_gather1<<<(NN + 7) / 8, 256>>>(b1);

    // layer 2
    k_gemm2_mma<<<NP / 128, 256, smem2>>>(W2, as2, ad2);
    k_gather2<<<(NN + 7) / 8, 256>>>(b2, out);
}

// round 7
// speedup vs baseline: 1.6421x; 1.6421x over previous
#include <cuda_runtime.h>
#include <cuda_bf16.h>
#include <cuda_fp16.h>
#include <mma.h>
#include <cstdint>

using namespace nvcuda;

#define NN 50000
#define NP 50048          // 391 * 128
#define NE 800000
#define ET 850000         // NE + NN self loops
#define NS 0.2f
#define NBLK 196          // ceil(NN/256)

// ---------------- scratch (device globals) -----------------------------------
__device__ __half g_h1h[NN * 128];
__device__ float  g_out1[NN * 128];
__device__ float  g_as1[NN * 4];
__device__ float  g_ad1[NN * 4];
__device__ __half g_h2h[NN * 64];
__device__ float  g_as2[NN];
__device__ float  g_ad2[NN];
__device__ int g_deg[NN];        // invariant: zero before/after every call
__device__ int g_off[NN + 1];
__device__ int g_cur[NN];
__device__ int g_srcidx[ET];
__device__ int g_bsum[NBLK];
__device__ int g_boff[NBLK];
// bf16-split weights with fused alpha columns (pre-converted once per call)
__device__ __nv_bfloat16 g_w1h[128 * 144];
__device__ __nv_bfloat16 g_w1l[128 * 144];
__device__ __nv_bfloat16 g_w2h[128 * 80];
__device__ __nv_bfloat16 g_w2l[128 * 80];

__device__ __forceinline__ float lrelu(float v) { return v >= 0.f ? v : NS * v; }

// ---------------- weight conversion + fused alpha columns ---------------------
__global__ void k_convw(const float* __restrict__ W1, const float* __restrict__ W2,
                        const float* __restrict__ as1, const float* __restrict__ ad1,
                        const float* __restrict__ as2, const float* __restrict__ ad2) {
    int s = blockIdx.x * blockDim.x + threadIdx.x;
    float val; int dsth = -1, dstl = -1;
    if (s < 16384) {                       // W1 copy
        int k = s >> 7, n = s & 127;
        val = W1[k * 128 + n];
        dsth = k * 144 + n; dstl = 1;
    } else if (s < 17408) {                // W1 @ P (alpha cols)
        int i = s - 16384;
        int k = i >> 3, c = i & 7, h = c >> 1;
        const float* a = (c & 1) ? ad1 : as1;
        float sum = 0.f;
#pragma unroll
        for (int f = 0; f < 32; f++) sum += W1[k * 128 + h * 32 + f] * a[h * 32 + f];
        val = sum; dsth = k * 144 + 128 + c; dstl = 1;
    } else if (s < 18432) {                // W1 zero pad
        int i = s - 17408;
        int k = i >> 3, c = i & 7;
        val = 0.f; dsth = k * 144 + 136 + c; dstl = 1;
    } else if (s < 26624) {                // W2 copy
        int i = s - 18432;
        int k = i >> 6, n = i & 63;
        val = W2[k * 64 + n];
        dsth = k * 80 + n; dstl = 2;
    } else if (s < 26880) {                // W2 @ P2
        int i = s - 26624;
        int k = i >> 1, c = i & 1;
        const float* a = c ? ad2 : as2;
        float sum = 0.f;
#pragma unroll
        for (int f = 0; f < 64; f++) sum += W2[k * 64 + f] * a[f];
        val = sum; dsth = k * 80 + 64 + c; dstl = 2;
    } else if (s < 28672) {                // W2 zero pad
        int i = s - 26880;
        int k = i / 14, c = i % 14;
        val = 0.f; dsth = k * 80 + 66 + c; dstl = 2;
    } else return;
    __nv_bfloat16 hi = __float2bfloat16(val);
    __nv_bfloat16 lo = __float2bfloat16(val - __bfloat162float(hi));
    if (dstl == 1) { g_w1h[dsth] = hi; g_w1l[dsth] = lo; }
    else           { g_w2h[dsth] = hi; g_w2l[dsth] = lo; }
}

// ---------------- CSR construction ------------------------------------------
__global__ void k_hist(const int* __restrict__ ei) {
    int i = blockIdx.x * blockDim.x + threadIdx.x;
    if (i >= NE / 4) return;
    int4 d4 = ((const int4*)(ei + NE))[i];
    atomicAdd(&g_deg[d4.x], 1);
    atomicAdd(&g_deg[d4.y], 1);
    atomicAdd(&g_deg[d4.z], 1);
    atomicAdd(&g_deg[d4.w], 1);
}

__global__ void k_scanA() {
    __shared__ int sh[256];
    int i = blockIdx.x * 256 + threadIdx.x;
    sh[threadIdx.x] = (i < NN) ? g_deg[i] + 1 : 0;   // +1 self loop
    __syncthreads();
#pragma unroll
    for (int o = 128; o >= 1; o >>= 1) {
        if (threadIdx.x < o) sh[threadIdx.x] += sh[threadIdx.x + o];
        __syncthreads();
    }
    if (threadIdx.x == 0) g_bsum[blockIdx.x] = sh[0];
}

__global__ void k_scanB() {
    __shared__ int sh[256];
    int t = threadIdx.x;
    int v = (t < NBLK) ? g_bsum[t] : 0;
    sh[t] = v;
    __syncthreads();
#pragma unroll
    for (int o = 1; o < 256; o <<= 1) {
        int tv = (t >= o) ? sh[t - o] : 0;
        __syncthreads();
        sh[t] += tv;
        __syncthreads();
    }
    if (t < NBLK) g_boff[t] = sh[t] - v;   // exclusive
    if (t == 0) g_off[NN] = ET;
}

__global__ void k_scanC() {
    __shared__ int sh[256];
    int t = threadIdx.x;
    int i = blockIdx.x * 256 + t;
    int v = (i < NN) ? g_deg[i] + 1 : 0;
    sh[t] = v;
    __syncthreads();
#pragma unroll
    for (int o = 1; o < 256; o <<= 1) {
        int tv = (t >= o) ? sh[t - o] : 0;
        __syncthreads();
        sh[t] += tv;
        __syncthreads();
    }
    if (i < NN) {
        int off = g_boff[blockIdx.x] + sh[t] - v;
        g_off[i] = off;
        g_srcidx[off] = i;      // self loop seeded first
        g_cur[i] = off + 1;
        g_deg[i] = 0;           // restore invariant for next call
    }
}

__global__ void k_fill(const int* __restrict__ ei) {
    int i = blockIdx.x * blockDim.x + threadIdx.x;
    if (i >= NE / 4) return;
    int4 s4 = ((const int4*)ei)[i];
    int4 d4 = ((const int4*)(ei + NE))[i];
    int p;
    p = atomicAdd(&g_cur[d4.x], 1); g_srcidx[p] = s4.x;
    p = atomicAdd(&g_cur[d4.y], 1); g_srcidx[p] = s4.y;
    p = atomicAdd(&g_cur[d4.z], 1); g_srcidx[p] = s4.z;
    p = atomicAdd(&g_cur[d4.w], 1); g_srcidx[p] = s4.w;
}

// ---------------- GEMM1: [h1 | as1 | ad1] = x @ [W1 | W1@P] -------------------
// 256 thr = 4x2 warp grid; warp = 32 rows x (80|64) cols
#define LDA 136
#define ST1 148
__global__ __launch_bounds__(256)
void k_gemm1_mma(const float* __restrict__ X) {
    extern __shared__ char raw[];
    __nv_bfloat16* sAh = (__nv_bfloat16*)raw;
    __nv_bfloat16* sAl = sAh + 128 * LDA;
    float* stage = (float*)raw;
    int tid = threadIdx.x;
    int row0 = blockIdx.x * 128;

    for (int i = tid; i < 4096; i += 256) {
        int r = i >> 5, c4 = i & 31;
        float4 v = make_float4(0.f, 0.f, 0.f, 0.f);
        if (row0 + r < NN) v = ((const float4*)X)[(size_t)(row0 + r) * 32 + c4];
        int base = r * LDA + c4 * 4;
        float vv[4] = {v.x, v.y, v.z, v.w};
#pragma unroll
        for (int j = 0; j < 4; j++) {
            __nv_bfloat16 h = __float2bfloat16(vv[j]);
            sAh[base + j] = h;
            sAl[base + j] = __float2bfloat16(vv[j] - __bfloat162float(h));
        }
    }
    __syncthreads();

    int w = tid >> 5, wr = w >> 1, wc = w & 1;
    const int nf = wc ? 4 : 5;          // col frags: 5 (cols 0-79) | 4 (cols 80-143)
    const int col0 = wc * 80;

    wmma::fragment<wmma::accumulator, 16, 16, 16, float> c[2][5];
#pragma unroll
    for (int i = 0; i < 2; i++)
#pragma unroll
        for (int j = 0; j < 5; j++) wmma::fill_fragment(c[i][j], 0.f);

    for (int kk = 0; kk < 128; kk += 16) {
        wmma::fragment<wmma::matrix_a, 16, 16, 16, __nv_bfloat16, wmma::row_major> ah[2], al[2];
#pragma unroll
        for (int i = 0; i < 2; i++) {
            wmma::load_matrix_sync(ah[i], sAh + (wr * 32 + i * 16) * LDA + kk, LDA);
            wmma::load_matrix_sync(al[i], sAl + (wr * 32 + i * 16) * LDA + kk, LDA);
        }
#pragma unroll
        for (int j = 0; j < 5; j++) {
            if (j >= nf) break;
            wmma::fragment<wmma::matrix_b, 16, 16, 16, __nv_bfloat16, wmma::row_major> bh, bl;
            wmma::load_matrix_sync(bh, g_w1h + kk * 144 + col0 + j * 16, 144);
            wmma::load_matrix_sync(bl, g_w1l + kk * 144 + col0 + j * 16, 144);
#pragma unroll
            for (int i = 0; i < 2; i++) {
                wmma::mma_sync(c[i][j], ah[i], bh, c[i][j]);
                wmma::mma_sync(c[i][j], al[i], bh, c[i][j]);
                wmma::mma_sync(c[i][j], ah[i], bl, c[i][j]);
            }
        }
    }
    __syncthreads();   // reuse smem as stage
#pragma unroll
    for (int i = 0; i < 2; i++)
#pragma unroll
        for (int j = 0; j < 5; j++) {
            if (j >= nf) break;
            wmma::store_matrix_sync(stage + (wr * 32 + i * 16) * ST1 + col0 + j * 16,
                                    c[i][j], ST1, wmma::mem_row_major);
        }
    __syncthreads();

    {
        int r = tid >> 1, half = tid & 1;
        int row = row0 + r;
        if (row < NN) {
            const float* sp = stage + r * ST1 + half * 64;
            uint4* dp = (uint4*)(g_h1h + (size_t)row * 128 + half * 64);
#pragma unroll
            for (int q = 0; q < 8; q++) {
                float4 a = *(const float4*)(sp + 8 * q);
                float4 b = *(const float4*)(sp + 8 * q + 4);
                __half2 h0 = __floats2half2_rn(a.x, a.y);
                __half2 h1 = __floats2half2_rn(a.z, a.w);
                __half2 h2 = __floats2half2_rn(b.x, b.y);
                __half2 h3 = __floats2half2_rn(b.z, b.w);
                uint4 u;
                u.x = *(uint32_t*)&h0; u.y = *(uint32_t*)&h1;
                u.z = *(uint32_t*)&h2; u.w = *(uint32_t*)&h3;
                dp[q] = u;
            }
        }
    }
    if (tid < 128) {
        int row = row0 + tid;
        if (row < NN) {
            const float* sp = stage + tid * ST1 + 128;
#pragma unroll
            for (int h = 0; h < 4; h++) {
                g_as1[row * 4 + h] = sp[2 * h];
                g_ad1[row * 4 + h] = sp[2 * h + 1];
            }
        }
    }
}

// ---------------- GEMM2: [h2 | as2 | ad2] = relu(out1) @ [W2 | W2@P2] ---------
#define ST2 84
__global__ __launch_bounds__(256)
void k_gemm2_mma() {
    extern __shared__ char raw[];
    __nv_bfloat16* sAh = (__nv_bfloat16*)raw;
    __nv_bfloat16* sAl = sAh + 128 * LDA;
    float* stage = (float*)raw;
    int tid = threadIdx.x;
    int row0 = blockIdx.x * 128;

    for (int i = tid; i < 4096; i += 256) {
        int r = i >> 5, c4 = i & 31;
        float4 v = make_float4(0.f, 0.f, 0.f, 0.f);
        if (row0 + r < NN) v = ((const float4*)g_out1)[(size_t)(row0 + r) * 32 + c4];
        int base = r * LDA + c4 * 4;
        float vv[4] = {fmaxf(v.x, 0.f), fmaxf(v.y, 0.f), fmaxf(v.z, 0.f), fmaxf(v.w, 0.f)};
#pragma unroll
        for (int j = 0; j < 4; j++) {
            __nv_bfloat16 h = __float2bfloat16(vv[j]);
            sAh[base + j] = h;
            sAl[base + j] = __float2bfloat16(vv[j] - __bfloat162float(h));
        }
    }
    __syncthreads();

    int w = tid >> 5, wr = w >> 1, wc = w & 1;
    const int nf = wc ? 2 : 3;          // col frags: 3 (cols 0-47) | 2 (cols 48-79)
    const int col0 = wc * 48;

    wmma::fragment<wmma::accumulator, 16, 16, 16, float> c[2][3];
#pragma unroll
    for (int i = 0; i < 2; i++)
#pragma unroll
        for (int j = 0; j < 3; j++) wmma::fill_fragment(c[i][j], 0.f);

    for (int kk = 0; kk < 128; kk += 16) {
        wmma::fragment<wmma::matrix_a, 16, 16, 16, __nv_bfloat16, wmma::row_major> ah[2], al[2];
#pragma unroll
        for (int i = 0; i < 2; i++) {
            wmma::load_matrix_sync(ah[i], sAh + (wr * 32 + i * 16) * LDA + kk, LDA);
            wmma::load_matrix_sync(al[i], sAl + (wr * 32 + i * 16) * LDA + kk, LDA);
        }
#pragma unroll
        for (int j = 0; j < 3; j++) {
            if (j >= nf) break;
            wmma::fragment<wmma::matrix_b, 16, 16, 16, __nv_bfloat16, wmma::row_major> bh, bl;
            wmma::load_matrix_sync(bh, g_w2h + kk * 80 + col0 + j * 16, 80);
            wmma::load_matrix_sync(bl, g_w2l + kk * 80 + col0 + j * 16, 80);
#pragma unroll
            for (int i = 0; i < 2; i++) {
                wmma::mma_sync(c[i][j], ah[i], bh, c[i][j]);
                wmma::mma_sync(c[i][j], al[i], bh, c[i][j]);
                wmma::mma_sync(c[i][j], ah[i], bl, c[i][j]);
            }
        }
    }
    __syncthreads();
#pragma unroll
    for (int i = 0; i < 2; i++)
#pragma unroll
        for (int j = 0; j < 3; j++) {
            if (j >= nf) break;
            wmma::store_matrix_sync(stage + (wr * 32 + i * 16) * ST2 + col0 + j * 16,
                                    c[i][j], ST2, wmma::mem_row_major);
        }
    __syncthreads();

    {
        int r = tid >> 1, half = tid & 1;
        int row = row0 + r;
        if (row < NN) {
            const float* sp = stage + r * ST2 + half * 32;
            uint4* dp = (uint4*)(g_h2h + (size_t)row * 64 + half * 32);
#pragma unroll
            for (int q = 0; q < 4; q++) {
                float4 a = *(const float4*)(sp + 8 * q);
                float4 b = *(const float4*)(sp + 8 * q + 4);
                __half2 h0 = __floats2half2_rn(a.x, a.y);
                __half2 h1 = __floats2half2_rn(a.z, a.w);
                __half2 h2 = __floats2half2_rn(b.x, b.y);
                __half2 h3 = __floats2half2_rn(b.z, b.w);
                uint4 u;
                u.x = *(uint32_t*)&h0; u.y = *(uint32_t*)&h1;
                u.z = *(uint32_t*)&h2; u.w = *(uint32_t*)&h3;
                dp[q] = u;
            }
        }
    }
    if (tid < 128) {
        int row = row0 + tid;
        if (row < NN) {
            g_as2[row] = stage[tid * ST2 + 64];
            g_ad2[row] = stage[tid * ST2 + 65];
        }
    }
}

// ---------------- gather1: two-phase softmax aggregation (4 heads, fp16 h) ---
__global__ __launch_bounds__(256)
void k_gather1(const float* __restrict__ b1) {
    int n = blockIdx.x * 8 + (threadIdx.x >> 5);
    if (n >= NN) return;
    int lane = threadIdx.x & 31, h = lane >> 3;
    float adh = g_ad1[4 * n + h];
    int beg = g_off[n], end = g_off[n + 1];

    float4 mx = make_float4(-3.4e38f, -3.4e38f, -3.4e38f, -3.4e38f);
    for (int j = beg + lane; j < end; j += 32) {
        int s = g_srcidx[j];
        float4 a = *(const float4*)(g_as1 + 4 * s);
        mx.x = fmaxf(mx.x, a.x); mx.y = fmaxf(mx.y, a.y);
        mx.z = fmaxf(mx.z, a.z); mx.w = fmaxf(mx.w, a.w);
    }
#pragma unroll
    for (int o = 16; o >= 1; o >>= 1) {
        mx.x = fmaxf(mx.x, __shfl_xor_sync(0xffffffffu, mx.x, o));
        mx.y = fmaxf(mx.y, __shfl_xor_sync(0xffffffffu, mx.y, o));
        mx.z = fmaxf(mx.z, __shfl_xor_sync(0xffffffffu, mx.z, o));
        mx.w = fmaxf(mx.w, __shfl_xor_sync(0xffffffffu, mx.w, o));
    }
    float mh = (h == 0) ? mx.x : (h == 1) ? mx.y : (h == 2) ? mx.z : mx.w;
    mh = lrelu(mh + adh);

    float4 acc = make_float4(0.f, 0.f, 0.f, 0.f);
    float den = 0.f;
    int s0 = 0; float a0 = 0.f; uint2 u0 = make_uint2(0, 0);
    if (beg < end) {
        s0 = g_srcidx[beg];
        a0 = g_as1[4 * s0 + h];
        u0 = *(const uint2*)(g_h1h + (size_t)s0 * 128 + 4 * lane);
    }
    for (int j = beg; j < end; j++) {
        int s1 = 0; float a1 = 0.f; uint2 u1 = make_uint2(0, 0);
        if (j + 1 < end) {
            s1 = g_srcidx[j + 1];
            a1 = g_as1[4 * s1 + h];
            u1 = *(const uint2*)(g_h1h + (size_t)s1 * 128 + 4 * lane);
        }
        float w = __expf(lrelu(a0 + adh) - mh);
        den += w;
        float2 f0 = __half22float2(*(__half2*)&u0.x);
        float2 f1 = __half22float2(*(__half2*)&u0.y);
        acc.x += w * f0.x; acc.y += w * f0.y;
        acc.z += w * f1.x; acc.w += w * f1.y;
        s0 = s1; a0 = a1; u0 = u1;
    }
    float inv = 1.f / (den + 1e-16f);
    float4 bv = *(const float4*)(b1 + 4 * lane);
    *(float4*)(g_out1 + (size_t)n * 128 + 4 * lane) =
        make_float4(acc.x * inv + bv.x, acc.y * inv + bv.y,
                    acc.z * inv + bv.z, acc.w * inv + bv.w);
}

// ---------------- gather2: two-phase (1 head, fp16 h) -------------------------
__global__ __launch_bounds__(256)
void k_gather2(const float* __restrict__ b2, float* __restrict__ out) {
    int n = blockIdx.x * 8 + (threadIdx.x >> 5);
    if (n >= NN) return;
    int lane = threadIdx.x & 31;
    float adh = g_ad2[n];
    int beg = g_off[n], end = g_off[n + 1];

    float mx = -3.4e38f;
    for (int j = beg + lane; j < end; j += 32)
        mx = fmaxf(mx, g_as2[g_srcidx[j]]);
#pragma unroll
    for (int o = 16; o >= 1; o >>= 1)
        mx = fmaxf(mx, __shfl_xor_sync(0xffffffffu, mx, o));
    float mh = lrelu(mx + adh);

    float2 acc = make_float2(0.f, 0.f);
    float den = 0.f;
    int s0 = 0; float a0 = 0.f; uint32_t u0 = 0;
    if (beg < end) {
        s0 = g_srcidx[beg];
        a0 = g_as2[s0];
        u0 = *(const uint32_t*)(g_h2h + (size_t)s0 * 64 + 2 * lane);
    }
    for (int j = beg; j < end; j++) {
        int s1 = 0; float a1 = 0.f; uint32_t u1 = 0;
        if (j + 1 < end) {
            s1 = g_srcidx[j + 1];
            a1 = g_as2[s1];
            u1 = *(const uint32_t*)(g_h2h + (size_t)s1 * 64 + 2 * lane);
        }
        float w = __expf(lrelu(a0 + adh) - mh);
        den += w;
        float2 f = __half22float2(*(__half2*)&u0);
        acc.x += w * f.x; acc.y += w * f.y;
        s0 = s1; a0 = a1; u0 = u1;
    }
    float inv = 1.f / (den + 1e-16f);
    float2 bv = *(const float2*)(b2 + 2 * lane);
    *(float2*)(out + (size_t)n * 64 + 2 * lane) =
        make_float2(acc.x * inv + bv.x, acc.y * inv + bv.y);
}

// ---------------- launch ------------------------------------------------------
extern "C" void kernel_launch(void* const* d_in, const int* in_sizes, int n_in,
                              void* d_out, int out_size) {
    const float* x   = (const float*)d_in[0];
    const int*   ei  = (const int*)d_in[1];
    const float* W1  = (const float*)d_in[2];
    const float* as1 = (const float*)d_in[3];
    const float* ad1 = (const float*)d_in[4];
    const float* b1  = (const float*)d_in[5];
    const float* W2  = (const float*)d_in[6];
    const float* as2 = (const float*)d_in[7];
    const float* ad2 = (const float*)d_in[8];
    const float* b2  = (const float*)d_in[9];
    float* out = (float*)d_out;

    const int smem1 = 128 * ST1 * 4;     // 75776 (>= A tiles 69632)
    const int smem2 = 128 * LDA * 2 * 2; // 69632 (>= stage 43008)
    static bool attr_done = false;
    if (!attr_done) {
        cudaFuncSetAttribute(k_gemm1_mma, cudaFuncAttributeMaxDynamicSharedMemorySize, smem1);
        cudaFuncSetAttribute(k_gemm2_mma, cudaFuncAttributeMaxDynamicSharedMemorySize, smem2);
        attr_done = true;
    }

    // CSR build (g_deg zero on entry; scanC restores it)
    k_hist<<<(NE / 4 + 255) / 256, 256>>>(ei);
    k_scanA<<<NBLK, 256>>>();
    k_scanB<<<1, 256>>>();
    k_scanC<<<NBLK, 256>>>();
    k_fill<<<(NE / 4 + 255) / 256, 256>>>(ei);

    // weights -> bf16 split with fused alpha columns
    k_convw<<<112, 256>>>(W1, W2, as1, ad1, as2, ad2);

    // layer 1
    k_gemm1_mma<<<NP / 128, 256, smem1>>>(x);
    k_gather1<<<(NN + 7) / 8, 256>>>(b1);

    // layer 2
    k_gemm2_mma<<<NP / 128, 256, smem2>>>();
    k_gather2<<<(NN + 7) / 8, 256>>>(b2, out);
}

// round 8
// speedup vs baseline: 1.8021x; 1.0974x over previous
#include <cuda_runtime.h>
#include <cuda_bf16.h>
#include <cuda_fp16.h>
#include <mma.h>
#include <cstdint>

using namespace nvcuda;

#define NN 50000
#define NP 50048          // 391 * 128
#define NE 800000
#define ET 850000         // NE + NN self loops
#define NS 0.2f
#define NBLK 196          // ceil(NN/256)

// ---------------- scratch (device globals) -----------------------------------
__device__ __half g_h1h[NN * 128];
__device__ float  g_out1[NN * 128];
__device__ float  g_as1[NN * 4];
__device__ float  g_ad1[NN * 4];
__device__ __half g_h2h[NN * 64];
__device__ float  g_as2[NN];
__device__ float  g_ad2[NN];
__device__ int g_deg[NN];        // invariant: zero before/after every call
__device__ int g_off[NN + 1];
__device__ int g_cur[NN];
__device__ int g_srcidx[ET];
__device__ unsigned int g_blkst[NBLK];   // lookback state: (val<<2)|flag
// bf16-split weights with fused alpha columns
__device__ __nv_bfloat16 g_w1h[128 * 144];
__device__ __nv_bfloat16 g_w1l[128 * 144];
__device__ __nv_bfloat16 g_w2h[128 * 80];
__device__ __nv_bfloat16 g_w2l[128 * 80];

__device__ __forceinline__ float lrelu(float v) { return v >= 0.f ? v : NS * v; }

// ---------------- prep: hist + weight conversion + scan-flag reset -----------
// blocks [0,782): hist; [782,894): convw; 894: flag reset
#define HIST_BLKS 782
__global__ void k_prep(const int* __restrict__ ei,
                       const float* __restrict__ W1, const float* __restrict__ W2,
                       const float* __restrict__ as1, const float* __restrict__ ad1,
                       const float* __restrict__ as2, const float* __restrict__ ad2) {
    int b = blockIdx.x, t = threadIdx.x;
    if (b < HIST_BLKS) {
        int i = b * 256 + t;
        if (i >= NE / 4) return;
        int4 d4 = ((const int4*)(ei + NE))[i];
        atomicAdd(&g_deg[d4.x], 1);
        atomicAdd(&g_deg[d4.y], 1);
        atomicAdd(&g_deg[d4.z], 1);
        atomicAdd(&g_deg[d4.w], 1);
        return;
    }
    if (b == HIST_BLKS + 112) {
        if (t < NBLK) g_blkst[t] = 0u;
        if (t == 0) g_off[NN] = ET;
        return;
    }
    int s = (b - HIST_BLKS) * 256 + t;
    float val; int dsth, dstl;
    if (s < 16384) {                       // W1 copy
        int k = s >> 7, n = s & 127;
        val = W1[k * 128 + n];
        dsth = k * 144 + n; dstl = 1;
    } else if (s < 17408) {                // W1 @ P (alpha cols)
        int i = s - 16384;
        int k = i >> 3, c = i & 7, h = c >> 1;
        const float* a = (c & 1) ? ad1 : as1;
        float sum = 0.f;
#pragma unroll
        for (int f = 0; f < 32; f++) sum += W1[k * 128 + h * 32 + f] * a[h * 32 + f];
        val = sum; dsth = k * 144 + 128 + c; dstl = 1;
    } else if (s < 18432) {                // W1 zero pad
        int i = s - 17408;
        int k = i >> 3, c = i & 7;
        val = 0.f; dsth = k * 144 + 136 + c; dstl = 1;
    } else if (s < 26624) {                // W2 copy
        int i = s - 18432;
        int k = i >> 6, n = i & 63;
        val = W2[k * 64 + n];
        dsth = k * 80 + n; dstl = 2;
    } else if (s < 26880) {                // W2 @ P2
        int i = s - 26624;
        int k = i >> 1, c = i & 1;
        const float* a = c ? ad2 : as2;
        float sum = 0.f;
#pragma unroll
        for (int f = 0; f < 64; f++) sum += W2[k * 64 + f] * a[f];
        val = sum; dsth = k * 80 + 64 + c; dstl = 2;
    } else if (s < 28672) {                // W2 zero pad
        int i = s - 26880;
        int k = i / 14, c = i % 14;
        val = 0.f; dsth = k * 80 + 66 + c; dstl = 2;
    } else return;
    __nv_bfloat16 hi = __float2bfloat16(val);
    __nv_bfloat16 lo = __float2bfloat16(val - __bfloat162float(hi));
    if (dstl == 1) { g_w1h[dsth] = hi; g_w1l[dsth] = lo; }
    else           { g_w2h[dsth] = hi; g_w2l[dsth] = lo; }
}

// ---------------- single-pass scan with decoupled lookback --------------------
__global__ void k_scan() {
    __shared__ int sh[256];
    __shared__ int s_excl;
    int t = threadIdx.x, b = blockIdx.x;
    int i = b * 256 + t;
    int v = (i < NN) ? g_deg[i] + 1 : 0;   // +1 self loop
    sh[t] = v;
    __syncthreads();
#pragma unroll
    for (int o = 1; o < 256; o <<= 1) {
        int tv = (t >= o) ? sh[t - o] : 0;
        __syncthreads();
        sh[t] += tv;
        __syncthreads();
    }
    int incl = sh[t];
    int total = sh[255];

    if (t == 0) {
        if (b == 0) {
            atomicExch(&g_blkst[0], ((unsigned)total << 2) | 2u);
            s_excl = 0;
        } else {
            atomicExch(&g_blkst[b], ((unsigned)total << 2) | 1u);
            int run = 0;
            for (int p = b - 1; p >= 0; p--) {
                unsigned st;
                do { st = atomicAdd(&g_blkst[p], 0u); } while ((st & 3u) == 0u);
                run += (int)(st >> 2);
                if ((st & 3u) == 2u) break;
            }
            s_excl = run;
            atomicExch(&g_blkst[b], ((unsigned)(run + total) << 2) | 2u);
        }
    }
    __syncthreads();
    if (i < NN) {
        int off = s_excl + incl - v;
        g_off[i] = off;
        g_srcidx[off] = i;      // self loop seeded first
        g_cur[i] = off + 1;
        g_deg[i] = 0;           // restore invariant
    }
}

__global__ void k_fill(const int* __restrict__ ei) {
    int i = blockIdx.x * blockDim.x + threadIdx.x;
    if (i >= NE / 4) return;
    int4 s4 = ((const int4*)ei)[i];
    int4 d4 = ((const int4*)(ei + NE))[i];
    int p;
    p = atomicAdd(&g_cur[d4.x], 1); g_srcidx[p] = s4.x;
    p = atomicAdd(&g_cur[d4.y], 1); g_srcidx[p] = s4.y;
    p = atomicAdd(&g_cur[d4.z], 1); g_srcidx[p] = s4.z;
    p = atomicAdd(&g_cur[d4.w], 1); g_srcidx[p] = s4.w;
}

// ---------------- GEMM1: [h1 | as1 | ad1] = x @ [W1 | W1@P] -------------------
#define LDA 136
#define ST1 148
__global__ __launch_bounds__(256)
void k_gemm1_mma(const float* __restrict__ X) {
    extern __shared__ char raw[];
    __nv_bfloat16* sAh = (__nv_bfloat16*)raw;
    __nv_bfloat16* sAl = sAh + 128 * LDA;
    float* stage = (float*)raw;
    int tid = threadIdx.x;
    int row0 = blockIdx.x * 128;

    for (int i = tid; i < 4096; i += 256) {
        int r = i >> 5, c4 = i & 31;
        float4 v = make_float4(0.f, 0.f, 0.f, 0.f);
        if (row0 + r < NN) v = ((const float4*)X)[(size_t)(row0 + r) * 32 + c4];
        int base = r * LDA + c4 * 4;
        float vv[4] = {v.x, v.y, v.z, v.w};
#pragma unroll
        for (int j = 0; j < 4; j++) {
            __nv_bfloat16 h = __float2bfloat16(vv[j]);
            sAh[base + j] = h;
            sAl[base + j] = __float2bfloat16(vv[j] - __bfloat162float(h));
        }
    }
    __syncthreads();

    int w = tid >> 5, wr = w >> 1, wc = w & 1;
    const int nf = wc ? 4 : 5;
    const int col0 = wc * 80;

    wmma::fragment<wmma::accumulator, 16, 16, 16, float> c[2][5];
#pragma unroll
    for (int i = 0; i < 2; i++)
#pragma unroll
        for (int j = 0; j < 5; j++) wmma::fill_fragment(c[i][j], 0.f);

    for (int kk = 0; kk < 128; kk += 16) {
        wmma::fragment<wmma::matrix_a, 16, 16, 16, __nv_bfloat16, wmma::row_major> ah[2], al[2];
#pragma unroll
        for (int i = 0; i < 2; i++) {
            wmma::load_matrix_sync(ah[i], sAh + (wr * 32 + i * 16) * LDA + kk, LDA);
            wmma::load_matrix_sync(al[i], sAl + (wr * 32 + i * 16) * LDA + kk, LDA);
        }
#pragma unroll
        for (int j = 0; j < 5; j++) {
            if (j >= nf) break;
            wmma::fragment<wmma::matrix_b, 16, 16, 16, __nv_bfloat16, wmma::row_major> bh, bl;
            wmma::load_matrix_sync(bh, g_w1h + kk * 144 + col0 + j * 16, 144);
            wmma::load_matrix_sync(bl, g_w1l + kk * 144 + col0 + j * 16, 144);
#pragma unroll
            for (int i = 0; i < 2; i++) {
                wmma::mma_sync(c[i][j], ah[i], bh, c[i][j]);
                wmma::mma_sync(c[i][j], al[i], bh, c[i][j]);
                wmma::mma_sync(c[i][j], ah[i], bl, c[i][j]);
            }
        }
    }
    __syncthreads();
#pragma unroll
    for (int i = 0; i < 2; i++)
#pragma unroll
        for (int j = 0; j < 5; j++) {
            if (j >= nf) break;
            wmma::store_matrix_sync(stage + (wr * 32 + i * 16) * ST1 + col0 + j * 16,
                                    c[i][j], ST1, wmma::mem_row_major);
        }
    __syncthreads();

    {
        int r = tid >> 1, half = tid & 1;
        int row = row0 + r;
        if (row < NN) {
            const float* sp = stage + r * ST1 + half * 64;
            uint4* dp = (uint4*)(g_h1h + (size_t)row * 128 + half * 64);
#pragma unroll
            for (int q = 0; q < 8; q++) {
                float4 a = *(const float4*)(sp + 8 * q);
                float4 b = *(const float4*)(sp + 8 * q + 4);
                __half2 h0 = __floats2half2_rn(a.x, a.y);
                __half2 h1 = __floats2half2_rn(a.z, a.w);
                __half2 h2 = __floats2half2_rn(b.x, b.y);
                __half2 h3 = __floats2half2_rn(b.z, b.w);
                uint4 u;
                u.x = *(uint32_t*)&h0; u.y = *(uint32_t*)&h1;
                u.z = *(uint32_t*)&h2; u.w = *(uint32_t*)&h3;
                dp[q] = u;
            }
        }
    }
    if (tid < 128) {
        int row = row0 + tid;
        if (row < NN) {
            const float* sp = stage + tid * ST1 + 128;
#pragma unroll
            for (int h = 0; h < 4; h++) {
                g_as1[row * 4 + h] = sp[2 * h];
                g_ad1[row * 4 + h] = sp[2 * h + 1];
            }
        }
    }
}

// ---------------- GEMM2: [h2 | as2 | ad2] = relu(out1) @ [W2 | W2@P2] ---------
#define ST2 84
__global__ __launch_bounds__(256)
void k_gemm2_mma() {
    extern __shared__ char raw[];
    __nv_bfloat16* sAh = (__nv_bfloat16*)raw;
    __nv_bfloat16* sAl = sAh + 128 * LDA;
    float* stage = (float*)raw;
    int tid = threadIdx.x;
    int row0 = blockIdx.x * 128;

    for (int i = tid; i < 4096; i += 256) {
        int r = i >> 5, c4 = i & 31;
        float4 v = make_float4(0.f, 0.f, 0.f, 0.f);
        if (row0 + r < NN) v = ((const float4*)g_out1)[(size_t)(row0 + r) * 32 + c4];
        int base = r * LDA + c4 * 4;
        float vv[4] = {fmaxf(v.x, 0.f), fmaxf(v.y, 0.f), fmaxf(v.z, 0.f), fmaxf(v.w, 0.f)};
#pragma unroll
        for (int j = 0; j < 4; j++) {
            __nv_bfloat16 h = __float2bfloat16(vv[j]);
            sAh[base + j] = h;
            sAl[base + j] = __float2bfloat16(vv[j] - __bfloat162float(h));
        }
    }
    __syncthreads();

    int w = tid >> 5, wr = w >> 1, wc = w & 1;
    const int nf = wc ? 2 : 3;
    const int col0 = wc * 48;

    wmma::fragment<wmma::accumulator, 16, 16, 16, float> c[2][3];
#pragma unroll
    for (int i = 0; i < 2; i++)
#pragma unroll
        for (int j = 0; j < 3; j++) wmma::fill_fragment(c[i][j], 0.f);

    for (int kk = 0; kk < 128; kk += 16) {
        wmma::fragment<wmma::matrix_a, 16, 16, 16, __nv_bfloat16, wmma::row_major> ah[2], al[2];
#pragma unroll
        for (int i = 0; i < 2; i++) {
            wmma::load_matrix_sync(ah[i], sAh + (wr * 32 + i * 16) * LDA + kk, LDA);
            wmma::load_matrix_sync(al[i], sAl + (wr * 32 + i * 16) * LDA + kk, LDA);
        }
#pragma unroll
        for (int j = 0; j < 3; j++) {
            if (j >= nf) break;
            wmma::fragment<wmma::matrix_b, 16, 16, 16, __nv_bfloat16, wmma::row_major> bh, bl;
            wmma::load_matrix_sync(bh, g_w2h + kk * 80 + col0 + j * 16, 80);
            wmma::load_matrix_sync(bl, g_w2l + kk * 80 + col0 + j * 16, 80);
#pragma unroll
            for (int i = 0; i < 2; i++) {
                wmma::mma_sync(c[i][j], ah[i], bh, c[i][j]);
                wmma::mma_sync(c[i][j], al[i], bh, c[i][j]);
                wmma::mma_sync(c[i][j], ah[i], bl, c[i][j]);
            }
        }
    }
    __syncthreads();
#pragma unroll
    for (int i = 0; i < 2; i++)
#pragma unroll
        for (int j = 0; j < 3; j++) {
            if (j >= nf) break;
            wmma::store_matrix_sync(stage + (wr * 32 + i * 16) * ST2 + col0 + j * 16,
                                    c[i][j], ST2, wmma::mem_row_major);
        }
    __syncthreads();

    {
        int r = tid >> 1, half = tid & 1;
        int row = row0 + r;
        if (row < NN) {
            const float* sp = stage + r * ST2 + half * 32;
            uint4* dp = (uint4*)(g_h2h + (size_t)row * 64 + half * 32);
#pragma unroll
            for (int q = 0; q < 4; q++) {
                float4 a = *(const float4*)(sp + 8 * q);
                float4 b = *(const float4*)(sp + 8 * q + 4);
                __half2 h0 = __floats2half2_rn(a.x, a.y);
                __half2 h1 = __floats2half2_rn(a.z, a.w);
                __half2 h2 = __floats2half2_rn(b.x, b.y);
                __half2 h3 = __floats2half2_rn(b.z, b.w);
                uint4 u;
                u.x = *(uint32_t*)&h0; u.y = *(uint32_t*)&h1;
                u.z = *(uint32_t*)&h2; u.w = *(uint32_t*)&h3;
                dp[q] = u;
            }
        }
    }
    if (tid < 128) {
        int row = row0 + tid;
        if (row < NN) {
            g_as2[row] = stage[tid * ST2 + 64];
            g_ad2[row] = stage[tid * ST2 + 65];
        }
    }
}

// ---------------- gather1: 2 edges/warp, 16 lanes x 8 fp16 cols ---------------
__global__ __launch_bounds__(256)
void k_gather1(const float* __restrict__ b1) {
    int n = blockIdx.x * 8 + (threadIdx.x >> 5);
    if (n >= NN) return;
    int lane = threadIdx.x & 31;
    int g = lane >> 4, li = lane & 15;
    int head = li >> 2;
    float adh = g_ad1[4 * n + head];
    int beg = g_off[n], end = g_off[n + 1];

    // phase 1: per-head max of as over neighbors (all 32 lanes parallel)
    float4 mx = make_float4(-3.4e38f, -3.4e38f, -3.4e38f, -3.4e38f);
    for (int j = beg + lane; j < end; j += 32) {
        int s = g_srcidx[j];
        float4 a = *(const float4*)(g_as1 + 4 * s);
        mx.x = fmaxf(mx.x, a.x); mx.y = fmaxf(mx.y, a.y);
        mx.z = fmaxf(mx.z, a.z); mx.w = fmaxf(mx.w, a.w);
    }
#pragma unroll
    for (int o = 16; o >= 1; o >>= 1) {
        mx.x = fmaxf(mx.x, __shfl_xor_sync(0xffffffffu, mx.x, o));
        mx.y = fmaxf(mx.y, __shfl_xor_sync(0xffffffffu, mx.y, o));
        mx.z = fmaxf(mx.z, __shfl_xor_sync(0xffffffffu, mx.z, o));
        mx.w = fmaxf(mx.w, __shfl_xor_sync(0xffffffffu, mx.w, o));
    }
    float mh = (head == 0) ? mx.x : (head == 1) ? mx.y : (head == 2) ? mx.z : mx.w;
    mh = lrelu(mh + adh);

    // phase 2: group g handles edges beg+g, beg+g+2, ...
    float acc[8];
#pragma unroll
    for (int q = 0; q < 8; q++) acc[q] = 0.f;
    float den = 0.f;

    int j0 = beg + g;
    int s0 = 0; float a0 = 0.f; uint4 u0 = make_uint4(0, 0, 0, 0);
    if (j0 < end) {
        s0 = g_srcidx[j0];
        a0 = g_as1[4 * s0 + head];
        u0 = *(const uint4*)(g_h1h + (size_t)s0 * 128 + 8 * li);
    }
    for (int j = j0; j < end; j += 2) {
        int s1 = 0; float a1 = 0.f; uint4 u1 = make_uint4(0, 0, 0, 0);
        if (j + 2 < end) {
            s1 = g_srcidx[j + 2];
            a1 = g_as1[4 * s1 + head];
            u1 = *(const uint4*)(g_h1h + (size_t)s1 * 128 + 8 * li);
        }
        float w = __expf(lrelu(a0 + adh) - mh);
        den += w;
        const __half2* hp = (const __half2*)&u0;
#pragma unroll
        for (int q = 0; q < 4; q++) {
            float2 f = __half22float2(hp[q]);
            acc[2 * q] += w * f.x;
            acc[2 * q + 1] += w * f.y;
        }
        s0 = s1; a0 = a1; u0 = u1;
    }
    // combine the two edge groups
    den += __shfl_xor_sync(0xffffffffu, den, 16);
#pragma unroll
    for (int q = 0; q < 8; q++) acc[q] += __shfl_xor_sync(0xffffffffu, acc[q], 16);

    if (g == 0) {
        float inv = 1.f / (den + 1e-16f);
        float4 b0 = *(const float4*)(b1 + 8 * li);
        float4 b4 = *(const float4*)(b1 + 8 * li + 4);
        float* op = g_out1 + (size_t)n * 128 + 8 * li;
        *(float4*)op = make_float4(acc[0] * inv + b0.x, acc[1] * inv + b0.y,
                                   acc[2] * inv + b0.z, acc[3] * inv + b0.w);
        *(float4*)(op + 4) = make_float4(acc[4] * inv + b4.x, acc[5] * inv + b4.y,
                                         acc[6] * inv + b4.z, acc[7] * inv + b4.w);
    }
}

// ---------------- gather2: 4 edges/warp, 8 lanes x 8 fp16 cols ----------------
__global__ __launch_bounds__(256)
void k_gather2(const float* __restrict__ b2, float* __restrict__ out) {
    int n = blockIdx.x * 8 + (threadIdx.x >> 5);
    if (n >= NN) return;
    int lane = threadIdx.x & 31;
    int g = lane >> 3, li = lane & 7;
    float adh = g_ad2[n];
    int beg = g_off[n], end = g_off[n + 1];

    float mx = -3.4e38f;
    for (int j = beg + lane; j < end; j += 32)
        mx = fmaxf(mx, g_as2[g_srcidx[j]]);
#pragma unroll
    for (int o = 16; o >= 1; o >>= 1)
        mx = fmaxf(mx, __shfl_xor_sync(0xffffffffu, mx, o));
    float mh = lrelu(mx + adh);

    float acc[8];
#pragma unroll
    for (int q = 0; q < 8; q++) acc[q] = 0.f;
    float den = 0.f;

    int j0 = beg + g;
    int s0 = 0; float a0 = 0.f; uint4 u0 = make_uint4(0, 0, 0, 0);
    if (j0 < end) {
        s0 = g_srcidx[j0];
        a0 = g_as2[s0];
        u0 = *(const uint4*)(g_h2h + (size_t)s0 * 64 + 8 * li);
    }
    for (int j = j0; j < end; j += 4) {
        int s1 = 0; float a1 = 0.f; uint4 u1 = make_uint4(0, 0, 0, 0);
        if (j + 4 < end) {
            s1 = g_srcidx[j + 4];
            a1 = g_as2[s1];
            u1 = *(const uint4*)(g_h2h + (size_t)s1 * 64 + 8 * li);
        }
        float w = __expf(lrelu(a0 + adh) - mh);
        den += w;
        const __half2* hp = (const __half2*)&u0;
#pragma unroll
        for (int q = 0; q < 4; q++) {
            float2 f = __half22float2(hp[q]);
            acc[2 * q] += w * f.x;
            acc[2 * q + 1] += w * f.y;
        }
        s0 = s1; a0 = a1; u0 = u1;
    }
    den += __shfl_xor_sync(0xffffffffu, den, 8);
    den += __shfl_xor_sync(0xffffffffu, den, 16);
#pragma unroll
    for (int q = 0; q < 8; q++) {
        acc[q] += __shfl_xor_sync(0xffffffffu, acc[q], 8);
        acc[q] += __shfl_xor_sync(0xffffffffu, acc[q], 16);
    }

    if (g == 0) {
        float inv = 1.f / (den + 1e-16f);
        float4 b0 = *(const float4*)(b2 + 8 * li);
        float4 b4 = *(const float4*)(b2 + 8 * li + 4);
        float* op = out + (size_t)n * 64 + 8 * li;
        *(float4*)op = make_float4(acc[0] * inv + b0.x, acc[1] * inv + b0.y,
                                   acc[2] * inv + b0.z, acc[3] * inv + b0.w);
        *(float4*)(op + 4) = make_float4(acc[4] * inv + b4.x, acc[5] * inv + b4.y,
                                         acc[6] * inv + b4.z, acc[7] * inv + b4.w);
    }
}

// ---------------- launch ------------------------------------------------------
extern "C" void kernel_launch(void* const* d_in, const int* in_sizes, int n_in,
                              void* d_out, int out_size) {
    const float* x   = (const float*)d_in[0];
    const int*   ei  = (const int*)d_in[1];
    const float* W1  = (const float*)d_in[2];
    const float* as1 = (const float*)d_in[3];
    const float* ad1 = (const float*)d_in[4];
    const float* b1  = (const float*)d_in[5];
    const float* W2  = (const float*)d_in[6];
    const float* as2 = (const float*)d_in[7];
    const float* ad2 = (const float*)d_in[8];
    const float* b2  = (const float*)d_in[9];
    float* out = (float*)d_out;

    const int smem1 = 128 * ST1 * 4;     // 75776
    const int smem2 = 128 * LDA * 2 * 2; // 69632
    static bool attr_done = false;
    if (!attr_done) {
        cudaFuncSetAttribute(k_gemm1_mma, cudaFuncAttributeMaxDynamicSharedMemorySize, smem1);
        cudaFuncSetAttribute(k_gemm2_mma, cudaFuncAttributeMaxDynamicSharedMemorySize, smem2);
        attr_done = true;
    }

    // prep: hist + weight conversion + lookback-flag reset (one kernel)
    k_prep<<<HIST_BLKS + 112 + 1, 256>>>(ei, W1, W2, as1, ad1, as2, ad2);
    // single-pass CSR offsets (decoupled lookback)
    k_scan<<<NBLK, 256>>>();
    k_fill<<<(NE / 4 + 255) / 256, 256>>>(ei);

    // layer 1
    k_gemm1_mma<<<NP / 128, 256, smem1>>>(x);
    k_gather1<<<(NN + 7) / 8, 256>>>(b1);

    // layer 2
    k_gemm2_mma<<<NP / 128, 256, smem2>>>();
    k_gather2<<<(NN + 7) / 8, 256>>>(b2, out);
}

// round 9
// speedup vs baseline: 1.9153x; 1.0628x over previous
#include <cuda_runtime.h>
#include <cuda_bf16.h>
#include <cuda_fp16.h>
#include <mma.h>
#include <cstdint>

using namespace nvcuda;

#define NN 50000
#define NP 50048          // 391 * 128
#define NE 800000
#define ET 850000         // NE + NN self loops
#define NS 0.2f
#define NBLK 196          // ceil(NN/256)

// ---------------- scratch (device globals) -----------------------------------
__device__ __half g_h1h[NN * 128];
__device__ float  g_out1[NN * 128];
__device__ float  g_as1[NN * 4];
__device__ float  g_ad1[NN * 4];
__device__ __half g_h2h[NN * 64];
__device__ float  g_as2[NN];
__device__ float  g_ad2[NN];
__device__ int g_deg[NN];        // invariant: zero before/after every call
__device__ int g_off[NN + 1];
__device__ int g_cur[NN];
__device__ int g_srcidx[ET];
__device__ unsigned int g_blkst[NBLK];   // lookback state: (val<<2)|flag
// fp16 weights with fused alpha columns
__device__ __half g_w1[128 * 144];   // cols 0..127 W1, 128..135 W1@P, 136..143 zero
__device__ __half g_w2[128 * 80];    // cols 0..63 W2, 64..65 W2@P2, 66..79 zero

__device__ __forceinline__ float lrelu(float v) { return v >= 0.f ? v : NS * v; }

// ---------------- prep: hist + weight conversion + scan-flag reset -----------
#define HIST_BLKS 782
__global__ void k_prep(const int* __restrict__ ei,
                       const float* __restrict__ W1, const float* __restrict__ W2,
                       const float* __restrict__ as1, const float* __restrict__ ad1,
                       const float* __restrict__ as2, const float* __restrict__ ad2) {
    int b = blockIdx.x, t = threadIdx.x;
    if (b < HIST_BLKS) {
        int i = b * 256 + t;
        if (i >= NE / 4) return;
        int4 d4 = ((const int4*)(ei + NE))[i];
        atomicAdd(&g_deg[d4.x], 1);
        atomicAdd(&g_deg[d4.y], 1);
        atomicAdd(&g_deg[d4.z], 1);
        atomicAdd(&g_deg[d4.w], 1);
        return;
    }
    if (b == HIST_BLKS + 112) {
        if (t < NBLK) g_blkst[t] = 0u;
        if (t == 0) g_off[NN] = ET;
        return;
    }
    int s = (b - HIST_BLKS) * 256 + t;
    float val; int dsth, dstl;
    if (s < 16384) {                       // W1 copy
        int k = s >> 7, n = s & 127;
        val = W1[k * 128 + n];
        dsth = k * 144 + n; dstl = 1;
    } else if (s < 17408) {                // W1 @ P (alpha cols)
        int i = s - 16384;
        int k = i >> 3, c = i & 7, h = c >> 1;
        const float* a = (c & 1) ? ad1 : as1;
        float sum = 0.f;
#pragma unroll
        for (int f = 0; f < 32; f++) sum += W1[k * 128 + h * 32 + f] * a[h * 32 + f];
        val = sum; dsth = k * 144 + 128 + c; dstl = 1;
    } else if (s < 18432) {                // W1 zero pad
        int i = s - 17408;
        int k = i >> 3, c = i & 7;
        val = 0.f; dsth = k * 144 + 136 + c; dstl = 1;
    } else if (s < 26624) {                // W2 copy
        int i = s - 18432;
        int k = i >> 6, n = i & 63;
        val = W2[k * 64 + n];
        dsth = k * 80 + n; dstl = 2;
    } else if (s < 26880) {                // W2 @ P2
        int i = s - 26624;
        int k = i >> 1, c = i & 1;
        const float* a = c ? ad2 : as2;
        float sum = 0.f;
#pragma unroll
        for (int f = 0; f < 64; f++) sum += W2[k * 64 + f] * a[f];
        val = sum; dsth = k * 80 + 64 + c; dstl = 2;
    } else if (s < 28672) {                // W2 zero pad
        int i = s - 26880;
        int k = i / 14, c = i % 14;
        val = 0.f; dsth = k * 80 + 66 + c; dstl = 2;
    } else return;
    __half hv = __float2half_rn(val);
    if (dstl == 1) g_w1[dsth] = hv;
    else           g_w2[dsth] = hv;
}

// ---------------- single-pass scan with decoupled lookback --------------------
__global__ void k_scan() {
    __shared__ int sh[256];
    __shared__ int s_excl;
    int t = threadIdx.x, b = blockIdx.x;
    int i = b * 256 + t;
    int v = (i < NN) ? g_deg[i] + 1 : 0;   // +1 self loop
    sh[t] = v;
    __syncthreads();
#pragma unroll
    for (int o = 1; o < 256; o <<= 1) {
        int tv = (t >= o) ? sh[t - o] : 0;
        __syncthreads();
        sh[t] += tv;
        __syncthreads();
    }
    int incl = sh[t];
    int total = sh[255];

    if (t == 0) {
        if (b == 0) {
            atomicExch(&g_blkst[0], ((unsigned)total << 2) | 2u);
            s_excl = 0;
        } else {
            atomicExch(&g_blkst[b], ((unsigned)total << 2) | 1u);
            int run = 0;
            for (int p = b - 1; p >= 0; p--) {
                unsigned st;
                do { st = atomicAdd(&g_blkst[p], 0u); } while ((st & 3u) == 0u);
                run += (int)(st >> 2);
                if ((st & 3u) == 2u) break;
            }
            s_excl = run;
            atomicExch(&g_blkst[b], ((unsigned)(run + total) << 2) | 2u);
        }
    }
    __syncthreads();
    if (i < NN) {
        int off = s_excl + incl - v;
        g_off[i] = off;
        g_srcidx[off] = i;      // self loop seeded first
        g_cur[i] = off + 1;
        g_deg[i] = 0;           // restore invariant
    }
}

__global__ void k_fill(const int* __restrict__ ei) {
    int i = blockIdx.x * blockDim.x + threadIdx.x;
    if (i >= NE / 4) return;
    int4 s4 = ((const int4*)ei)[i];
    int4 d4 = ((const int4*)(ei + NE))[i];
    int p;
    p = atomicAdd(&g_cur[d4.x], 1); g_srcidx[p] = s4.x;
    p = atomicAdd(&g_cur[d4.y], 1); g_srcidx[p] = s4.y;
    p = atomicAdd(&g_cur[d4.z], 1); g_srcidx[p] = s4.z;
    p = atomicAdd(&g_cur[d4.w], 1); g_srcidx[p] = s4.w;
}

// ---------------- GEMM1: [h1 | as1 | ad1] = x @ [W1 | W1@P] -------------------
// fp16 A-split (hi+lo), single fp16 W staged in smem
#define LDA 136
#define LDW1 152
#define ST1 148
__global__ __launch_bounds__(256)
void k_gemm1_mma(const float* __restrict__ X) {
    extern __shared__ char raw[];
    __half* sAh = (__half*)raw;
    __half* sAl = sAh + 128 * LDA;
    __half* sW  = (__half*)(raw + 4 * 128 * LDA);       // byte 69632
    float* stage = (float*)raw;
    int tid = threadIdx.x;
    int row0 = blockIdx.x * 128;

    // copy W (fp16, pre-converted) into padded smem
    {
        const uint2* wv = (const uint2*)g_w1;
        for (int i = tid; i < 128 * 144 / 4; i += 256) {
            int k = i / 36, j = i % 36;
            *(uint2*)(sW + k * LDW1 + 4 * j) = wv[i];
        }
    }
    // A tile fp32 -> fp16 hi/lo
    for (int i = tid; i < 4096; i += 256) {
        int r = i >> 5, c4 = i & 31;
        float4 v = make_float4(0.f, 0.f, 0.f, 0.f);
        if (row0 + r < NN) v = ((const float4*)X)[(size_t)(row0 + r) * 32 + c4];
        int base = r * LDA + c4 * 4;
        float vv[4] = {v.x, v.y, v.z, v.w};
#pragma unroll
        for (int j = 0; j < 4; j++) {
            __half h = __float2half_rn(vv[j]);
            sAh[base + j] = h;
            sAl[base + j] = __float2half_rn(vv[j] - __half2float(h));
        }
    }
    __syncthreads();

    int w = tid >> 5, wr = w >> 1, wc = w & 1;
    const int nf = wc ? 4 : 5;
    const int col0 = wc * 80;

    wmma::fragment<wmma::accumulator, 16, 16, 16, float> c[2][5];
#pragma unroll
    for (int i = 0; i < 2; i++)
#pragma unroll
        for (int j = 0; j < 5; j++) wmma::fill_fragment(c[i][j], 0.f);

    for (int kk = 0; kk < 128; kk += 16) {
        wmma::fragment<wmma::matrix_a, 16, 16, 16, __half, wmma::row_major> ah[2], al[2];
#pragma unroll
        for (int i = 0; i < 2; i++) {
            wmma::load_matrix_sync(ah[i], sAh + (wr * 32 + i * 16) * LDA + kk, LDA);
            wmma::load_matrix_sync(al[i], sAl + (wr * 32 + i * 16) * LDA + kk, LDA);
        }
#pragma unroll
        for (int j = 0; j < 5; j++) {
            if (j >= nf) break;
            wmma::fragment<wmma::matrix_b, 16, 16, 16, __half, wmma::row_major> bh;
            wmma::load_matrix_sync(bh, sW + kk * LDW1 + col0 + j * 16, LDW1);
#pragma unroll
            for (int i = 0; i < 2; i++) {
                wmma::mma_sync(c[i][j], ah[i], bh, c[i][j]);
                wmma::mma_sync(c[i][j], al[i], bh, c[i][j]);
            }
        }
    }
    __syncthreads();   // reuse smem as stage
#pragma unroll
    for (int i = 0; i < 2; i++)
#pragma unroll
        for (int j = 0; j < 5; j++) {
            if (j >= nf) break;
            wmma::store_matrix_sync(stage + (wr * 32 + i * 16) * ST1 + col0 + j * 16,
                                    c[i][j], ST1, wmma::mem_row_major);
        }
    __syncthreads();

    {
        int r = tid >> 1, half = tid & 1;
        int row = row0 + r;
        if (row < NN) {
            const float* sp = stage + r * ST1 + half * 64;
            uint4* dp = (uint4*)(g_h1h + (size_t)row * 128 + half * 64);
#pragma unroll
            for (int q = 0; q < 8; q++) {
                float4 a = *(const float4*)(sp + 8 * q);
                float4 b = *(const float4*)(sp + 8 * q + 4);
                __half2 h0 = __floats2half2_rn(a.x, a.y);
                __half2 h1 = __floats2half2_rn(a.z, a.w);
                __half2 h2 = __floats2half2_rn(b.x, b.y);
                __half2 h3 = __floats2half2_rn(b.z, b.w);
                uint4 u;
                u.x = *(uint32_t*)&h0; u.y = *(uint32_t*)&h1;
                u.z = *(uint32_t*)&h2; u.w = *(uint32_t*)&h3;
                dp[q] = u;
            }
        }
    }
    if (tid < 128) {
        int row = row0 + tid;
        if (row < NN) {
            const float* sp = stage + tid * ST1 + 128;
#pragma unroll
            for (int h = 0; h < 4; h++) {
                g_as1[row * 4 + h] = sp[2 * h];
                g_ad1[row * 4 + h] = sp[2 * h + 1];
            }
        }
    }
}

// ---------------- GEMM2: [h2 | as2 | ad2] = relu(out1) @ [W2 | W2@P2] ---------
#define LDW2 88
#define ST2 84
__global__ __launch_bounds__(256)
void k_gemm2_mma() {
    extern __shared__ char raw[];
    __half* sAh = (__half*)raw;
    __half* sAl = sAh + 128 * LDA;
    __half* sW  = (__half*)(raw + 4 * 128 * LDA);
    float* stage = (float*)raw;
    int tid = threadIdx.x;
    int row0 = blockIdx.x * 128;

    {
        const uint2* wv = (const uint2*)g_w2;
        for (int i = tid; i < 128 * 80 / 4; i += 256) {
            int k = i / 20, j = i % 20;
            *(uint2*)(sW + k * LDW2 + 4 * j) = wv[i];
        }
    }
    for (int i = tid; i < 4096; i += 256) {
        int r = i >> 5, c4 = i & 31;
        float4 v = make_float4(0.f, 0.f, 0.f, 0.f);
        if (row0 + r < NN) v = ((const float4*)g_out1)[(size_t)(row0 + r) * 32 + c4];
        int base = r * LDA + c4 * 4;
        float vv[4] = {fmaxf(v.x, 0.f), fmaxf(v.y, 0.f), fmaxf(v.z, 0.f), fmaxf(v.w, 0.f)};
#pragma unroll
        for (int j = 0; j < 4; j++) {
            __half h = __float2half_rn(vv[j]);
            sAh[base + j] = h;
            sAl[base + j] = __float2half_rn(vv[j] - __half2float(h));
        }
    }
    __syncthreads();

    int w = tid >> 5, wr = w >> 1, wc = w & 1;
    const int nf = wc ? 2 : 3;
    const int col0 = wc * 48;

    wmma::fragment<wmma::accumulator, 16, 16, 16, float> c[2][3];
#pragma unroll
    for (int i = 0; i < 2; i++)
#pragma unroll
        for (int j = 0; j < 3; j++) wmma::fill_fragment(c[i][j], 0.f);

    for (int kk = 0; kk < 128; kk += 16) {
        wmma::fragment<wmma::matrix_a, 16, 16, 16, __half, wmma::row_major> ah[2], al[2];
#pragma unroll
        for (int i = 0; i < 2; i++) {
            wmma::load_matrix_sync(ah[i], sAh + (wr * 32 + i * 16) * LDA + kk, LDA);
            wmma::load_matrix_sync(al[i], sAl + (wr * 32 + i * 16) * LDA + kk, LDA);
        }
#pragma unroll
        for (int j = 0; j < 3; j++) {
            if (j >= nf) break;
            wmma::fragment<wmma::matrix_b, 16, 16, 16, __half, wmma::row_major> bh;
            wmma::load_matrix_sync(bh, sW + kk * LDW2 + col0 + j * 16, LDW2);
#pragma unroll
            for (int i = 0; i < 2; i++) {
                wmma::mma_sync(c[i][j], ah[i], bh, c[i][j]);
                wmma::mma_sync(c[i][j], al[i], bh, c[i][j]);
            }
        }
    }
    __syncthreads();
#pragma unroll
    for (int i = 0; i < 2; i++)
#pragma unroll
        for (int j = 0; j < 3; j++) {
            if (j >= nf) break;
            wmma::store_matrix_sync(stage + (wr * 32 + i * 16) * ST2 + col0 + j * 16,
                                    c[i][j], ST2, wmma::mem_row_major);
        }
    __syncthreads();

    {
        int r = tid >> 1, half = tid & 1;
        int row = row0 + r;
        if (row < NN) {
            const float* sp = stage + r * ST2 + half * 32;
            uint4* dp = (uint4*)(g_h2h + (size_t)row * 64 + half * 32);
#pragma unroll
            for (int q = 0; q < 4; q++) {
                float4 a = *(const float4*)(sp + 8 * q);
                float4 b = *(const float4*)(sp + 8 * q + 4);
                __half2 h0 = __floats2half2_rn(a.x, a.y);
                __half2 h1 = __floats2half2_rn(a.z, a.w);
                __half2 h2 = __floats2half2_rn(b.x, b.y);
                __half2 h3 = __floats2half2_rn(b.z, b.w);
                uint4 u;
                u.x = *(uint32_t*)&h0; u.y = *(uint32_t*)&h1;
                u.z = *(uint32_t*)&h2; u.w = *(uint32_t*)&h3;
                dp[q] = u;
            }
        }
    }
    if (tid < 128) {
        int row = row0 + tid;
        if (row < NN) {
            g_as2[row] = stage[tid * ST2 + 64];
            g_ad2[row] = stage[tid * ST2 + 65];
        }
    }
}

// ---------------- gather1: 2 edges/warp, 16 lanes x 8 fp16 cols ---------------
__global__ __launch_bounds__(256)
void k_gather1(const float* __restrict__ b1) {
    int n = blockIdx.x * 8 + (threadIdx.x >> 5);
    if (n >= NN) return;
    int lane = threadIdx.x & 31;
    int g = lane >> 4, li = lane & 15;
    int head = li >> 2;
    float adh = g_ad1[4 * n + head];
    int beg = g_off[n], end = g_off[n + 1];

    float4 mx = make_float4(-3.4e38f, -3.4e38f, -3.4e38f, -3.4e38f);
    for (int j = beg + lane; j < end; j += 32) {
        int s = g_srcidx[j];
        float4 a = *(const float4*)(g_as1 + 4 * s);
        mx.x = fmaxf(mx.x, a.x); mx.y = fmaxf(mx.y, a.y);
        mx.z = fmaxf(mx.z, a.z); mx.w = fmaxf(mx.w, a.w);
    }
#pragma unroll
    for (int o = 16; o >= 1; o >>= 1) {
        mx.x = fmaxf(mx.x, __shfl_xor_sync(0xffffffffu, mx.x, o));
        mx.y = fmaxf(mx.y, __shfl_xor_sync(0xffffffffu, mx.y, o));
        mx.z = fmaxf(mx.z, __shfl_xor_sync(0xffffffffu, mx.z, o));
        mx.w = fmaxf(mx.w, __shfl_xor_sync(0xffffffffu, mx.w, o));
    }
    float mh = (head == 0) ? mx.x : (head == 1) ? mx.y : (head == 2) ? mx.z : mx.w;
    mh = lrelu(mh + adh);

    float acc[8];
#pragma unroll
    for (int q = 0; q < 8; q++) acc[q] = 0.f;
    float den = 0.f;

    int j0 = beg + g;
    int s0 = 0; float a0 = 0.f; uint4 u0 = make_uint4(0, 0, 0, 0);
    if (j0 < end) {
        s0 = g_srcidx[j0];
        a0 = g_as1[4 * s0 + head];
        u0 = *(const uint4*)(g_h1h + (size_t)s0 * 128 + 8 * li);
    }
    for (int j = j0; j < end; j += 2) {
        int s1 = 0; float a1 = 0.f; uint4 u1 = make_uint4(0, 0, 0, 0);
        if (j + 2 < end) {
            s1 = g_srcidx[j + 2];
            a1 = g_as1[4 * s1 + head];
            u1 = *(const uint4*)(g_h1h + (size_t)s1 * 128 + 8 * li);
        }
        float w = __expf(lrelu(a0 + adh) - mh);
        den += w;
        const __half2* hp = (const __half2*)&u0;
#pragma unroll
        for (int q = 0; q < 4; q++) {
            float2 f = __half22float2(hp[q]);
            acc[2 * q] += w * f.x;
            acc[2 * q + 1] += w * f.y;
        }
        s0 = s1; a0 = a1; u0 = u1;
    }
    den += __shfl_xor_sync(0xffffffffu, den, 16);
#pragma unroll
    for (int q = 0; q < 8; q++) acc[q] += __shfl_xor_sync(0xffffffffu, acc[q], 16);

    if (g == 0) {
        float inv = 1.f / (den + 1e-16f);
        float4 b0 = *(const float4*)(b1 + 8 * li);
        float4 b4 = *(const float4*)(b1 + 8 * li + 4);
        float* op = g_out1 + (size_t)n * 128 + 8 * li;
        *(float4*)op = make_float4(acc[0] * inv + b0.x, acc[1] * inv + b0.y,
                                   acc[2] * inv + b0.z, acc[3] * inv + b0.w);
        *(float4*)(op + 4) = make_float4(acc[4] * inv + b4.x, acc[5] * inv + b4.y,
                                         acc[6] * inv + b4.z, acc[7] * inv + b4.w);
    }
}

// ---------------- gather2: 4 edges/warp, 8 lanes x 8 fp16 cols ----------------
__global__ __launch_bounds__(256)
void k_gather2(const float* __restrict__ b2, float* __restrict__ out) {
    int n = blockIdx.x * 8 + (threadIdx.x >> 5);
    if (n >= NN) return;
    int lane = threadIdx.x & 31;
    int g = lane >> 3, li = lane & 7;
    float adh = g_ad2[n];
    int beg = g_off[n], end = g_off[n + 1];

    float mx = -3.4e38f;
    for (int j = beg + lane; j < end; j += 32)
        mx = fmaxf(mx, g_as2[g_srcidx[j]]);
#pragma unroll
    for (int o = 16; o >= 1; o >>= 1)
        mx = fmaxf(mx, __shfl_xor_sync(0xffffffffu, mx, o));
    float mh = lrelu(mx + adh);

    float acc[8];
#pragma unroll
    for (int q = 0; q < 8; q++) acc[q] = 0.f;
    float den = 0.f;

    int j0 = beg + g;
    int s0 = 0; float a0 = 0.f; uint4 u0 = make_uint4(0, 0, 0, 0);
    if (j0 < end) {
        s0 = g_srcidx[j0];
        a0 = g_as2[s0];
        u0 = *(const uint4*)(g_h2h + (size_t)s0 * 64 + 8 * li);
    }
    for (int j = j0; j < end; j += 4) {
        int s1 = 0; float a1 = 0.f; uint4 u1 = make_uint4(0, 0, 0, 0);
        if (j + 4 < end) {
            s1 = g_srcidx[j + 4];
            a1 = g_as2[s1];
            u1 = *(const uint4*)(g_h2h + (size_t)s1 * 64 + 8 * li);
        }
        float w = __expf(lrelu(a0 + adh) - mh);
        den += w;
        const __half2* hp = (const __half2*)&u0;
#pragma unroll
        for (int q = 0; q < 4; q++) {
            float2 f = __half22float2(hp[q]);
            acc[2 * q] += w * f.x;
            acc[2 * q + 1] += w * f.y;
        }
        s0 = s1; a0 = a1; u0 = u1;
    }
    den += __shfl_xor_sync(0xffffffffu, den, 8);
    den += __shfl_xor_sync(0xffffffffu, den, 16);
#pragma unroll
    for (int q = 0; q < 8; q++) {
        acc[q] += __shfl_xor_sync(0xffffffffu, acc[q], 8);
        acc[q] += __shfl_xor_sync(0xffffffffu, acc[q], 16);
    }

    if (g == 0) {
        float inv = 1.f / (den + 1e-16f);
        float4 b0 = *(const float4*)(b2 + 8 * li);
        float4 b4 = *(const float4*)(b2 + 8 * li + 4);
        float* op = out + (size_t)n * 64 + 8 * li;
        *(float4*)op = make_float4(acc[0] * inv + b0.x, acc[1] * inv + b0.y,
                                   acc[2] * inv + b0.z, acc[3] * inv + b0.w);
        *(float4*)(op + 4) = make_float4(acc[4] * inv + b4.x, acc[5] * inv + b4.y,
                                         acc[6] * inv + b4.z, acc[7] * inv + b4.w);
    }
}

// ---------------- launch ------------------------------------------------------
extern "C" void kernel_launch(void* const* d_in, const int* in_sizes, int n_in,
                              void* d_out, int out_size) {
    const float* x   = (const float*)d_in[0];
    const int*   ei  = (const int*)d_in[1];
    const float* W1  = (const float*)d_in[2];
    const float* as1 = (const float*)d_in[3];
    const float* ad1 = (const float*)d_in[4];
    const float* b1  = (const float*)d_in[5];
    const float* W2  = (const float*)d_in[6];
    const float* as2 = (const float*)d_in[7];
    const float* ad2 = (const float*)d_in[8];
    const float* b2  = (const float*)d_in[9];
    float* out = (float*)d_out;

    const int smem1 = 4 * 128 * LDA + 2 * 128 * LDW1;   // 69632 + 38912 = 108544
    const int smem2 = 4 * 128 * LDA + 2 * 128 * LDW2;   // 69632 + 22528 = 92160
    static bool attr_done = false;
    if (!attr_done) {
        cudaFuncSetAttribute(k_gemm1_mma, cudaFuncAttributeMaxDynamicSharedMemorySize, smem1);
        cudaFuncSetAttribute(k_gemm2_mma, cudaFuncAttributeMaxDynamicSharedMemorySize, smem2);
        attr_done = true;
    }

    // prep: hist + weight conversion + lookback-flag reset
    k_prep<<<HIST_BLKS + 112 + 1, 256>>>(ei, W1, W2, as1, ad1, as2, ad2);
    // single-pass CSR offsets (decoupled lookback)
    k_scan<<<NBLK, 256>>>();
    k_fill<<<(NE / 4 + 255) / 256, 256>>>(ei);

    // layer 1
    k_gemm1_mma<<<NP / 128, 256, smem1>>>(x);
    k_gather1<<<(NN + 7) / 8, 256>>>(b1);

    // layer 2
    k_gemm2_mma<<<NP / 128, 256, smem2>>>();
    k_gather2<<<(NN + 7) / 8, 256>>>(b2, out);
}

// round 10
// speedup vs baseline: 2.2054x; 1.1515x over previous
#include <cuda_runtime.h>
#include <cuda_bf16.h>
#include <cuda_fp16.h>
#include <mma.h>
#include <cstdint>

using namespace nvcuda;

#define NN 50000
#define NP 50048          // 782 * 64
#define NE 800000
#define ET 850000         // NE + NN self loops
#define NS 0.2f
#define NBLK 196          // ceil(NN/256)

// ---------------- scratch (device globals) -----------------------------------
__device__ __half g_h1h[NN * 128];
__device__ float  g_out1[NN * 128];
__device__ float  g_as1[NN * 4];
__device__ float  g_ad1[NN * 4];
__device__ __half g_h2h[NN * 64];
__device__ float  g_as2[NN];
__device__ float  g_ad2[NN];
__device__ int g_deg[NN];        // invariant: zero before/after every call
__device__ int g_off[NN + 1];
__device__ int g_cur[NN];
__device__ int g_srcidx[ET];
__device__ unsigned int g_blkst[NBLK];   // lookback state: (val<<2)|flag
// fp16 weights with fused alpha columns
__device__ __half g_w1[128 * 144];   // cols 0..127 W1, 128..135 W1@P, 136..143 zero
__device__ __half g_w2[128 * 80];    // cols 0..63 W2, 64..65 W2@P2, 66..79 zero

__device__ __forceinline__ float lrelu(float v) { return v >= 0.f ? v : NS * v; }

// ---------------- prep: hist + weight conversion + scan-flag reset -----------
#define HIST_BLKS 782
__global__ void k_prep(const int* __restrict__ ei,
                       const float* __restrict__ W1, const float* __restrict__ W2,
                       const float* __restrict__ as1, const float* __restrict__ ad1,
                       const float* __restrict__ as2, const float* __restrict__ ad2) {
    int b = blockIdx.x, t = threadIdx.x;
    if (b < HIST_BLKS) {
        int i = b * 256 + t;
        if (i >= NE / 4) return;
        int4 d4 = ((const int4*)(ei + NE))[i];
        atomicAdd(&g_deg[d4.x], 1);
        atomicAdd(&g_deg[d4.y], 1);
        atomicAdd(&g_deg[d4.z], 1);
        atomicAdd(&g_deg[d4.w], 1);
        return;
    }
    if (b == HIST_BLKS + 112) {
        if (t < NBLK) g_blkst[t] = 0u;
        if (t == 0) g_off[NN] = ET;
        return;
    }
    int s = (b - HIST_BLKS) * 256 + t;
    float val; int dsth, dstl;
    if (s < 16384) {                       // W1 copy
        int k = s >> 7, n = s & 127;
        val = W1[k * 128 + n];
        dsth = k * 144 + n; dstl = 1;
    } else if (s < 17408) {                // W1 @ P (alpha cols)
        int i = s - 16384;
        int k = i >> 3, c = i & 7, h = c >> 1;
        const float* a = (c & 1) ? ad1 : as1;
        float sum = 0.f;
#pragma unroll
        for (int f = 0; f < 32; f++) sum += W1[k * 128 + h * 32 + f] * a[h * 32 + f];
        val = sum; dsth = k * 144 + 128 + c; dstl = 1;
    } else if (s < 18432) {                // W1 zero pad
        int i = s - 17408;
        int k = i >> 3, c = i & 7;
        val = 0.f; dsth = k * 144 + 136 + c; dstl = 1;
    } else if (s < 26624) {                // W2 copy
        int i = s - 18432;
        int k = i >> 6, n = i & 63;
        val = W2[k * 64 + n];
        dsth = k * 80 + n; dstl = 2;
    } else if (s < 26880) {                // W2 @ P2
        int i = s - 26624;
        int k = i >> 1, c = i & 1;
        const float* a = c ? ad2 : as2;
        float sum = 0.f;
#pragma unroll
        for (int f = 0; f < 64; f++) sum += W2[k * 64 + f] * a[f];
        val = sum; dsth = k * 80 + 64 + c; dstl = 2;
    } else if (s < 28672) {                // W2 zero pad
        int i = s - 26880;
        int k = i / 14, c = i % 14;
        val = 0.f; dsth = k * 80 + 66 + c; dstl = 2;
    } else return;
    __half hv = __float2half_rn(val);
    if (dstl == 1) g_w1[dsth] = hv;
    else           g_w2[dsth] = hv;
}

// ---------------- single-pass scan with decoupled lookback --------------------
__global__ void k_scan() {
    __shared__ int sh[256];
    __shared__ int s_excl;
    int t = threadIdx.x, b = blockIdx.x;
    int i = b * 256 + t;
    int v = (i < NN) ? g_deg[i] + 1 : 0;   // +1 self loop
    sh[t] = v;
    __syncthreads();
#pragma unroll
    for (int o = 1; o < 256; o <<= 1) {
        int tv = (t >= o) ? sh[t - o] : 0;
        __syncthreads();
        sh[t] += tv;
        __syncthreads();
    }
    int incl = sh[t];
    int total = sh[255];

    if (t == 0) {
        if (b == 0) {
            atomicExch(&g_blkst[0], ((unsigned)total << 2) | 2u);
            s_excl = 0;
        } else {
            atomicExch(&g_blkst[b], ((unsigned)total << 2) | 1u);
            int run = 0;
            for (int p = b - 1; p >= 0; p--) {
                unsigned st;
                do { st = atomicAdd(&g_blkst[p], 0u); } while ((st & 3u) == 0u);
                run += (int)(st >> 2);
                if ((st & 3u) == 2u) break;
            }
            s_excl = run;
            atomicExch(&g_blkst[b], ((unsigned)(run + total) << 2) | 2u);
        }
    }
    __syncthreads();
    if (i < NN) {
        int off = s_excl + incl - v;
        g_off[i] = off;
        g_srcidx[off] = i;      // self loop seeded first
        g_cur[i] = off + 1;
        g_deg[i] = 0;           // restore invariant
    }
}

__global__ void k_fill(const int* __restrict__ ei) {
    int i = blockIdx.x * blockDim.x + threadIdx.x;
    if (i >= NE / 4) return;
    int4 s4 = ((const int4*)ei)[i];
    int4 d4 = ((const int4*)(ei + NE))[i];
    int p;
    p = atomicAdd(&g_cur[d4.x], 1); g_srcidx[p] = s4.x;
    p = atomicAdd(&g_cur[d4.y], 1); g_srcidx[p] = s4.y;
    p = atomicAdd(&g_cur[d4.z], 1); g_srcidx[p] = s4.z;
    p = atomicAdd(&g_cur[d4.w], 1); g_srcidx[p] = s4.w;
}

// ---------------- GEMM1: [h1 | as1 | ad1] = x @ [W1 | W1@P] -------------------
// M-tile 64, 8 warps = 4x2 grid; warp = 16 rows x (80|64) cols
#define LDA 136
#define LDW1 152
#define ST1 148
__global__ __launch_bounds__(256)
void k_gemm1_mma(const float* __restrict__ X) {
    extern __shared__ char raw[];
    __half* sAh = (__half*)raw;
    __half* sAl = sAh + 64 * LDA;
    __half* sW  = (__half*)(raw + 4 * 64 * LDA);        // byte 34816
    float* stage = (float*)raw;
    int tid = threadIdx.x;
    int row0 = blockIdx.x * 64;

    // copy W (fp16, pre-converted) into padded smem
    {
        const uint2* wv = (const uint2*)g_w1;
        for (int i = tid; i < 128 * 144 / 4; i += 256) {
            int k = i / 36, j = i % 36;
            *(uint2*)(sW + k * LDW1 + 4 * j) = wv[i];
        }
    }
    // A tile fp32 -> fp16 hi/lo (64 rows)
    for (int i = tid; i < 2048; i += 256) {
        int r = i >> 5, c4 = i & 31;
        float4 v = make_float4(0.f, 0.f, 0.f, 0.f);
        if (row0 + r < NN) v = ((const float4*)X)[(size_t)(row0 + r) * 32 + c4];
        int base = r * LDA + c4 * 4;
        float vv[4] = {v.x, v.y, v.z, v.w};
#pragma unroll
        for (int j = 0; j < 4; j++) {
            __half h = __float2half_rn(vv[j]);
            sAh[base + j] = h;
            sAl[base + j] = __float2half_rn(vv[j] - __half2float(h));
        }
    }
    __syncthreads();

    int w = tid >> 5, wr = w >> 1, wc = w & 1;
    const int nf = wc ? 4 : 5;
    const int col0 = wc * 80;

    wmma::fragment<wmma::accumulator, 16, 16, 16, float> c[5];
#pragma unroll
    for (int j = 0; j < 5; j++) wmma::fill_fragment(c[j], 0.f);

    for (int kk = 0; kk < 128; kk += 16) {
        wmma::fragment<wmma::matrix_a, 16, 16, 16, __half, wmma::row_major> ah, al;
        wmma::load_matrix_sync(ah, sAh + (wr * 16) * LDA + kk, LDA);
        wmma::load_matrix_sync(al, sAl + (wr * 16) * LDA + kk, LDA);
#pragma unroll
        for (int j = 0; j < 5; j++) {
            if (j >= nf) break;
            wmma::fragment<wmma::matrix_b, 16, 16, 16, __half, wmma::row_major> bh;
            wmma::load_matrix_sync(bh, sW + kk * LDW1 + col0 + j * 16, LDW1);
            wmma::mma_sync(c[j], ah, bh, c[j]);
            wmma::mma_sync(c[j], al, bh, c[j]);
        }
    }
    __syncthreads();   // reuse smem as stage (64*ST1*4 = 37888 <= 73728)
#pragma unroll
    for (int j = 0; j < 5; j++) {
        if (j >= nf) break;
        wmma::store_matrix_sync(stage + (wr * 16) * ST1 + col0 + j * 16,
                                c[j], ST1, wmma::mem_row_major);
    }
    __syncthreads();

    // h1 -> fp16: 64 rows x 128 cols; thread handles 32 cols
    {
        int r = tid >> 2, q = tid & 3;
        int row = row0 + r;
        if (row < NN) {
            const float* sp = stage + r * ST1 + 32 * q;
            uint4* dp = (uint4*)(g_h1h + (size_t)row * 128 + 32 * q);
#pragma unroll
            for (int u = 0; u < 4; u++) {
                float4 a = *(const float4*)(sp + 8 * u);
                float4 b = *(const float4*)(sp + 8 * u + 4);
                __half2 h0 = __floats2half2_rn(a.x, a.y);
                __half2 h1 = __floats2half2_rn(a.z, a.w);
                __half2 h2 = __floats2half2_rn(b.x, b.y);
                __half2 h3 = __floats2half2_rn(b.z, b.w);
                uint4 uu;
                uu.x = *(uint32_t*)&h0; uu.y = *(uint32_t*)&h1;
                uu.z = *(uint32_t*)&h2; uu.w = *(uint32_t*)&h3;
                dp[u] = uu;
            }
        }
    }
    if (tid < 64) {
        int row = row0 + tid;
        if (row < NN) {
            const float* sp = stage + tid * ST1 + 128;
#pragma unroll
            for (int h = 0; h < 4; h++) {
                g_as1[row * 4 + h] = sp[2 * h];
                g_ad1[row * 4 + h] = sp[2 * h + 1];
            }
        }
    }
}

// ---------------- GEMM2: [h2 | as2 | ad2] = relu(out1) @ [W2 | W2@P2] ---------
// M-tile 64, 8 warps = 4x2 grid; warp = 16 rows x (48|32) cols
#define LDW2 88
#define ST2 84
__global__ __launch_bounds__(256)
void k_gemm2_mma() {
    extern __shared__ char raw[];
    __half* sAh = (__half*)raw;
    __half* sAl = sAh + 64 * LDA;
    __half* sW  = (__half*)(raw + 4 * 64 * LDA);
    float* stage = (float*)raw;
    int tid = threadIdx.x;
    int row0 = blockIdx.x * 64;

    {
        const uint2* wv = (const uint2*)g_w2;
        for (int i = tid; i < 128 * 80 / 4; i += 256) {
            int k = i / 20, j = i % 20;
            *(uint2*)(sW + k * LDW2 + 4 * j) = wv[i];
        }
    }
    for (int i = tid; i < 2048; i += 256) {
        int r = i >> 5, c4 = i & 31;
        float4 v = make_float4(0.f, 0.f, 0.f, 0.f);
        if (row0 + r < NN) v = ((const float4*)g_out1)[(size_t)(row0 + r) * 32 + c4];
        int base = r * LDA + c4 * 4;
        float vv[4] = {fmaxf(v.x, 0.f), fmaxf(v.y, 0.f), fmaxf(v.z, 0.f), fmaxf(v.w, 0.f)};
#pragma unroll
        for (int j = 0; j < 4; j++) {
            __half h = __float2half_rn(vv[j]);
            sAh[base + j] = h;
            sAl[base + j] = __float2half_rn(vv[j] - __half2float(h));
        }
    }
    __syncthreads();

    int w = tid >> 5, wr = w >> 1, wc = w & 1;
    const int nf = wc ? 2 : 3;
    const int col0 = wc * 48;

    wmma::fragment<wmma::accumulator, 16, 16, 16, float> c[3];
#pragma unroll
    for (int j = 0; j < 3; j++) wmma::fill_fragment(c[j], 0.f);

    for (int kk = 0; kk < 128; kk += 16) {
        wmma::fragment<wmma::matrix_a, 16, 16, 16, __half, wmma::row_major> ah, al;
        wmma::load_matrix_sync(ah, sAh + (wr * 16) * LDA + kk, LDA);
        wmma::load_matrix_sync(al, sAl + (wr * 16) * LDA + kk, LDA);
#pragma unroll
        for (int j = 0; j < 3; j++) {
            if (j >= nf) break;
            wmma::fragment<wmma::matrix_b, 16, 16, 16, __half, wmma::row_major> bh;
            wmma::load_matrix_sync(bh, sW + kk * LDW2 + col0 + j * 16, LDW2);
            wmma::mma_sync(c[j], ah, bh, c[j]);
            wmma::mma_sync(c[j], al, bh, c[j]);
        }
    }
    __syncthreads();
#pragma unroll
    for (int j = 0; j < 3; j++) {
        if (j >= nf) break;
        wmma::store_matrix_sync(stage + (wr * 16) * ST2 + col0 + j * 16,
                                c[j], ST2, wmma::mem_row_major);
    }
    __syncthreads();

    // h2 -> fp16: 64 rows x 64 cols; thread handles 16 cols
    {
        int r = tid >> 2, q = tid & 3;
        int row = row0 + r;
        if (row < NN) {
            const float* sp = stage + r * ST2 + 16 * q;
            uint4* dp = (uint4*)(g_h2h + (size_t)row * 64 + 16 * q);
#pragma unroll
            for (int u = 0; u < 2; u++) {
                float4 a = *(const float4*)(sp + 8 * u);
                float4 b = *(const float4*)(sp + 8 * u + 4);
                __half2 h0 = __floats2half2_rn(a.x, a.y);
                __half2 h1 = __floats2half2_rn(a.z, a.w);
                __half2 h2 = __floats2half2_rn(b.x, b.y);
                __half2 h3 = __floats2half2_rn(b.z, b.w);
                uint4 uu;
                uu.x = *(uint32_t*)&h0; uu.y = *(uint32_t*)&h1;
                uu.z = *(uint32_t*)&h2; uu.w = *(uint32_t*)&h3;
                dp[u] = uu;
            }
        }
    }
    if (tid < 64) {
        int row = row0 + tid;
        if (row < NN) {
            g_as2[row] = stage[tid * ST2 + 64];
            g_ad2[row] = stage[tid * ST2 + 65];
        }
    }
}

// ---------------- gather1: 2 edges/warp, 16 lanes x 8 fp16 cols ---------------
__global__ __launch_bounds__(256)
void k_gather1(const float* __restrict__ b1) {
    int n = blockIdx.x * 8 + (threadIdx.x >> 5);
    if (n >= NN) return;
    int lane = threadIdx.x & 31;
    int g = lane >> 4, li = lane & 15;
    int head = li >> 2;
    float adh = g_ad1[4 * n + head];
    int beg = g_off[n], end = g_off[n + 1];

    float4 mx = make_float4(-3.4e38f, -3.4e38f, -3.4e38f, -3.4e38f);
    for (int j = beg + lane; j < end; j += 32) {
        int s = g_srcidx[j];
        float4 a = *(const float4*)(g_as1 + 4 * s);
        mx.x = fmaxf(mx.x, a.x); mx.y = fmaxf(mx.y, a.y);
        mx.z = fmaxf(mx.z, a.z); mx.w = fmaxf(mx.w, a.w);
    }
#pragma unroll
    for (int o = 16; o >= 1; o >>= 1) {
        mx.x = fmaxf(mx.x, __shfl_xor_sync(0xffffffffu, mx.x, o));
        mx.y = fmaxf(mx.y, __shfl_xor_sync(0xffffffffu, mx.y, o));
        mx.z = fmaxf(mx.z, __shfl_xor_sync(0xffffffffu, mx.z, o));
        mx.w = fmaxf(mx.w, __shfl_xor_sync(0xffffffffu, mx.w, o));
    }
    float mh = (head == 0) ? mx.x : (head == 1) ? mx.y : (head == 2) ? mx.z : mx.w;
    mh = lrelu(mh + adh);

    float acc[8];
#pragma unroll
    for (int q = 0; q < 8; q++) acc[q] = 0.f;
    float den = 0.f;

    int j0 = beg + g;
    int s0 = 0; float a0 = 0.f; uint4 u0 = make_uint4(0, 0, 0, 0);
    if (j0 < end) {
        s0 = g_srcidx[j0];
        a0 = g_as1[4 * s0 + head];
        u0 = *(const uint4*)(g_h1h + (size_t)s0 * 128 + 8 * li);
    }
    for (int j = j0; j < end; j += 2) {
        int s1 = 0; float a1 = 0.f; uint4 u1 = make_uint4(0, 0, 0, 0);
        if (j + 2 < end) {
            s1 = g_srcidx[j + 2];
            a1 = g_as1[4 * s1 + head];
            u1 = *(const uint4*)(g_h1h + (size_t)s1 * 128 + 8 * li);
        }
        float w = __expf(lrelu(a0 + adh) - mh);
        den += w;
        const __half2* hp = (const __half2*)&u0;
#pragma unroll
        for (int q = 0; q < 4; q++) {
            float2 f = __half22float2(hp[q]);
            acc[2 * q] += w * f.x;
            acc[2 * q + 1] += w * f.y;
        }
        s0 = s1; a0 = a1; u0 = u1;
    }
    den += __shfl_xor_sync(0xffffffffu, den, 16);
#pragma unroll
    for (int q = 0; q < 8; q++) acc[q] += __shfl_xor_sync(0xffffffffu, acc[q], 16);

    if (g == 0) {
        float inv = 1.f / (den + 1e-16f);
        float4 b0 = *(const float4*)(b1 + 8 * li);
        float4 b4 = *(const float4*)(b1 + 8 * li + 4);
        float* op = g_out1 + (size_t)n * 128 + 8 * li;
        *(float4*)op = make_float4(acc[0] * inv + b0.x, acc[1] * inv + b0.y,
                                   acc[2] * inv + b0.z, acc[3] * inv + b0.w);
        *(float4*)(op + 4) = make_float4(acc[4] * inv + b4.x, acc[5] * inv + b4.y,
                                         acc[6] * inv + b4.z, acc[7] * inv + b4.w);
    }
}

// ---------------- gather2: 4 edges/warp, 8 lanes x 8 fp16 cols ----------------
__global__ __launch_bounds__(256)
void k_gather2(const float* __restrict__ b2, float* __restrict__ out) {
    int n = blockIdx.x * 8 + (threadIdx.x >> 5);
    if (n >= NN) return;
    int lane = threadIdx.x & 31;
    int g = lane >> 3, li = lane & 7;
    float adh = g_ad2[n];
    int beg = g_off[n], end = g_off[n + 1];

    float mx = -3.4e38f;
    for (int j = beg + lane; j < end; j += 32)
        mx = fmaxf(mx, g_as2[g_srcidx[j]]);
#pragma unroll
    for (int o = 16; o >= 1; o >>= 1)
        mx = fmaxf(mx, __shfl_xor_sync(0xffffffffu, mx, o));
    float mh = lrelu(mx + adh);

    float acc[8];
#pragma unroll
    for (int q = 0; q < 8; q++) acc[q] = 0.f;
    float den = 0.f;

    int j0 = beg + g;
    int s0 = 0; float a0 = 0.f; uint4 u0 = make_uint4(0, 0, 0, 0);
    if (j0 < end) {
        s0 = g_srcidx[j0];
        a0 = g_as2[s0];
        u0 = *(const uint4*)(g_h2h + (size_t)s0 * 64 + 8 * li);
    }
    for (int j = j0; j < end; j += 4) {
        int s1 = 0; float a1 = 0.f; uint4 u1 = make_uint4(0, 0, 0, 0);
        if (j + 4 < end) {
            s1 = g_srcidx[j + 4];
            a1 = g_as2[s1];
            u1 = *(const uint4*)(g_h2h + (size_t)s1 * 64 + 8 * li);
        }
        float w = __expf(lrelu(a0 + adh) - mh);
        den += w;
        const __half2* hp = (const __half2*)&u0;
#pragma unroll
        for (int q = 0; q < 4; q++) {
            float2 f = __half22float2(hp[q]);
            acc[2 * q] += w * f.x;
            acc[2 * q + 1] += w * f.y;
        }
        s0 = s1; a0 = a1; u0 = u1;
    }
    den += __shfl_xor_sync(0xffffffffu, den, 8);
    den += __shfl_xor_sync(0xffffffffu, den, 16);
#pragma unroll
    for (int q = 0; q < 8; q++) {
        acc[q] += __shfl_xor_sync(0xffffffffu, acc[q], 8);
        acc[q] += __shfl_xor_sync(0xffffffffu, acc[q], 16);
    }

    if (g == 0) {
        float inv = 1.f / (den + 1e-16f);
        float4 b0 = *(const float4*)(b2 + 8 * li);
        float4 b4 = *(const float4*)(b2 + 8 * li + 4);
        float* op = out + (size_t)n * 64 + 8 * li;
        *(float4*)op = make_float4(acc[0] * inv + b0.x, acc[1] * inv + b0.y,
                                   acc[2] * inv + b0.z, acc[3] * inv + b0.w);
        *(float4*)(op + 4) = make_float4(acc[4] * inv + b4.x, acc[5] * inv + b4.y,
                                         acc[6] * inv + b4.z, acc[7] * inv + b4.w);
    }
}

// ---------------- launch ------------------------------------------------------
extern "C" void kernel_launch(void* const* d_in, const int* in_sizes, int n_in,
                              void* d_out, int out_size) {
    const float* x   = (const float*)d_in[0];
    const int*   ei  = (const int*)d_in[1];
    const float* W1  = (const float*)d_in[2];
    const float* as1 = (const float*)d_in[3];
    const float* ad1 = (const float*)d_in[4];
    const float* b1  = (const float*)d_in[5];
    const float* W2  = (const float*)d_in[6];
    const float* as2 = (const float*)d_in[7];
    const float* ad2 = (const float*)d_in[8];
    const float* b2  = (const float*)d_in[9];
    float* out = (float*)d_out;

    const int smem1 = 4 * 64 * LDA + 2 * 128 * LDW1;   // 34816 + 38912 = 73728
    const int smem2 = 4 * 64 * LDA + 2 * 128 * LDW2;   // 34816 + 22528 = 57344
    static bool attr_done = false;
    if (!attr_done) {
        cudaFuncSetAttribute(k_gemm1_mma, cudaFuncAttributeMaxDynamicSharedMemorySize, smem1);
        cudaFuncSetAttribute(k_gemm2_mma, cudaFuncAttributeMaxDynamicSharedMemorySize, smem2);
        attr_done = true;
    }

    // prep: hist + weight conversion + lookback-flag reset
    k_prep<<<HIST_BLKS + 112 + 1, 256>>>(ei, W1, W2, as1, ad1, as2, ad2);
    // single-pass CSR offsets (decoupled lookback)
    k_scan<<<NBLK, 256>>>();
    k_fill<<<(NE / 4 + 255) / 256, 256>>>(ei);

    // layer 1
    k_gemm1_mma<<<NP / 64, 256, smem1>>>(x);
    k_gather1<<<(NN + 7) / 8, 256>>>(b1);

    // layer 2
    k_gemm2_mma<<<NP / 64, 256, smem2>>>();
    k_gather2<<<(NN + 7) / 8, 256>>>(b2, out);
}

// round 11
// speedup vs baseline: 2.3254x; 1.0544x over previous
#include <cuda_runtime.h>
#include <cuda_bf16.h>
#include <cuda_fp16.h>
#include <mma.h>
#include <cstdint>

using namespace nvcuda;

#define NN 50000
#define NP 50048          // 782 * 64
#define NE 800000
#define ET 850000         // NE + NN self loops
#define NS 0.2f
#define NBLK 196          // ceil(NN/256)

// ---------------- scratch (device globals) -----------------------------------
__device__ __half g_xh[NN * 128];    // X split hi
__device__ __half g_xl[NN * 128];    // X split lo
__device__ __half g_h1h[NN * 128];
__device__ float  g_out1[NN * 128];
__device__ float  g_as1[NN * 4];
__device__ float  g_ad1[NN * 4];
__device__ __half g_h2h[NN * 64];
__device__ float  g_as2[NN];
__device__ float  g_ad2[NN];
__device__ float  g_mx1[4];          // global per-head max of as1
__device__ float  g_mx2;             // global max of as2
__device__ int g_deg[NN];            // invariant: zero before/after every call
__device__ int g_off[NN + 1];
__device__ int g_cur[NN];
__device__ int g_srcidx[ET];
__device__ unsigned int g_blkst[NBLK];
// fp16 weights with fused alpha columns
__device__ __half g_w1[128 * 144];
__device__ __half g_w2[128 * 80];

__device__ __forceinline__ float lrelu(float v) { return v >= 0.f ? v : NS * v; }

__device__ __forceinline__ void atomicMaxF(float* addr, float v) {
    if (v >= 0.f) atomicMax((int*)addr, __float_as_int(v));
    else          atomicMin((unsigned int*)addr, __float_as_uint(v));
}

// ---------------- prep: hist + convw + reset + X split -----------------------
#define HIST_BLKS 782
#define CONV_BLKS 112
#define XS0 (HIST_BLKS + CONV_BLKS + 1)      // 895
#define XS_BLKS 1563                          // ceil(NN*32 / 1024)
__global__ void k_prep(const int* __restrict__ ei, const float* __restrict__ X,
                       const float* __restrict__ W1, const float* __restrict__ W2,
                       const float* __restrict__ as1, const float* __restrict__ ad1,
                       const float* __restrict__ as2, const float* __restrict__ ad2) {
    int b = blockIdx.x, t = threadIdx.x;
    if (b < HIST_BLKS) {
        int i = b * 256 + t;
        if (i >= NE / 4) return;
        int4 d4 = ((const int4*)(ei + NE))[i];
        atomicAdd(&g_deg[d4.x], 1);
        atomicAdd(&g_deg[d4.y], 1);
        atomicAdd(&g_deg[d4.z], 1);
        atomicAdd(&g_deg[d4.w], 1);
        return;
    }
    if (b >= XS0) {                            // X fp32 -> fp16 hi/lo
        int base = (b - XS0) * 1024 + t;
#pragma unroll
        for (int q = 0; q < 4; q++) {
            int idx = base + q * 256;          // float4 index
            if (idx < NN * 32) {
                float4 v = ((const float4*)X)[idx];
                __half2 h0 = __floats2half2_rn(v.x, v.y);
                __half2 h1 = __floats2half2_rn(v.z, v.w);
                float2 f0 = __half22float2(h0), f1 = __half22float2(h1);
                __half2 l0 = __floats2half2_rn(v.x - f0.x, v.y - f0.y);
                __half2 l1 = __floats2half2_rn(v.z - f1.x, v.w - f1.y);
                uint2 uh, ul;
                uh.x = *(uint32_t*)&h0; uh.y = *(uint32_t*)&h1;
                ul.x = *(uint32_t*)&l0; ul.y = *(uint32_t*)&l1;
                ((uint2*)g_xh)[idx] = uh;
                ((uint2*)g_xl)[idx] = ul;
            }
        }
        return;
    }
    if (b == HIST_BLKS + CONV_BLKS) {          // reset block
        if (t < NBLK) g_blkst[t] = 0u;
        if (t == 0) {
            g_off[NN] = ET;
            g_mx1[0] = -3.4e38f; g_mx1[1] = -3.4e38f;
            g_mx1[2] = -3.4e38f; g_mx1[3] = -3.4e38f;
            g_mx2 = -3.4e38f;
        }
        return;
    }
    int s = (b - HIST_BLKS) * 256 + t;         // weight conversion
    float val; int dsth, dstl;
    if (s < 16384) {
        int k = s >> 7, n = s & 127;
        val = W1[k * 128 + n];
        dsth = k * 144 + n; dstl = 1;
    } else if (s < 17408) {
        int i = s - 16384;
        int k = i >> 3, c = i & 7, h = c >> 1;
        const float* a = (c & 1) ? ad1 : as1;
        float sum = 0.f;
#pragma unroll
        for (int f = 0; f < 32; f++) sum += W1[k * 128 + h * 32 + f] * a[h * 32 + f];
        val = sum; dsth = k * 144 + 128 + c; dstl = 1;
    } else if (s < 18432) {
        int i = s - 17408;
        int k = i >> 3, c = i & 7;
        val = 0.f; dsth = k * 144 + 136 + c; dstl = 1;
    } else if (s < 26624) {
        int i = s - 18432;
        int k = i >> 6, n = i & 63;
        val = W2[k * 64 + n];
        dsth = k * 80 + n; dstl = 2;
    } else if (s < 26880) {
        int i = s - 26624;
        int k = i >> 1, c = i & 1;
        const float* a = c ? ad2 : as2;
        float sum = 0.f;
#pragma unroll
        for (int f = 0; f < 64; f++) sum += W2[k * 64 + f] * a[f];
        val = sum; dsth = k * 80 + 64 + c; dstl = 2;
    } else if (s < 28672) {
        int i = s - 26880;
        int k = i / 14, c = i % 14;
        val = 0.f; dsth = k * 80 + 66 + c; dstl = 2;
    } else return;
    __half hv = __float2half_rn(val);
    if (dstl == 1) g_w1[dsth] = hv;
    else           g_w2[dsth] = hv;
}

// ---------------- single-pass scan with decoupled lookback --------------------
__global__ void k_scan() {
    __shared__ int sh[256];
    __shared__ int s_excl;
    int t = threadIdx.x, b = blockIdx.x;
    int i = b * 256 + t;
    int v = (i < NN) ? g_deg[i] + 1 : 0;   // +1 self loop
    sh[t] = v;
    __syncthreads();
#pragma unroll
    for (int o = 1; o < 256; o <<= 1) {
        int tv = (t >= o) ? sh[t - o] : 0;
        __syncthreads();
        sh[t] += tv;
        __syncthreads();
    }
    int incl = sh[t];
    int total = sh[255];

    if (t == 0) {
        if (b == 0) {
            atomicExch(&g_blkst[0], ((unsigned)total << 2) | 2u);
            s_excl = 0;
        } else {
            atomicExch(&g_blkst[b], ((unsigned)total << 2) | 1u);
            int run = 0;
            for (int p = b - 1; p >= 0; p--) {
                unsigned st;
                do { st = atomicAdd(&g_blkst[p], 0u); } while ((st & 3u) == 0u);
                run += (int)(st >> 2);
                if ((st & 3u) == 2u) break;
            }
            s_excl = run;
            atomicExch(&g_blkst[b], ((unsigned)(run + total) << 2) | 2u);
        }
    }
    __syncthreads();
    if (i < NN) {
        int off = s_excl + incl - v;
        g_off[i] = off;
        g_srcidx[off] = i;      // self loop seeded first
        g_cur[i] = off + 1;
        g_deg[i] = 0;           // restore invariant
    }
}

__global__ void k_fill(const int* __restrict__ ei) {
    int i = blockIdx.x * blockDim.x + threadIdx.x;
    if (i >= NE / 4) return;
    int4 s4 = ((const int4*)ei)[i];
    int4 d4 = ((const int4*)(ei + NE))[i];
    int p;
    p = atomicAdd(&g_cur[d4.x], 1); g_srcidx[p] = s4.x;
    p = atomicAdd(&g_cur[d4.y], 1); g_srcidx[p] = s4.y;
    p = atomicAdd(&g_cur[d4.z], 1); g_srcidx[p] = s4.z;
    p = atomicAdd(&g_cur[d4.w], 1); g_srcidx[p] = s4.w;
}

// ---------------- GEMM1: [h1 | as1 | ad1] = x @ [W1 | W1@P] -------------------
// M-tile 64, fp16 pre-split A (pure copy), W fp16 smem
#define LDA 136
#define LDW1 152
#define ST1 148
__global__ __launch_bounds__(256)
void k_gemm1_mma() {
    extern __shared__ char raw[];
    __half* sAh = (__half*)raw;
    __half* sAl = sAh + 64 * LDA;
    __half* sW  = (__half*)(raw + 4 * 64 * LDA);
    float* stage = (float*)raw;
    int tid = threadIdx.x;
    int row0 = blockIdx.x * 64;

    // W copy
    {
        const uint2* wv = (const uint2*)g_w1;
        for (int i = tid; i < 128 * 144 / 4; i += 256) {
            int k = i / 36, j = i % 36;
            *(uint2*)(sW + k * LDW1 + 4 * j) = wv[i];
        }
    }
    // A copy: 64 rows x 16 uint4 per array
    for (int i = tid; i < 1024; i += 256) {
        int r = i >> 4, c = i & 15;
        uint4 vh = make_uint4(0, 0, 0, 0), vl = make_uint4(0, 0, 0, 0);
        if (row0 + r < NN) {
            vh = ((const uint4*)g_xh)[(size_t)(row0 + r) * 16 + c];
            vl = ((const uint4*)g_xl)[(size_t)(row0 + r) * 16 + c];
        }
        *(uint4*)(sAh + r * LDA + 8 * c) = vh;
        *(uint4*)(sAl + r * LDA + 8 * c) = vl;
    }
    __syncthreads();

    int w = tid >> 5, wr = w >> 1, wc = w & 1;
    const int nf = wc ? 4 : 5;
    const int col0 = wc * 80;

    wmma::fragment<wmma::accumulator, 16, 16, 16, float> c[5];
#pragma unroll
    for (int j = 0; j < 5; j++) wmma::fill_fragment(c[j], 0.f);

    for (int kk = 0; kk < 128; kk += 16) {
        wmma::fragment<wmma::matrix_a, 16, 16, 16, __half, wmma::row_major> ah, al;
        wmma::load_matrix_sync(ah, sAh + (wr * 16) * LDA + kk, LDA);
        wmma::load_matrix_sync(al, sAl + (wr * 16) * LDA + kk, LDA);
#pragma unroll
        for (int j = 0; j < 5; j++) {
            if (j >= nf) break;
            wmma::fragment<wmma::matrix_b, 16, 16, 16, __half, wmma::row_major> bh;
            wmma::load_matrix_sync(bh, sW + kk * LDW1 + col0 + j * 16, LDW1);
            wmma::mma_sync(c[j], ah, bh, c[j]);
            wmma::mma_sync(c[j], al, bh, c[j]);
        }
    }
    __syncthreads();
#pragma unroll
    for (int j = 0; j < 5; j++) {
        if (j >= nf) break;
        wmma::store_matrix_sync(stage + (wr * 16) * ST1 + col0 + j * 16,
                                c[j], ST1, wmma::mem_row_major);
    }
    __syncthreads();

    // h1 -> fp16
    {
        int r = tid >> 2, q = tid & 3;
        int row = row0 + r;
        if (row < NN) {
            const float* sp = stage + r * ST1 + 32 * q;
            uint4* dp = (uint4*)(g_h1h + (size_t)row * 128 + 32 * q);
#pragma unroll
            for (int u = 0; u < 4; u++) {
                float4 a = *(const float4*)(sp + 8 * u);
                float4 b = *(const float4*)(sp + 8 * u + 4);
                __half2 h0 = __floats2half2_rn(a.x, a.y);
                __half2 h1 = __floats2half2_rn(a.z, a.w);
                __half2 h2 = __floats2half2_rn(b.x, b.y);
                __half2 h3 = __floats2half2_rn(b.z, b.w);
                uint4 uu;
                uu.x = *(uint32_t*)&h0; uu.y = *(uint32_t*)&h1;
                uu.z = *(uint32_t*)&h2; uu.w = *(uint32_t*)&h3;
                dp[u] = uu;
            }
        }
    }
    // alphas + global per-head max of as
    if (tid < 64) {
        int row = row0 + tid;
        const float* sp = stage + tid * ST1 + 128;
        float ps[4];
#pragma unroll
        for (int h = 0; h < 4; h++) {
            float a_ = sp[2 * h], d_ = sp[2 * h + 1];
            if (row < NN) {
                g_as1[row * 4 + h] = a_;
                g_ad1[row * 4 + h] = d_;
                ps[h] = a_;
            } else ps[h] = -3.4e38f;
        }
#pragma unroll
        for (int h = 0; h < 4; h++) {
#pragma unroll
            for (int o = 16; o >= 1; o >>= 1)
                ps[h] = fmaxf(ps[h], __shfl_xor_sync(0xffffffffu, ps[h], o));
        }
        if ((tid & 31) == 0) {
#pragma unroll
            for (int h = 0; h < 4; h++) atomicMaxF(&g_mx1[h], ps[h]);
        }
    }
}

// ---------------- GEMM2: [h2 | as2 | ad2] = relu(out1) @ [W2 | W2@P2] ---------
#define LDW2 88
#define ST2 84
__global__ __launch_bounds__(256)
void k_gemm2_mma() {
    extern __shared__ char raw[];
    __half* sAh = (__half*)raw;
    __half* sAl = sAh + 64 * LDA;
    __half* sW  = (__half*)(raw + 4 * 64 * LDA);
    float* stage = (float*)raw;
    int tid = threadIdx.x;
    int row0 = blockIdx.x * 64;

    {
        const uint2* wv = (const uint2*)g_w2;
        for (int i = tid; i < 128 * 80 / 4; i += 256) {
            int k = i / 20, j = i % 20;
            *(uint2*)(sW + k * LDW2 + 4 * j) = wv[i];
        }
    }
    for (int i = tid; i < 2048; i += 256) {
        int r = i >> 5, c4 = i & 31;
        float4 v = make_float4(0.f, 0.f, 0.f, 0.f);
        if (row0 + r < NN) v = ((const float4*)g_out1)[(size_t)(row0 + r) * 32 + c4];
        int base = r * LDA + c4 * 4;
        float vv[4] = {fmaxf(v.x, 0.f), fmaxf(v.y, 0.f), fmaxf(v.z, 0.f), fmaxf(v.w, 0.f)};
#pragma unroll
        for (int j = 0; j < 4; j++) {
            __half h = __float2half_rn(vv[j]);
            sAh[base + j] = h;
            sAl[base + j] = __float2half_rn(vv[j] - __half2float(h));
        }
    }
    __syncthreads();

    int w = tid >> 5, wr = w >> 1, wc = w & 1;
    const int nf = wc ? 2 : 3;
    const int col0 = wc * 48;

    wmma::fragment<wmma::accumulator, 16, 16, 16, float> c[3];
#pragma unroll
    for (int j = 0; j < 3; j++) wmma::fill_fragment(c[j], 0.f);

    for (int kk = 0; kk < 128; kk += 16) {
        wmma::fragment<wmma::matrix_a, 16, 16, 16, __half, wmma::row_major> ah, al;
        wmma::load_matrix_sync(ah, sAh + (wr * 16) * LDA + kk, LDA);
        wmma::load_matrix_sync(al, sAl + (wr * 16) * LDA + kk, LDA);
#pragma unroll
        for (int j = 0; j < 3; j++) {
            if (j >= nf) break;
            wmma::fragment<wmma::matrix_b, 16, 16, 16, __half, wmma::row_major> bh;
            wmma::load_matrix_sync(bh, sW + kk * LDW2 + col0 + j * 16, LDW2);
            wmma::mma_sync(c[j], ah, bh, c[j]);
            wmma::mma_sync(c[j], al, bh, c[j]);
        }
    }
    __syncthreads();
#pragma unroll
    for (int j = 0; j < 3; j++) {
        if (j >= nf) break;
        wmma::store_matrix_sync(stage + (wr * 16) * ST2 + col0 + j * 16,
                                c[j], ST2, wmma::mem_row_major);
    }
    __syncthreads();

    {
        int r = tid >> 2, q = tid & 3;
        int row = row0 + r;
        if (row < NN) {
            const float* sp = stage + r * ST2 + 16 * q;
            uint4* dp = (uint4*)(g_h2h + (size_t)row * 64 + 16 * q);
#pragma unroll
            for (int u = 0; u < 2; u++) {
                float4 a = *(const float4*)(sp + 8 * u);
                float4 b = *(const float4*)(sp + 8 * u + 4);
                __half2 h0 = __floats2half2_rn(a.x, a.y);
                __half2 h1 = __floats2half2_rn(a.z, a.w);
                __half2 h2 = __floats2half2_rn(b.x, b.y);
                __half2 h3 = __floats2half2_rn(b.z, b.w);
                uint4 uu;
                uu.x = *(uint32_t*)&h0; uu.y = *(uint32_t*)&h1;
                uu.z = *(uint32_t*)&h2; uu.w = *(uint32_t*)&h3;
                dp[u] = uu;
            }
        }
    }
    if (tid < 64) {
        int row = row0 + tid;
        float ps;
        if (row < NN) {
            ps = stage[tid * ST2 + 64];
            g_as2[row] = ps;
            g_ad2[row] = stage[tid * ST2 + 65];
        } else ps = -3.4e38f;
#pragma unroll
        for (int o = 16; o >= 1; o >>= 1)
            ps = fmaxf(ps, __shfl_xor_sync(0xffffffffu, ps, o));
        if ((tid & 31) == 0) atomicMaxF(&g_mx2, ps);
    }
}

// ---------------- gather1: 2 edges/warp, 16 lanes x 8 fp16 cols ---------------
__global__ __launch_bounds__(256)
void k_gather1(const float* __restrict__ b1) {
    int n = blockIdx.x * 8 + (threadIdx.x >> 5);
    if (n >= NN) return;
    int lane = threadIdx.x & 31;
    int g = lane >> 4, li = lane & 15;
    int head = li >> 2;
    float adh = g_ad1[4 * n + head];
    int beg = g_off[n], end = g_off[n + 1];

    // global-shift softmax: mh >= all e in this neighborhood (lrelu monotonic)
    float mh = lrelu(g_mx1[head] + adh);

    float acc[8];
#pragma unroll
    for (int q = 0; q < 8; q++) acc[q] = 0.f;
    float den = 0.f;

    int j0 = beg + g;
    int s0 = 0; float a0 = 0.f; uint4 u0 = make_uint4(0, 0, 0, 0);
    if (j0 < end) {
        s0 = g_srcidx[j0];
        a0 = g_as1[4 * s0 + head];
        u0 = *(const uint4*)(g_h1h + (size_t)s0 * 128 + 8 * li);
    }
    for (int j = j0; j < end; j += 2) {
        int s1 = 0; float a1 = 0.f; uint4 u1 = make_uint4(0, 0, 0, 0);
        if (j + 2 < end) {
            s1 = g_srcidx[j + 2];
            a1 = g_as1[4 * s1 + head];
            u1 = *(const uint4*)(g_h1h + (size_t)s1 * 128 + 8 * li);
        }
        float w = __expf(lrelu(a0 + adh) - mh);
        den += w;
        const __half2* hp = (const __half2*)&u0;
#pragma unroll
        for (int q = 0; q < 4; q++) {
            float2 f = __half22float2(hp[q]);
            acc[2 * q] += w * f.x;
            acc[2 * q + 1] += w * f.y;
        }
        s0 = s1; a0 = a1; u0 = u1;
    }
    den += __shfl_xor_sync(0xffffffffu, den, 16);
#pragma unroll
    for (int q = 0; q < 8; q++) acc[q] += __shfl_xor_sync(0xffffffffu, acc[q], 16);

    if (g == 0) {
        float inv = 1.f / (den + 1e-16f);
        float4 b0 = *(const float4*)(b1 + 8 * li);
        float4 b4 = *(const float4*)(b1 + 8 * li + 4);
        float* op = g_out1 + (size_t)n * 128 + 8 * li;
        *(float4*)op = make_float4(acc[0] * inv + b0.x, acc[1] * inv + b0.y,
                                   acc[2] * inv + b0.z, acc[3] * inv + b0.w);
        *(float4*)(op + 4) = make_float4(acc[4] * inv + b4.x, acc[5] * inv + b4.y,
                                         acc[6] * inv + b4.z, acc[7] * inv + b4.w);
    }
}

// ---------------- gather2: 4 edges/warp, 8 lanes x 8 fp16 cols ----------------
__global__ __launch_bounds__(256)
void k_gather2(const float* __restrict__ b2, float* __restrict__ out) {
    int n = blockIdx.x * 8 + (threadIdx.x >> 5);
    if (n >= NN) return;
    int lane = threadIdx.x & 31;
    int g = lane >> 3, li = lane & 7;
    float adh = g_ad2[n];
    int beg = g_off[n], end = g_off[n + 1];

    float mh = lrelu(g_mx2 + adh);

    float acc[8];
#pragma unroll
    for (int q = 0; q < 8; q++) acc[q] = 0.f;
    float den = 0.f;

    int j0 = beg + g;
    int s0 = 0; float a0 = 0.f; uint4 u0 = make_uint4(0, 0, 0, 0);
    if (j0 < end) {
        s0 = g_srcidx[j0];
        a0 = g_as2[s0];
        u0 = *(const uint4*)(g_h2h + (size_t)s0 * 64 + 8 * li);
    }
    for (int j = j0; j < end; j += 4) {
        int s1 = 0; float a1 = 0.f; uint4 u1 = make_uint4(0, 0, 0, 0);
        if (j + 4 < end) {
            s1 = g_srcidx[j + 4];
            a1 = g_as2[s1];
            u1 = *(const uint4*)(g_h2h + (size_t)s1 * 64 + 8 * li);
        }
        float w = __expf(lrelu(a0 + adh) - mh);
        den += w;
        const __half2* hp = (const __half2*)&u0;
#pragma unroll
        for (int q = 0; q < 4; q++) {
            float2 f = __half22float2(hp[q]);
            acc[2 * q] += w * f.x;
            acc[2 * q + 1] += w * f.y;
        }
        s0 = s1; a0 = a1; u0 = u1;
    }
    den += __shfl_xor_sync(0xffffffffu, den, 8);
    den += __shfl_xor_sync(0xffffffffu, den, 16);
#pragma unroll
    for (int q = 0; q < 8; q++) {
        acc[q] += __shfl_xor_sync(0xffffffffu, acc[q], 8);
        acc[q] += __shfl_xor_sync(0xffffffffu, acc[q], 16);
    }

    if (g == 0) {
        float inv = 1.f / (den + 1e-16f);
        float4 b0 = *(const float4*)(b2 + 8 * li);
        float4 b4 = *(const float4*)(b2 + 8 * li + 4);
        float* op = out + (size_t)n * 64 + 8 * li;
        *(float4*)op = make_float4(acc[0] * inv + b0.x, acc[1] * inv + b0.y,
                                   acc[2] * inv + b0.z, acc[3] * inv + b0.w);
        *(float4*)(op + 4) = make_float4(acc[4] * inv + b4.x, acc[5] * inv + b4.y,
                                         acc[6] * inv + b4.z, acc[7] * inv + b4.w);
    }
}

// ---------------- launch ------------------------------------------------------
extern "C" void kernel_launch(void* const* d_in, const int* in_sizes, int n_in,
                              void* d_out, int out_size) {
    const float* x   = (const float*)d_in[0];
    const int*   ei  = (const int*)d_in[1];
    const float* W1  = (const float*)d_in[2];
    const float* as1 = (const float*)d_in[3];
    const float* ad1 = (const float*)d_in[4];
    const float* b1  = (const float*)d_in[5];
    const float* W2  = (const float*)d_in[6];
    const float* as2 = (const float*)d_in[7];
    const float* ad2 = (const float*)d_in[8];
    const float* b2  = (const float*)d_in[9];
    float* out = (float*)d_out;

    const int smem1 = 4 * 64 * LDA + 2 * 128 * LDW1;   // 34816 + 38912 = 73728
    const int smem2 = 4 * 64 * LDA + 2 * 128 * LDW2;   // 34816 + 22528 = 57344
    static bool attr_done = false;
    if (!attr_done) {
        cudaFuncSetAttribute(k_gemm1_mma, cudaFuncAttributeMaxDynamicSharedMemorySize, smem1);
        cudaFuncSetAttribute(k_gemm2_mma, cudaFuncAttributeMaxDynamicSharedMemorySize, smem2);
        attr_done = true;
    }

    // prep: hist + weight conversion + reset + X split
    k_prep<<<XS0 + XS_BLKS, 256>>>(ei, x, W1, W2, as1, ad1, as2, ad2);
    // single-pass CSR offsets (decoupled lookback)
    k_scan<<<NBLK, 256>>>();
    k_fill<<<(NE / 4 + 255) / 256, 256>>>(ei);

    // layer 1
    k_gemm1_mma<<<NP / 64, 256, smem1>>>();
    k_gather1<<<(NN + 7) / 8, 256>>>(b1);

    // layer 2
    k_gemm2_mma<<<NP / 64, 256, smem2>>>();
    k_gather2<<<(NN + 7) / 8, 256>>>(b2, out);
}

// round 12
// speedup vs baseline: 2.5069x; 1.0781x over previous
#include <cuda_runtime.h>
#include <cuda_bf16.h>
#include <cuda_fp16.h>
#include <mma.h>
#include <cstdint>

using namespace nvcuda;

#define NN 50000
#define NP 50048          // 782 * 64
#define NE 800000
#define ET 850000         // NE + NN self loops
#define NS 0.2f
#define NBLK 196          // ceil(NN/256)

// ---------------- scratch (device globals) -----------------------------------
__device__ __half g_xh[NN * 128];    // X split hi
__device__ __half g_xl[NN * 128];    // X split lo
__device__ __half g_h1h[NN * 128];
__device__ float  g_out1[NN * 128];
__device__ float  g_as1[NN * 4];
__device__ float  g_ad1[NN * 4];
__device__ __half g_h2h[NN * 64];
__device__ float  g_as2[NN];
__device__ float  g_ad2[NN];
__device__ float  g_mx1[4];          // global per-head max of as1
__device__ float  g_mx2;             // global max of as2
__device__ int g_deg[NN];            // invariant: zero before/after every call
__device__ int g_off[NN + 1];
__device__ int g_cur[NN];
__device__ int g_srcidx[ET];
__device__ unsigned int g_blkst[NBLK];
// fp16 weights with fused alpha columns
__device__ __half g_w1[128 * 144];
__device__ __half g_w2[128 * 80];

__device__ __forceinline__ float lrelu(float v) { return v >= 0.f ? v : NS * v; }

__device__ __forceinline__ void atomicMaxF(float* addr, float v) {
    if (v >= 0.f) atomicMax((int*)addr, __float_as_int(v));
    else          atomicMin((unsigned int*)addr, __float_as_uint(v));
}

__device__ __forceinline__ uint32_t smem_u32(const void* p) {
    uint32_t a;
    asm("{ .reg .u64 t; cvta.to.shared.u64 t, %1; cvt.u32.u64 %0, t; }" : "=r"(a) : "l"(p));
    return a;
}
__device__ __forceinline__ void cp16(void* smem, const void* gmem) {
    asm volatile("cp.async.cg.shared.global [%0], [%1], 16;"
                 :: "r"(smem_u32(smem)), "l"(gmem) : "memory");
}
__device__ __forceinline__ void cp_commit_wait() {
    asm volatile("cp.async.commit_group;" ::: "memory");
    asm volatile("cp.async.wait_group 0;" ::: "memory");
}

// ---------------- prep: hist + convw + reset + X split -----------------------
#define HIST_BLKS 782
#define CONV_BLKS 112
#define XS0 (HIST_BLKS + CONV_BLKS + 1)      // 895
#define XS_BLKS 1563                          // ceil(NN*32 / 1024)
__global__ void k_prep(const int* __restrict__ ei, const float* __restrict__ X,
                       const float* __restrict__ W1, const float* __restrict__ W2,
                       const float* __restrict__ as1, const float* __restrict__ ad1,
                       const float* __restrict__ as2, const float* __restrict__ ad2) {
    int b = blockIdx.x, t = threadIdx.x;
    if (b < HIST_BLKS) {
        int i = b * 256 + t;
        if (i >= NE / 4) return;
        int4 d4 = ((const int4*)(ei + NE))[i];
        atomicAdd(&g_deg[d4.x], 1);
        atomicAdd(&g_deg[d4.y], 1);
        atomicAdd(&g_deg[d4.z], 1);
        atomicAdd(&g_deg[d4.w], 1);
        return;
    }
    if (b >= XS0) {                            // X fp32 -> fp16 hi/lo
        int base = (b - XS0) * 1024 + t;
#pragma unroll
        for (int q = 0; q < 4; q++) {
            int idx = base + q * 256;          // float4 index
            if (idx < NN * 32) {
                float4 v = ((const float4*)X)[idx];
                __half2 h0 = __floats2half2_rn(v.x, v.y);
                __half2 h1 = __floats2half2_rn(v.z, v.w);
                float2 f0 = __half22float2(h0), f1 = __half22float2(h1);
                __half2 l0 = __floats2half2_rn(v.x - f0.x, v.y - f0.y);
                __half2 l1 = __floats2half2_rn(v.z - f1.x, v.w - f1.y);
                uint2 uh, ul;
                uh.x = *(uint32_t*)&h0; uh.y = *(uint32_t*)&h1;
                ul.x = *(uint32_t*)&l0; ul.y = *(uint32_t*)&l1;
                ((uint2*)g_xh)[idx] = uh;
                ((uint2*)g_xl)[idx] = ul;
            }
        }
        return;
    }
    if (b == HIST_BLKS + CONV_BLKS) {          // reset block
        if (t < NBLK) g_blkst[t] = 0u;
        if (t == 0) {
            g_off[NN] = ET;
            g_mx1[0] = -3.4e38f; g_mx1[1] = -3.4e38f;
            g_mx1[2] = -3.4e38f; g_mx1[3] = -3.4e38f;
            g_mx2 = -3.4e38f;
        }
        return;
    }
    int s = (b - HIST_BLKS) * 256 + t;         // weight conversion
    float val; int dsth, dstl;
    if (s < 16384) {
        int k = s >> 7, n = s & 127;
        val = W1[k * 128 + n];
        dsth = k * 144 + n; dstl = 1;
    } else if (s < 17408) {
        int i = s - 16384;
        int k = i >> 3, c = i & 7, h = c >> 1;
        const float* a = (c & 1) ? ad1 : as1;
        float sum = 0.f;
#pragma unroll
        for (int f = 0; f < 32; f++) sum += W1[k * 128 + h * 32 + f] * a[h * 32 + f];
        val = sum; dsth = k * 144 + 128 + c; dstl = 1;
    } else if (s < 18432) {
        int i = s - 17408;
        int k = i >> 3, c = i & 7;
        val = 0.f; dsth = k * 144 + 136 + c; dstl = 1;
    } else if (s < 26624) {
        int i = s - 18432;
        int k = i >> 6, n = i & 63;
        val = W2[k * 64 + n];
        dsth = k * 80 + n; dstl = 2;
    } else if (s < 26880) {
        int i = s - 26624;
        int k = i >> 1, c = i & 1;
        const float* a = c ? ad2 : as2;
        float sum = 0.f;
#pragma unroll
        for (int f = 0; f < 64; f++) sum += W2[k * 64 + f] * a[f];
        val = sum; dsth = k * 80 + 64 + c; dstl = 2;
    } else if (s < 28672) {
        int i = s - 26880;
        int k = i / 14, c = i % 14;
        val = 0.f; dsth = k * 80 + 66 + c; dstl = 2;
    } else return;
    __half hv = __float2half_rn(val);
    if (dstl == 1) g_w1[dsth] = hv;
    else           g_w2[dsth] = hv;
}

// ---------------- single-pass scan with decoupled lookback --------------------
__global__ void k_scan() {
    __shared__ int sh[256];
    __shared__ int s_excl;
    int t = threadIdx.x, b = blockIdx.x;
    int i = b * 256 + t;
    int v = (i < NN) ? g_deg[i] + 1 : 0;   // +1 self loop
    sh[t] = v;
    __syncthreads();
#pragma unroll
    for (int o = 1; o < 256; o <<= 1) {
        int tv = (t >= o) ? sh[t - o] : 0;
        __syncthreads();
        sh[t] += tv;
        __syncthreads();
    }
    int incl = sh[t];
    int total = sh[255];

    if (t == 0) {
        if (b == 0) {
            atomicExch(&g_blkst[0], ((unsigned)total << 2) | 2u);
            s_excl = 0;
        } else {
            atomicExch(&g_blkst[b], ((unsigned)total << 2) | 1u);
            int run = 0;
            for (int p = b - 1; p >= 0; p--) {
                unsigned st;
                do { st = atomicAdd(&g_blkst[p], 0u); } while ((st & 3u) == 0u);
                run += (int)(st >> 2);
                if ((st & 3u) == 2u) break;
            }
            s_excl = run;
            atomicExch(&g_blkst[b], ((unsigned)(run + total) << 2) | 2u);
        }
    }
    __syncthreads();
    if (i < NN) {
        int off = s_excl + incl - v;
        g_off[i] = off;
        g_srcidx[off] = i;      // self loop seeded first
        g_cur[i] = off + 1;
        g_deg[i] = 0;           // restore invariant
    }
}

__global__ void k_fill(const int* __restrict__ ei) {
    int i = blockIdx.x * blockDim.x + threadIdx.x;
    if (i >= NE / 4) return;
    int4 s4 = ((const int4*)ei)[i];
    int4 d4 = ((const int4*)(ei + NE))[i];
    int p;
    p = atomicAdd(&g_cur[d4.x], 1); g_srcidx[p] = s4.x;
    p = atomicAdd(&g_cur[d4.y], 1); g_srcidx[p] = s4.y;
    p = atomicAdd(&g_cur[d4.z], 1); g_srcidx[p] = s4.z;
    p = atomicAdd(&g_cur[d4.w], 1); g_srcidx[p] = s4.w;
}

// ---------------- GEMM1: [h1 | as1 | ad1] = x @ [W1 | W1@P] -------------------
// M-tile 64, cp.async tile loads, fp16 pre-split A, W fp16 smem
#define LDA 136
#define LDW1 152
#define ST1 148
__global__ __launch_bounds__(256)
void k_gemm1_mma() {
    extern __shared__ char raw[];
    __half* sAh = (__half*)raw;
    __half* sAl = sAh + 64 * LDA;
    __half* sW  = (__half*)(raw + 4 * 64 * LDA);
    float* stage = (float*)raw;
    int tid = threadIdx.x;
    int row0 = blockIdx.x * 64;

    // A via cp.async: 64 rows x 16 uint4 per array
#pragma unroll
    for (int ii = 0; ii < 4; ii++) {
        int i = tid + ii * 256;
        int r = i >> 4, c = i & 15;
        if (row0 + r < NN) {
            cp16(sAh + r * LDA + 8 * c, (const uint4*)g_xh + (size_t)(row0 + r) * 16 + c);
            cp16(sAl + r * LDA + 8 * c, (const uint4*)g_xl + (size_t)(row0 + r) * 16 + c);
        } else {
            *(uint4*)(sAh + r * LDA + 8 * c) = make_uint4(0, 0, 0, 0);
            *(uint4*)(sAl + r * LDA + 8 * c) = make_uint4(0, 0, 0, 0);
        }
    }
    // W via cp.async: 128 rows x 18 uint4
    for (int i = tid; i < 2304; i += 256) {
        int k = i / 18, j = i % 18;
        cp16(sW + k * LDW1 + 8 * j, (const uint4*)g_w1 + i);
    }
    cp_commit_wait();
    __syncthreads();

    int w = tid >> 5, wr = w >> 1, wc = w & 1;
    const int nf = wc ? 4 : 5;
    const int col0 = wc * 80;

    wmma::fragment<wmma::accumulator, 16, 16, 16, float> c[5];
#pragma unroll
    for (int j = 0; j < 5; j++) wmma::fill_fragment(c[j], 0.f);

    for (int kk = 0; kk < 128; kk += 16) {
        wmma::fragment<wmma::matrix_a, 16, 16, 16, __half, wmma::row_major> ah, al;
        wmma::load_matrix_sync(ah, sAh + (wr * 16) * LDA + kk, LDA);
        wmma::load_matrix_sync(al, sAl + (wr * 16) * LDA + kk, LDA);
#pragma unroll
        for (int j = 0; j < 5; j++) {
            if (j >= nf) break;
            wmma::fragment<wmma::matrix_b, 16, 16, 16, __half, wmma::row_major> bh;
            wmma::load_matrix_sync(bh, sW + kk * LDW1 + col0 + j * 16, LDW1);
            wmma::mma_sync(c[j], ah, bh, c[j]);
            wmma::mma_sync(c[j], al, bh, c[j]);
        }
    }
    __syncthreads();
#pragma unroll
    for (int j = 0; j < 5; j++) {
        if (j >= nf) break;
        wmma::store_matrix_sync(stage + (wr * 16) * ST1 + col0 + j * 16,
                                c[j], ST1, wmma::mem_row_major);
    }
    __syncthreads();

    // h1 -> fp16
    {
        int r = tid >> 2, q = tid & 3;
        int row = row0 + r;
        if (row < NN) {
            const float* sp = stage + r * ST1 + 32 * q;
            uint4* dp = (uint4*)(g_h1h + (size_t)row * 128 + 32 * q);
#pragma unroll
            for (int u = 0; u < 4; u++) {
                float4 a = *(const float4*)(sp + 8 * u);
                float4 b = *(const float4*)(sp + 8 * u + 4);
                __half2 h0 = __floats2half2_rn(a.x, a.y);
                __half2 h1 = __floats2half2_rn(a.z, a.w);
                __half2 h2 = __floats2half2_rn(b.x, b.y);
                __half2 h3 = __floats2half2_rn(b.z, b.w);
                uint4 uu;
                uu.x = *(uint32_t*)&h0; uu.y = *(uint32_t*)&h1;
                uu.z = *(uint32_t*)&h2; uu.w = *(uint32_t*)&h3;
                dp[u] = uu;
            }
        }
    }
    // alphas + global per-head max of as
    if (tid < 64) {
        int row = row0 + tid;
        const float* sp = stage + tid * ST1 + 128;
        float ps[4];
#pragma unroll
        for (int h = 0; h < 4; h++) {
            float a_ = sp[2 * h], d_ = sp[2 * h + 1];
            if (row < NN) {
                g_as1[row * 4 + h] = a_;
                g_ad1[row * 4 + h] = d_;
                ps[h] = a_;
            } else ps[h] = -3.4e38f;
        }
#pragma unroll
        for (int h = 0; h < 4; h++) {
#pragma unroll
            for (int o = 16; o >= 1; o >>= 1)
                ps[h] = fmaxf(ps[h], __shfl_xor_sync(0xffffffffu, ps[h], o));
        }
        if ((tid & 31) == 0) {
#pragma unroll
            for (int h = 0; h < 4; h++) atomicMaxF(&g_mx1[h], ps[h]);
        }
    }
}

// ---------------- GEMM2: [h2 | as2 | ad2] = relu(out1) @ [W2 | W2@P2] ---------
#define LDW2 88
#define ST2 84
__global__ __launch_bounds__(256)
void k_gemm2_mma() {
    extern __shared__ char raw[];
    __half* sAh = (__half*)raw;
    __half* sAl = sAh + 64 * LDA;
    __half* sW  = (__half*)(raw + 4 * 64 * LDA);
    float* stage = (float*)raw;
    int tid = threadIdx.x;
    int row0 = blockIdx.x * 64;

    // W via cp.async: 128 rows x 10 uint4
    for (int i = tid; i < 1280; i += 256) {
        int k = i / 10, j = i % 10;
        cp16(sW + k * LDW2 + 8 * j, (const uint4*)g_w2 + i);
    }
    // A: fp32 relu + split (L2-resident source)
    for (int i = tid; i < 2048; i += 256) {
        int r = i >> 5, c4 = i & 31;
        float4 v = make_float4(0.f, 0.f, 0.f, 0.f);
        if (row0 + r < NN) v = ((const float4*)g_out1)[(size_t)(row0 + r) * 32 + c4];
        int base = r * LDA + c4 * 4;
        float vv[4] = {fmaxf(v.x, 0.f), fmaxf(v.y, 0.f), fmaxf(v.z, 0.f), fmaxf(v.w, 0.f)};
#pragma unroll
        for (int j = 0; j < 4; j++) {
            __half h = __float2half_rn(vv[j]);
            sAh[base + j] = h;
            sAl[base + j] = __float2half_rn(vv[j] - __half2float(h));
        }
    }
    cp_commit_wait();
    __syncthreads();

    int w = tid >> 5, wr = w >> 1, wc = w & 1;
    const int nf = wc ? 2 : 3;
    const int col0 = wc * 48;

    wmma::fragment<wmma::accumulator, 16, 16, 16, float> c[3];
#pragma unroll
    for (int j = 0; j < 3; j++) wmma::fill_fragment(c[j], 0.f);

    for (int kk = 0; kk < 128; kk += 16) {
        wmma::fragment<wmma::matrix_a, 16, 16, 16, __half, wmma::row_major> ah, al;
        wmma::load_matrix_sync(ah, sAh + (wr * 16) * LDA + kk, LDA);
        wmma::load_matrix_sync(al, sAl + (wr * 16) * LDA + kk, LDA);
#pragma unroll
        for (int j = 0; j < 3; j++) {
            if (j >= nf) break;
            wmma::fragment<wmma::matrix_b, 16, 16, 16, __half, wmma::row_major> bh;
            wmma::load_matrix_sync(bh, sW + kk * LDW2 + col0 + j * 16, LDW2);
            wmma::mma_sync(c[j], ah, bh, c[j]);
            wmma::mma_sync(c[j], al, bh, c[j]);
        }
    }
    __syncthreads();
#pragma unroll
    for (int j = 0; j < 3; j++) {
        if (j >= nf) break;
        wmma::store_matrix_sync(stage + (wr * 16) * ST2 + col0 + j * 16,
                                c[j], ST2, wmma::mem_row_major);
    }
    __syncthreads();

    {
        int r = tid >> 2, q = tid & 3;
        int row = row0 + r;
        if (row < NN) {
            const float* sp = stage + r * ST2 + 16 * q;
            uint4* dp = (uint4*)(g_h2h + (size_t)row * 64 + 16 * q);
#pragma unroll
            for (int u = 0; u < 2; u++) {
                float4 a = *(const float4*)(sp + 8 * u);
                float4 b = *(const float4*)(sp + 8 * u + 4);
                __half2 h0 = __floats2half2_rn(a.x, a.y);
                __half2 h1 = __floats2half2_rn(a.z, a.w);
                __half2 h2 = __floats2half2_rn(b.x, b.y);
                __half2 h3 = __floats2half2_rn(b.z, b.w);
                uint4 uu;
                uu.x = *(uint32_t*)&h0; uu.y = *(uint32_t*)&h1;
                uu.z = *(uint32_t*)&h2; uu.w = *(uint32_t*)&h3;
                dp[u] = uu;
            }
        }
    }
    if (tid < 64) {
        int row = row0 + tid;
        float ps;
        if (row < NN) {
            ps = stage[tid * ST2 + 64];
            g_as2[row] = ps;
            g_ad2[row] = stage[tid * ST2 + 65];
        } else ps = -3.4e38f;
#pragma unroll
        for (int o = 16; o >= 1; o >>= 1)
            ps = fmaxf(ps, __shfl_xor_sync(0xffffffffu, ps, o));
        if ((tid & 31) == 0) atomicMaxF(&g_mx2, ps);
    }
}

// ---------------- gather1: 2 edges/warp, 16 lanes x 8 fp16 cols ---------------
__global__ __launch_bounds__(256)
void k_gather1(const float* __restrict__ b1) {
    int n = blockIdx.x * 8 + (threadIdx.x >> 5);
    if (n >= NN) return;
    int lane = threadIdx.x & 31;
    int g = lane >> 4, li = lane & 15;
    int head = li >> 2;
    float adh = g_ad1[4 * n + head];
    int beg = g_off[n], end = g_off[n + 1];

    float mh = lrelu(g_mx1[head] + adh);

    float acc[8];
#pragma unroll
    for (int q = 0; q < 8; q++) acc[q] = 0.f;
    float den = 0.f;

    int j0 = beg + g;
    int s0 = 0; float a0 = 0.f; uint4 u0 = make_uint4(0, 0, 0, 0);
    if (j0 < end) {
        s0 = g_srcidx[j0];
        a0 = g_as1[4 * s0 + head];
        u0 = *(const uint4*)(g_h1h + (size_t)s0 * 128 + 8 * li);
    }
    for (int j = j0; j < end; j += 2) {
        int s1 = 0; float a1 = 0.f; uint4 u1 = make_uint4(0, 0, 0, 0);
        if (j + 2 < end) {
            s1 = g_srcidx[j + 2];
            a1 = g_as1[4 * s1 + head];
            u1 = *(const uint4*)(g_h1h + (size_t)s1 * 128 + 8 * li);
        }
        float w = __expf(lrelu(a0 + adh) - mh);
        den += w;
        const __half2* hp = (const __half2*)&u0;
#pragma unroll
        for (int q = 0; q < 4; q++) {
            float2 f = __half22float2(hp[q]);
            acc[2 * q] += w * f.x;
            acc[2 * q + 1] += w * f.y;
        }
        s0 = s1; a0 = a1; u0 = u1;
    }
    den += __shfl_xor_sync(0xffffffffu, den, 16);
#pragma unroll
    for (int q = 0; q < 8; q++) acc[q] += __shfl_xor_sync(0xffffffffu, acc[q], 16);

    if (g == 0) {
        float inv = 1.f / (den + 1e-16f);
        float4 b0 = *(const float4*)(b1 + 8 * li);
        float4 b4 = *(const float4*)(b1 + 8 * li + 4);
        float* op = g_out1 + (size_t)n * 128 + 8 * li;
        *(float4*)op = make_float4(acc[0] * inv + b0.x, acc[1] * inv + b0.y,
                                   acc[2] * inv + b0.z, acc[3] * inv + b0.w);
        *(float4*)(op + 4) = make_float4(acc[4] * inv + b4.x, acc[5] * inv + b4.y,
                                         acc[6] * inv + b4.z, acc[7] * inv + b4.w);
    }
}

// ---------------- gather2: 4 edges/warp, 8 lanes x 8 fp16 cols ----------------
__global__ __launch_bounds__(256)
void k_gather2(const float* __restrict__ b2, float* __restrict__ out) {
    int n = blockIdx.x * 8 + (threadIdx.x >> 5);
    if (n >= NN) return;
    int lane = threadIdx.x & 31;
    int g = lane >> 3, li = lane & 7;
    float adh = g_ad2[n];
    int beg = g_off[n], end = g_off[n + 1];

    float mh = lrelu(g_mx2 + adh);

    float acc[8];
#pragma unroll
    for (int q = 0; q < 8; q++) acc[q] = 0.f;
    float den = 0.f;

    int j0 = beg + g;
    int s0 = 0; float a0 = 0.f; uint4 u0 = make_uint4(0, 0, 0, 0);
    if (j0 < end) {
        s0 = g_srcidx[j0];
        a0 = g_as2[s0];
        u0 = *(const uint4*)(g_h2h + (size_t)s0 * 64 + 8 * li);
    }
    for (int j = j0; j < end; j += 4) {
        int s1 = 0; float a1 = 0.f; uint4 u1 = make_uint4(0, 0, 0, 0);
        if (j + 4 < end) {
            s1 = g_srcidx[j + 4];
            a1 = g_as2[s1];
            u1 = *(const uint4*)(g_h2h + (size_t)s1 * 64 + 8 * li);
        }
        float w = __expf(lrelu(a0 + adh) - mh);
        den += w;
        const __half2* hp = (const __half2*)&u0;
#pragma unroll
        for (int q = 0; q < 4; q++) {
            float2 f = __half22float2(hp[q]);
            acc[2 * q] += w * f.x;
            acc[2 * q + 1] += w * f.y;
        }
        s0 = s1; a0 = a1; u0 = u1;
    }
    den += __shfl_xor_sync(0xffffffffu, den, 8);
    den += __shfl_xor_sync(0xffffffffu, den, 16);
#pragma unroll
    for (int q = 0; q < 8; q++) {
        acc[q] += __shfl_xor_sync(0xffffffffu, acc[q], 8);
        acc[q] += __shfl_xor_sync(0xffffffffu, acc[q], 16);
    }

    if (g == 0) {
        float inv = 1.f / (den + 1e-16f);
        float4 b0 = *(const float4*)(b2 + 8 * li);
        float4 b4 = *(const float4*)(b2 + 8 * li + 4);
        float* op = out + (size_t)n * 64 + 8 * li;
        *(float4*)op = make_float4(acc[0] * inv + b0.x, acc[1] * inv + b0.y,
                                   acc[2] * inv + b0.z, acc[3] * inv + b0.w);
        *(float4*)(op + 4) = make_float4(acc[4] * inv + b4.x, acc[5] * inv + b4.y,
                                         acc[6] * inv + b4.z, acc[7] * inv + b4.w);
    }
}

// ---------------- launch ------------------------------------------------------
extern "C" void kernel_launch(void* const* d_in, const int* in_sizes, int n_in,
                              void* d_out, int out_size) {
    const float* x   = (const float*)d_in[0];
    const int*   ei  = (const int*)d_in[1];
    const float* W1  = (const float*)d_in[2];
    const float* as1 = (const float*)d_in[3];
    const float* ad1 = (const float*)d_in[4];
    const float* b1  = (const float*)d_in[5];
    const float* W2  = (const float*)d_in[6];
    const float* as2 = (const float*)d_in[7];
    const float* ad2 = (const float*)d_in[8];
    const float* b2  = (const float*)d_in[9];
    float* out = (float*)d_out;

    const int smem1 = 4 * 64 * LDA + 2 * 128 * LDW1;   // 73728
    const int smem2 = 4 * 64 * LDA + 2 * 128 * LDW2;   // 57344
    static cudaStream_t s_side = nullptr;
    static cudaEvent_t ev_root = nullptr, ev_side = nullptr;
    if (!s_side) {
        cudaFuncSetAttribute(k_gemm1_mma, cudaFuncAttributeMaxDynamicSharedMemorySize, smem1);
        cudaFuncSetAttribute(k_gemm2_mma, cudaFuncAttributeMaxDynamicSharedMemorySize, smem2);
        cudaStreamCreateWithFlags(&s_side, cudaStreamNonBlocking);
        cudaEventCreateWithFlags(&ev_root, cudaEventDisableTiming);
        cudaEventCreateWithFlags(&ev_side, cudaEventDisableTiming);
    }

    // root: prep (hist + convw + reset + X split)
    k_prep<<<XS0 + XS_BLKS, 256>>>(ei, x, W1, W2, as1, ad1, as2, ad2);

    // fork: CSR build (scan+fill) on side stream, GEMM1 on main stream
    cudaEventRecord(ev_root, 0);
    cudaStreamWaitEvent(s_side, ev_root, 0);
    k_scan<<<NBLK, 256, 0, s_side>>>();
    k_fill<<<(NE / 4 + 255) / 256, 256, 0, s_side>>>(ei);
    cudaEventRecord(ev_side, s_side);

    k_gemm1_mma<<<NP / 64, 256, smem1>>>();

    // join: gather1 needs both gemm1 (main) and fill (side)
    cudaStreamWaitEvent(0, ev_side, 0);
    k_gather1<<<(NN + 7) / 8, 256>>>(b1);

    // layer 2 (serial chain)
    k_gemm2_mma<<<NP / 64, 256, smem2>>>();
    k_gather2<<<(NN + 7) / 8, 256>>>(b2, out);
}

// round 13
// speedup vs baseline: 2.5875x; 1.0321x over previous
#include <cuda_runtime.h>
#include <cuda_bf16.h>
#include <cuda_fp16.h>
#include <mma.h>
#include <cstdint>

using namespace nvcuda;

#define NN 50000
#define NP 50048          // 782 * 64
#define NE 800000
#define ET 850000         // NE + NN self loops
#define NS 0.2f
#define NBLK 196          // ceil(NN/256)

// ---------------- scratch (device globals) -----------------------------------
__device__ __half g_h1h[NN * 128];
__device__ __half g_o1h[NN * 128];   // relu(out1) split hi
__device__ __half g_o1l[NN * 128];   // relu(out1) split lo
__device__ float  g_as1[NN * 4];
__device__ float  g_ad1[NN * 4];
__device__ __half g_h2h[NN * 64];
__device__ float  g_as2[NN];
__device__ float  g_ad2[NN];
__device__ float  g_mx1[4];          // global per-head max of as1
__device__ float  g_mx2;             // global max of as2
__device__ int g_deg[NN];            // invariant: zero before/after every call
__device__ int g_off[NN + 1];
__device__ int g_cur[NN];
__device__ int g_srcidx[ET];
__device__ unsigned int g_blkst[NBLK];
// fp16 weights with fused alpha columns
__device__ __half g_w1[128 * 144];
__device__ __half g_w2[128 * 80];

__device__ __forceinline__ float lrelu(float v) { return v >= 0.f ? v : NS * v; }

__device__ __forceinline__ void atomicMaxF(float* addr, float v) {
    if (v >= 0.f) atomicMax((int*)addr, __float_as_int(v));
    else          atomicMin((unsigned int*)addr, __float_as_uint(v));
}

__device__ __forceinline__ uint32_t smem_u32(const void* p) {
    uint32_t a;
    asm("{ .reg .u64 t; cvta.to.shared.u64 t, %1; cvt.u32.u64 %0, t; }" : "=r"(a) : "l"(p));
    return a;
}
__device__ __forceinline__ void cp16(void* smem, const void* gmem) {
    asm volatile("cp.async.cg.shared.global [%0], [%1], 16;"
                 :: "r"(smem_u32(smem)), "l"(gmem) : "memory");
}
__device__ __forceinline__ void cp_commit_wait() {
    asm volatile("cp.async.commit_group;" ::: "memory");
    asm volatile("cp.async.wait_group 0;" ::: "memory");
}

// ---------------- prep: hist + convw + reset ----------------------------------
#define HIST_BLKS 782
#define CONV_BLKS 112
__global__ void k_prep(const int* __restrict__ ei,
                       const float* __restrict__ W1, const float* __restrict__ W2,
                       const float* __restrict__ as1, const float* __restrict__ ad1,
                       const float* __restrict__ as2, const float* __restrict__ ad2) {
    int b = blockIdx.x, t = threadIdx.x;
    if (b < HIST_BLKS) {
        int i = b * 256 + t;
        if (i >= NE / 4) return;
        int4 d4 = ((const int4*)(ei + NE))[i];
        atomicAdd(&g_deg[d4.x], 1);
        atomicAdd(&g_deg[d4.y], 1);
        atomicAdd(&g_deg[d4.z], 1);
        atomicAdd(&g_deg[d4.w], 1);
        return;
    }
    if (b == HIST_BLKS + CONV_BLKS) {          // reset block
        if (t < NBLK) g_blkst[t] = 0u;
        if (t == 0) {
            g_off[NN] = ET;
            g_mx1[0] = -3.4e38f; g_mx1[1] = -3.4e38f;
            g_mx1[2] = -3.4e38f; g_mx1[3] = -3.4e38f;
            g_mx2 = -3.4e38f;
        }
        return;
    }
    int s = (b - HIST_BLKS) * 256 + t;         // weight conversion
    float val; int dsth, dstl;
    if (s < 16384) {
        int k = s >> 7, n = s & 127;
        val = W1[k * 128 + n];
        dsth = k * 144 + n; dstl = 1;
    } else if (s < 17408) {
        int i = s - 16384;
        int k = i >> 3, c = i & 7, h = c >> 1;
        const float* a = (c & 1) ? ad1 : as1;
        float sum = 0.f;
#pragma unroll
        for (int f = 0; f < 32; f++) sum += W1[k * 128 + h * 32 + f] * a[h * 32 + f];
        val = sum; dsth = k * 144 + 128 + c; dstl = 1;
    } else if (s < 18432) {
        int i = s - 17408;
        int k = i >> 3, c = i & 7;
        val = 0.f; dsth = k * 144 + 136 + c; dstl = 1;
    } else if (s < 26624) {
        int i = s - 18432;
        int k = i >> 6, n = i & 63;
        val = W2[k * 64 + n];
        dsth = k * 80 + n; dstl = 2;
    } else if (s < 26880) {
        int i = s - 26624;
        int k = i >> 1, c = i & 1;
        const float* a = c ? ad2 : as2;
        float sum = 0.f;
#pragma unroll
        for (int f = 0; f < 64; f++) sum += W2[k * 64 + f] * a[f];
        val = sum; dsth = k * 80 + 64 + c; dstl = 2;
    } else if (s < 28672) {
        int i = s - 26880;
        int k = i / 14, c = i % 14;
        val = 0.f; dsth = k * 80 + 66 + c; dstl = 2;
    } else return;
    __half hv = __float2half_rn(val);
    if (dstl == 1) g_w1[dsth] = hv;
    else           g_w2[dsth] = hv;
}

// ---------------- single-pass scan with decoupled lookback --------------------
__global__ void k_scan() {
    __shared__ int sh[256];
    __shared__ int s_excl;
    int t = threadIdx.x, b = blockIdx.x;
    int i = b * 256 + t;
    int v = (i < NN) ? g_deg[i] + 1 : 0;   // +1 self loop
    sh[t] = v;
    __syncthreads();
#pragma unroll
    for (int o = 1; o < 256; o <<= 1) {
        int tv = (t >= o) ? sh[t - o] : 0;
        __syncthreads();
        sh[t] += tv;
        __syncthreads();
    }
    int incl = sh[t];
    int total = sh[255];

    if (t == 0) {
        if (b == 0) {
            atomicExch(&g_blkst[0], ((unsigned)total << 2) | 2u);
            s_excl = 0;
        } else {
            atomicExch(&g_blkst[b], ((unsigned)total << 2) | 1u);
            int run = 0;
            for (int p = b - 1; p >= 0; p--) {
                unsigned st;
                do { st = atomicAdd(&g_blkst[p], 0u); } while ((st & 3u) == 0u);
                run += (int)(st >> 2);
                if ((st & 3u) == 2u) break;
            }
            s_excl = run;
            atomicExch(&g_blkst[b], ((unsigned)(run + total) << 2) | 2u);
        }
    }
    __syncthreads();
    if (i < NN) {
        int off = s_excl + incl - v;
        g_off[i] = off;
        g_srcidx[off] = i;      // self loop seeded first
        g_cur[i] = off + 1;
        g_deg[i] = 0;           // restore invariant
    }
}

__global__ void k_fill(const int* __restrict__ ei) {
    int i = blockIdx.x * blockDim.x + threadIdx.x;
    if (i >= NE / 4) return;
    int4 s4 = ((const int4*)ei)[i];
    int4 d4 = ((const int4*)(ei + NE))[i];
    int p;
    p = atomicAdd(&g_cur[d4.x], 1); g_srcidx[p] = s4.x;
    p = atomicAdd(&g_cur[d4.y], 1); g_srcidx[p] = s4.y;
    p = atomicAdd(&g_cur[d4.z], 1); g_srcidx[p] = s4.z;
    p = atomicAdd(&g_cur[d4.w], 1); g_srcidx[p] = s4.w;
}

// ---------------- GEMM1: [h1 | as1 | ad1] = x @ [W1 | W1@P] -------------------
// M-tile 64; fp32 X staged via cp.async into sW area, split in-smem, then W over it
#define LDA 136
#define LDW1 152
#define ST1 148
__global__ __launch_bounds__(256)
void k_gemm1_mma(const float* __restrict__ X) {
    extern __shared__ char raw[];
    __half* sAh = (__half*)raw;
    __half* sAl = sAh + 64 * LDA;
    __half* sW  = (__half*)(raw + 4 * 64 * LDA);
    float*  sX  = (float*)sW;                      // staging aliases sW
    float* stage = (float*)raw;
    int tid = threadIdx.x;
    int row0 = blockIdx.x * 64;

    // stage fp32 X tile (64 x 128) via cp.async
#pragma unroll
    for (int ii = 0; ii < 8; ii++) {
        int i = tid + ii * 256;
        int r = i >> 5, c4 = i & 31;
        if (row0 + r < NN)
            cp16(sX + r * 128 + 4 * c4, (const float4*)X + (size_t)(row0 + r) * 32 + c4);
        else
            *(float4*)(sX + r * 128 + 4 * c4) = make_float4(0.f, 0.f, 0.f, 0.f);
    }
    cp_commit_wait();
    __syncthreads();
    // convert to fp16 hi/lo
#pragma unroll
    for (int ii = 0; ii < 8; ii++) {
        int i = tid + ii * 256;
        int r = i >> 5, c4 = i & 31;
        float4 v = *(const float4*)(sX + r * 128 + 4 * c4);
        __half2 h0 = __floats2half2_rn(v.x, v.y);
        __half2 h1 = __floats2half2_rn(v.z, v.w);
        float2 f0 = __half22float2(h0), f1 = __half22float2(h1);
        __half2 l0 = __floats2half2_rn(v.x - f0.x, v.y - f0.y);
        __half2 l1 = __floats2half2_rn(v.z - f1.x, v.w - f1.y);
        uint2 uh, ul;
        uh.x = *(uint32_t*)&h0; uh.y = *(uint32_t*)&h1;
        ul.x = *(uint32_t*)&l0; ul.y = *(uint32_t*)&l1;
        *(uint2*)(sAh + r * LDA + 4 * c4) = uh;
        *(uint2*)(sAl + r * LDA + 4 * c4) = ul;
    }
    __syncthreads();
    // W over the staging area
    for (int i = tid; i < 2304; i += 256) {
        int k = i / 18, j = i % 18;
        cp16(sW + k * LDW1 + 8 * j, (const uint4*)g_w1 + i);
    }
    cp_commit_wait();
    __syncthreads();

    int w = tid >> 5, wr = w >> 1, wc = w & 1;
    const int nf = wc ? 4 : 5;
    const int col0 = wc * 80;

    wmma::fragment<wmma::accumulator, 16, 16, 16, float> c[5];
#pragma unroll
    for (int j = 0; j < 5; j++) wmma::fill_fragment(c[j], 0.f);

    for (int kk = 0; kk < 128; kk += 16) {
        wmma::fragment<wmma::matrix_a, 16, 16, 16, __half, wmma::row_major> ah, al;
        wmma::load_matrix_sync(ah, sAh + (wr * 16) * LDA + kk, LDA);
        wmma::load_matrix_sync(al, sAl + (wr * 16) * LDA + kk, LDA);
#pragma unroll
        for (int j = 0; j < 5; j++) {
            if (j >= nf) break;
            wmma::fragment<wmma::matrix_b, 16, 16, 16, __half, wmma::row_major> bh;
            wmma::load_matrix_sync(bh, sW + kk * LDW1 + col0 + j * 16, LDW1);
            wmma::mma_sync(c[j], ah, bh, c[j]);
            wmma::mma_sync(c[j], al, bh, c[j]);
        }
    }
    __syncthreads();
#pragma unroll
    for (int j = 0; j < 5; j++) {
        if (j >= nf) break;
        wmma::store_matrix_sync(stage + (wr * 16) * ST1 + col0 + j * 16,
                                c[j], ST1, wmma::mem_row_major);
    }
    __syncthreads();

    // h1 -> fp16
    {
        int r = tid >> 2, q = tid & 3;
        int row = row0 + r;
        if (row < NN) {
            const float* sp = stage + r * ST1 + 32 * q;
            uint4* dp = (uint4*)(g_h1h + (size_t)row * 128 + 32 * q);
#pragma unroll
            for (int u = 0; u < 4; u++) {
                float4 a = *(const float4*)(sp + 8 * u);
                float4 b = *(const float4*)(sp + 8 * u + 4);
                __half2 h0 = __floats2half2_rn(a.x, a.y);
                __half2 h1 = __floats2half2_rn(a.z, a.w);
                __half2 h2 = __floats2half2_rn(b.x, b.y);
                __half2 h3 = __floats2half2_rn(b.z, b.w);
                uint4 uu;
                uu.x = *(uint32_t*)&h0; uu.y = *(uint32_t*)&h1;
                uu.z = *(uint32_t*)&h2; uu.w = *(uint32_t*)&h3;
                dp[u] = uu;
            }
        }
    }
    // alphas + global per-head max of as
    if (tid < 64) {
        int row = row0 + tid;
        const float* sp = stage + tid * ST1 + 128;
        float ps[4];
#pragma unroll
        for (int h = 0; h < 4; h++) {
            float a_ = sp[2 * h], d_ = sp[2 * h + 1];
            if (row < NN) {
                g_as1[row * 4 + h] = a_;
                g_ad1[row * 4 + h] = d_;
                ps[h] = a_;
            } else ps[h] = -3.4e38f;
        }
#pragma unroll
        for (int h = 0; h < 4; h++) {
#pragma unroll
            for (int o = 16; o >= 1; o >>= 1)
                ps[h] = fmaxf(ps[h], __shfl_xor_sync(0xffffffffu, ps[h], o));
        }
        if ((tid & 31) == 0) {
#pragma unroll
            for (int h = 0; h < 4; h++) atomicMaxF(&g_mx1[h], ps[h]);
        }
    }
}

// ---------------- GEMM2: [h2 | as2 | ad2] = o1 @ [W2 | W2@P2] -----------------
// A is pre-split fp16 hi/lo (relu already applied by gather1) -> pure cp.async
#define LDW2 88
#define ST2 84
__global__ __launch_bounds__(256)
void k_gemm2_mma() {
    extern __shared__ char raw[];
    __half* sAh = (__half*)raw;
    __half* sAl = sAh + 64 * LDA;
    __half* sW  = (__half*)(raw + 4 * 64 * LDA);
    float* stage = (float*)raw;
    int tid = threadIdx.x;
    int row0 = blockIdx.x * 64;

    // A via cp.async: 64 rows x 16 uint4 per array
#pragma unroll
    for (int ii = 0; ii < 4; ii++) {
        int i = tid + ii * 256;
        int r = i >> 4, c = i & 15;
        if (row0 + r < NN) {
            cp16(sAh + r * LDA + 8 * c, (const uint4*)g_o1h + (size_t)(row0 + r) * 16 + c);
            cp16(sAl + r * LDA + 8 * c, (const uint4*)g_o1l + (size_t)(row0 + r) * 16 + c);
        } else {
            *(uint4*)(sAh + r * LDA + 8 * c) = make_uint4(0, 0, 0, 0);
            *(uint4*)(sAl + r * LDA + 8 * c) = make_uint4(0, 0, 0, 0);
        }
    }
    // W via cp.async
    for (int i = tid; i < 1280; i += 256) {
        int k = i / 10, j = i % 10;
        cp16(sW + k * LDW2 + 8 * j, (const uint4*)g_w2 + i);
    }
    cp_commit_wait();
    __syncthreads();

    int w = tid >> 5, wr = w >> 1, wc = w & 1;
    const int nf = wc ? 2 : 3;
    const int col0 = wc * 48;

    wmma::fragment<wmma::accumulator, 16, 16, 16, float> c[3];
#pragma unroll
    for (int j = 0; j < 3; j++) wmma::fill_fragment(c[j], 0.f);

    for (int kk = 0; kk < 128; kk += 16) {
        wmma::fragment<wmma::matrix_a, 16, 16, 16, __half, wmma::row_major> ah, al;
        wmma::load_matrix_sync(ah, sAh + (wr * 16) * LDA + kk, LDA);
        wmma::load_matrix_sync(al, sAl + (wr * 16) * LDA + kk, LDA);
#pragma unroll
        for (int j = 0; j < 3; j++) {
            if (j >= nf) break;
            wmma::fragment<wmma::matrix_b, 16, 16, 16, __half, wmma::row_major> bh;
            wmma::load_matrix_sync(bh, sW + kk * LDW2 + col0 + j * 16, LDW2);
            wmma::mma_sync(c[j], ah, bh, c[j]);
            wmma::mma_sync(c[j], al, bh, c[j]);
        }
    }
    __syncthreads();
#pragma unroll
    for (int j = 0; j < 3; j++) {
        if (j >= nf) break;
        wmma::store_matrix_sync(stage + (wr * 16) * ST2 + col0 + j * 16,
                                c[j], ST2, wmma::mem_row_major);
    }
    __syncthreads();

    {
        int r = tid >> 2, q = tid & 3;
        int row = row0 + r;
        if (row < NN) {
            const float* sp = stage + r * ST2 + 16 * q;
            uint4* dp = (uint4*)(g_h2h + (size_t)row * 64 + 16 * q);
#pragma unroll
            for (int u = 0; u < 2; u++) {
                float4 a = *(const float4*)(sp + 8 * u);
                float4 b = *(const float4*)(sp + 8 * u + 4);
                __half2 h0 = __floats2half2_rn(a.x, a.y);
                __half2 h1 = __floats2half2_rn(a.z, a.w);
                __half2 h2 = __floats2half2_rn(b.x, b.y);
                __half2 h3 = __floats2half2_rn(b.z, b.w);
                uint4 uu;
                uu.x = *(uint32_t*)&h0; uu.y = *(uint32_t*)&h1;
                uu.z = *(uint32_t*)&h2; uu.w = *(uint32_t*)&h3;
                dp[u] = uu;
            }
        }
    }
    if (tid < 64) {
        int row = row0 + tid;
        float ps;
        if (row < NN) {
            ps = stage[tid * ST2 + 64];
            g_as2[row] = ps;
            g_ad2[row] = stage[tid * ST2 + 65];
        } else ps = -3.4e38f;
#pragma unroll
        for (int o = 16; o >= 1; o >>= 1)
            ps = fmaxf(ps, __shfl_xor_sync(0xffffffffu, ps, o));
        if ((tid & 31) == 0) atomicMaxF(&g_mx2, ps);
    }
}

// ---------------- gather1: 2 edges/warp, depth-2 pipeline ---------------------
__global__ __launch_bounds__(256)
void k_gather1(const float* __restrict__ b1) {
    int n = blockIdx.x * 8 + (threadIdx.x >> 5);
    if (n >= NN) return;
    int lane = threadIdx.x & 31;
    int g = lane >> 4, li = lane & 15;
    int head = li >> 2;
    float adh = g_ad1[4 * n + head];
    int beg = g_off[n], end = g_off[n + 1];

    float mh = lrelu(g_mx1[head] + adh);

    float acc[8];
#pragma unroll
    for (int q = 0; q < 8; q++) acc[q] = 0.f;
    float den = 0.f;

    int j0 = beg + g;
    float aA = 0.f, aB = 0.f;
    uint4 uA = make_uint4(0, 0, 0, 0), uB = make_uint4(0, 0, 0, 0);
    if (j0 < end) {
        int s = g_srcidx[j0];
        aA = g_as1[4 * s + head];
        uA = *(const uint4*)(g_h1h + (size_t)s * 128 + 8 * li);
    }
    if (j0 + 2 < end) {
        int s = g_srcidx[j0 + 2];
        aB = g_as1[4 * s + head];
        uB = *(const uint4*)(g_h1h + (size_t)s * 128 + 8 * li);
    }
    for (int j = j0; j < end; j += 2) {
        float aC = 0.f; uint4 uC = make_uint4(0, 0, 0, 0);
        if (j + 4 < end) {
            int s = g_srcidx[j + 4];
            aC = g_as1[4 * s + head];
            uC = *(const uint4*)(g_h1h + (size_t)s * 128 + 8 * li);
        }
        float w = __expf(lrelu(aA + adh) - mh);
        den += w;
        const __half2* hp = (const __half2*)&uA;
#pragma unroll
        for (int q = 0; q < 4; q++) {
            float2 f = __half22float2(hp[q]);
            acc[2 * q] += w * f.x;
            acc[2 * q + 1] += w * f.y;
        }
        aA = aB; uA = uB;
        aB = aC; uB = uC;
    }
    den += __shfl_xor_sync(0xffffffffu, den, 16);
#pragma unroll
    for (int q = 0; q < 8; q++) acc[q] += __shfl_xor_sync(0xffffffffu, acc[q], 16);

    if (g == 0) {
        float inv = 1.f / (den + 1e-16f);
        float4 b0 = *(const float4*)(b1 + 8 * li);
        float4 b4 = *(const float4*)(b1 + 8 * li + 4);
        float v[8];
        v[0] = fmaxf(acc[0] * inv + b0.x, 0.f); v[1] = fmaxf(acc[1] * inv + b0.y, 0.f);
        v[2] = fmaxf(acc[2] * inv + b0.z, 0.f); v[3] = fmaxf(acc[3] * inv + b0.w, 0.f);
        v[4] = fmaxf(acc[4] * inv + b4.x, 0.f); v[5] = fmaxf(acc[5] * inv + b4.y, 0.f);
        v[6] = fmaxf(acc[6] * inv + b4.z, 0.f); v[7] = fmaxf(acc[7] * inv + b4.w, 0.f);
        uint4 uh, ul;
        uint32_t* uhp = (uint32_t*)&uh;
        uint32_t* ulp = (uint32_t*)&ul;
#pragma unroll
        for (int q = 0; q < 4; q++) {
            __half2 h = __floats2half2_rn(v[2 * q], v[2 * q + 1]);
            float2 f = __half22float2(h);
            __half2 l = __floats2half2_rn(v[2 * q] - f.x, v[2 * q + 1] - f.y);
            uhp[q] = *(uint32_t*)&h;
            ulp[q] = *(uint32_t*)&l;
        }
        *(uint4*)(g_o1h + (size_t)n * 128 + 8 * li) = uh;
        *(uint4*)(g_o1l + (size_t)n * 128 + 8 * li) = ul;
    }
}

// ---------------- gather2: 4 edges/warp, depth-2 pipeline ---------------------
__global__ __launch_bounds__(256)
void k_gather2(const float* __restrict__ b2, float* __restrict__ out) {
    int n = blockIdx.x * 8 + (threadIdx.x >> 5);
    if (n >= NN) return;
    int lane = threadIdx.x & 31;
    int g = lane >> 3, li = lane & 7;
    float adh = g_ad2[n];
    int beg = g_off[n], end = g_off[n + 1];

    float mh = lrelu(g_mx2 + adh);

    float acc[8];
#pragma unroll
    for (int q = 0; q < 8; q++) acc[q] = 0.f;
    float den = 0.f;

    int j0 = beg + g;
    float aA = 0.f, aB = 0.f;
    uint4 uA = make_uint4(0, 0, 0, 0), uB = make_uint4(0, 0, 0, 0);
    if (j0 < end) {
        int s = g_srcidx[j0];
        aA = g_as2[s];
        uA = *(const uint4*)(g_h2h + (size_t)s * 64 + 8 * li);
    }
    if (j0 + 4 < end) {
        int s = g_srcidx[j0 + 4];
        aB = g_as2[s];
        uB = *(const uint4*)(g_h2h + (size_t)s * 64 + 8 * li);
    }
    for (int j = j0; j < end; j += 4) {
        float aC = 0.f; uint4 uC = make_uint4(0, 0, 0, 0);
        if (j + 8 < end) {
            int s = g_srcidx[j + 8];
            aC = g_as2[s];
            uC = *(const uint4*)(g_h2h + (size_t)s * 64 + 8 * li);
        }
        float w = __expf(lrelu(aA + adh) - mh);
        den += w;
        const __half2* hp = (const __half2*)&uA;
#pragma unroll
        for (int q = 0; q < 4; q++) {
            float2 f = __half22float2(hp[q]);
            acc[2 * q] += w * f.x;
            acc[2 * q + 1] += w * f.y;
        }
        aA = aB; uA = uB;
        aB = aC; uB = uC;
    }
    den += __shfl_xor_sync(0xffffffffu, den, 8);
    den += __shfl_xor_sync(0xffffffffu, den, 16);
#pragma unroll
    for (int q = 0; q < 8; q++) {
        acc[q] += __shfl_xor_sync(0xffffffffu, acc[q], 8);
        acc[q] += __shfl_xor_sync(0xffffffffu, acc[q], 16);
    }

    if (g == 0) {
        float inv = 1.f / (den + 1e-16f);
        float4 b0 = *(const float4*)(b2 + 8 * li);
        float4 b4 = *(const float4*)(b2 + 8 * li + 4);
        float* op = out + (size_t)n * 64 + 8 * li;
        *(float4*)op = make_float4(acc[0] * inv + b0.x, acc[1] * inv + b0.y,
                                   acc[2] * inv + b0.z, acc[3] * inv + b0.w);
        *(float4*)(op + 4) = make_float4(acc[4] * inv + b4.x, acc[5] * inv + b4.y,
                                         acc[6] * inv + b4.z, acc[7] * inv + b4.w);
    }
}

// ---------------- launch ------------------------------------------------------
extern "C" void kernel_launch(void* const* d_in, const int* in_sizes, int n_in,
                              void* d_out, int out_size) {
    const float* x   = (const float*)d_in[0];
    const int*   ei  = (const int*)d_in[1];
    const float* W1  = (const float*)d_in[2];
    const float* as1 = (const float*)d_in[3];
    const float* ad1 = (const float*)d_in[4];
    const float* b1  = (const float*)d_in[5];
    const float* W2  = (const float*)d_in[6];
    const float* as2 = (const float*)d_in[7];
    const float* ad2 = (const float*)d_in[8];
    const float* b2  = (const float*)d_in[9];
    float* out = (float*)d_out;

    const int smem1 = 4 * 64 * LDA + 2 * 128 * LDW1;   // 73728
    const int smem2 = 4 * 64 * LDA + 2 * 128 * LDW2;   // 57344
    static cudaStream_t s_side = nullptr;
    static cudaEvent_t ev_root = nullptr, ev_side = nullptr;
    if (!s_side) {
        cudaFuncSetAttribute(k_gemm1_mma, cudaFuncAttributeMaxDynamicSharedMemorySize, smem1);
        cudaFuncSetAttribute(k_gemm2_mma, cudaFuncAttributeMaxDynamicSharedMemorySize, smem2);
        cudaStreamCreateWithFlags(&s_side, cudaStreamNonBlocking);
        cudaEventCreateWithFlags(&ev_root, cudaEventDisableTiming);
        cudaEventCreateWithFlags(&ev_side, cudaEventDisableTiming);
    }

    // root: prep (hist + convw + reset)
    k_prep<<<HIST_BLKS + CONV_BLKS + 1, 256>>>(ei, W1, W2, as1, ad1, as2, ad2);

    // fork: CSR build (scan+fill) on side stream, GEMM1 on main stream
    cudaEventRecord(ev_root, 0);
    cudaStreamWaitEvent(s_side, ev_root, 0);
    k_scan<<<NBLK, 256, 0, s_side>>>();
    k_fill<<<(NE / 4 + 255) / 256, 256, 0, s_side>>>(ei);
    cudaEventRecord(ev_side, s_side);

    k_gemm1_mma<<<NP / 64, 256, smem1>>>(x);

    // join: gather1 needs both gemm1 (main) and fill (side)
    cudaStreamWaitEvent(0, ev_side, 0);
    k_gather1<<<(NN + 7) / 8, 256>>>(b1);

    // layer 2 (serial chain)
    k_gemm2_mma<<<NP / 64, 256, smem2>>>();
    k_gather2<<<(NN + 7) / 8, 256>>>(b2, out);
}

// round 14
// speedup vs baseline: 2.6993x; 1.0432x over previous
#include <cuda_runtime.h>
#include <cuda_bf16.h>
#include <cuda_fp16.h>
#include <mma.h>
#include <cstdint>

using namespace nvcuda;

#define NN 50000
#define NP 50048          // 782 * 64
#define NE 800000
#define ET 850000         // NE + NN self loops
#define NS 0.2f
#define NBLK 196          // ceil(NN/256)

// ---------------- scratch (device globals) -----------------------------------
__device__ __half g_h1h[NN * 128];
__device__ __half g_o1h[NN * 128];   // relu(out1) split hi
__device__ __half g_o1l[NN * 128];   // relu(out1) split lo
__device__ float  g_as1[NN * 4];
__device__ float  g_ad1[NN * 4];
__device__ __half g_h2h[NN * 64];
__device__ float  g_as2[NN];
__device__ float  g_ad2[NN];
__device__ float  g_mx1[4];          // global per-head max of as1
__device__ float  g_mx2;             // global max of as2
__device__ int g_deg[NN];            // invariant: zero before/after every call
__device__ int g_off[NN + 1];
__device__ int g_cur[NN];
__device__ int g_srcidx[ET];
__device__ unsigned int g_blkst[NBLK];
// fp16 weights with fused alpha columns
__device__ __half g_w1[128 * 144];
__device__ __half g_w2[128 * 80];

__device__ __forceinline__ float lrelu(float v) { return v >= 0.f ? v : NS * v; }

__device__ __forceinline__ void atomicMaxF(float* addr, float v) {
    if (v >= 0.f) atomicMax((int*)addr, __float_as_int(v));
    else          atomicMin((unsigned int*)addr, __float_as_uint(v));
}

__device__ __forceinline__ uint32_t smem_u32(const void* p) {
    uint32_t a;
    asm("{ .reg .u64 t; cvta.to.shared.u64 t, %1; cvt.u32.u64 %0, t; }" : "=r"(a) : "l"(p));
    return a;
}
__device__ __forceinline__ void cp16(void* smem, const void* gmem) {
    asm volatile("cp.async.cg.shared.global [%0], [%1], 16;"
                 :: "r"(smem_u32(smem)), "l"(gmem) : "memory");
}
__device__ __forceinline__ void cp_commit_wait() {
    asm volatile("cp.async.commit_group;" ::: "memory");
    asm volatile("cp.async.wait_group 0;" ::: "memory");
}

// ---------------- hist (side stream, no deps beyond ei) -----------------------
#define HIST_BLKS 782
__global__ void k_hist(const int* __restrict__ ei) {
    int i = blockIdx.x * blockDim.x + threadIdx.x;
    if (i >= NE / 4) return;
    int4 d4 = ((const int4*)(ei + NE))[i];
    atomicAdd(&g_deg[d4.x], 1);
    atomicAdd(&g_deg[d4.y], 1);
    atomicAdd(&g_deg[d4.z], 1);
    atomicAdd(&g_deg[d4.w], 1);
}

// ---------------- convw + reset (main stream) ---------------------------------
#define CONV_BLKS 112
__global__ void k_convw(const float* __restrict__ W1, const float* __restrict__ W2,
                        const float* __restrict__ as1, const float* __restrict__ ad1,
                        const float* __restrict__ as2, const float* __restrict__ ad2) {
    int b = blockIdx.x, t = threadIdx.x;
    if (b == CONV_BLKS) {                      // reset block
        if (t < NBLK) g_blkst[t] = 0u;
        if (t == 0) {
            g_off[NN] = ET;
            g_mx1[0] = -3.4e38f; g_mx1[1] = -3.4e38f;
            g_mx1[2] = -3.4e38f; g_mx1[3] = -3.4e38f;
            g_mx2 = -3.4e38f;
        }
        return;
    }
    int s = b * 256 + t;                       // weight conversion
    float val; int dsth, dstl;
    if (s < 16384) {
        int k = s >> 7, n = s & 127;
        val = W1[k * 128 + n];
        dsth = k * 144 + n; dstl = 1;
    } else if (s < 17408) {
        int i = s - 16384;
        int k = i >> 3, c = i & 7, h = c >> 1;
        const float* a = (c & 1) ? ad1 : as1;
        float sum = 0.f;
#pragma unroll
        for (int f = 0; f < 32; f++) sum += W1[k * 128 + h * 32 + f] * a[h * 32 + f];
        val = sum; dsth = k * 144 + 128 + c; dstl = 1;
    } else if (s < 18432) {
        int i = s - 17408;
        int k = i >> 3, c = i & 7;
        val = 0.f; dsth = k * 144 + 136 + c; dstl = 1;
    } else if (s < 26624) {
        int i = s - 18432;
        int k = i >> 6, n = i & 63;
        val = W2[k * 64 + n];
        dsth = k * 80 + n; dstl = 2;
    } else if (s < 26880) {
        int i = s - 26624;
        int k = i >> 1, c = i & 1;
        const float* a = c ? ad2 : as2;
        float sum = 0.f;
#pragma unroll
        for (int f = 0; f < 64; f++) sum += W2[k * 64 + f] * a[f];
        val = sum; dsth = k * 80 + 64 + c; dstl = 2;
    } else if (s < 28672) {
        int i = s - 26880;
        int k = i / 14, c = i % 14;
        val = 0.f; dsth = k * 80 + 66 + c; dstl = 2;
    } else return;
    __half hv = __float2half_rn(val);
    if (dstl == 1) g_w1[dsth] = hv;
    else           g_w2[dsth] = hv;
}

// ---------------- single-pass scan with decoupled lookback --------------------
__global__ void k_scan() {
    __shared__ int sh[256];
    __shared__ int s_excl;
    int t = threadIdx.x, b = blockIdx.x;
    int i = b * 256 + t;
    int v = (i < NN) ? g_deg[i] + 1 : 0;   // +1 self loop
    sh[t] = v;
    __syncthreads();
#pragma unroll
    for (int o = 1; o < 256; o <<= 1) {
        int tv = (t >= o) ? sh[t - o] : 0;
        __syncthreads();
        sh[t] += tv;
        __syncthreads();
    }
    int incl = sh[t];
    int total = sh[255];

    if (t == 0) {
        if (b == 0) {
            atomicExch(&g_blkst[0], ((unsigned)total << 2) | 2u);
            s_excl = 0;
        } else {
            atomicExch(&g_blkst[b], ((unsigned)total << 2) | 1u);
            int run = 0;
            for (int p = b - 1; p >= 0; p--) {
                unsigned st;
                do { st = atomicAdd(&g_blkst[p], 0u); } while ((st & 3u) == 0u);
                run += (int)(st >> 2);
                if ((st & 3u) == 2u) break;
            }
            s_excl = run;
            atomicExch(&g_blkst[b], ((unsigned)(run + total) << 2) | 2u);
        }
    }
    __syncthreads();
    if (i < NN) {
        int off = s_excl + incl - v;
        g_off[i] = off;
        g_srcidx[off] = i;      // self loop seeded first
        g_cur[i] = off + 1;
        g_deg[i] = 0;           // restore invariant
    }
}

__global__ void k_fill(const int* __restrict__ ei) {
    int i = blockIdx.x * blockDim.x + threadIdx.x;
    if (i >= NE / 4) return;
    int4 s4 = ((const int4*)ei)[i];
    int4 d4 = ((const int4*)(ei + NE))[i];
    int p;
    p = atomicAdd(&g_cur[d4.x], 1); g_srcidx[p] = s4.x;
    p = atomicAdd(&g_cur[d4.y], 1); g_srcidx[p] = s4.y;
    p = atomicAdd(&g_cur[d4.z], 1); g_srcidx[p] = s4.z;
    p = atomicAdd(&g_cur[d4.w], 1); g_srcidx[p] = s4.w;
}

// ---------------- GEMM1: [h1 | as1 | ad1] = x @ [W1 | W1@P] -------------------
#define LDA 136
#define LDW1 152
#define ST1 148
__global__ __launch_bounds__(256)
void k_gemm1_mma(const float* __restrict__ X) {
    extern __shared__ char raw[];
    __half* sAh = (__half*)raw;
    __half* sAl = sAh + 64 * LDA;
    __half* sW  = (__half*)(raw + 4 * 64 * LDA);
    float*  sX  = (float*)sW;                      // staging aliases sW
    float* stage = (float*)raw;
    int tid = threadIdx.x;
    int row0 = blockIdx.x * 64;

    // stage fp32 X tile (64 x 128) via cp.async
#pragma unroll
    for (int ii = 0; ii < 8; ii++) {
        int i = tid + ii * 256;
        int r = i >> 5, c4 = i & 31;
        if (row0 + r < NN)
            cp16(sX + r * 128 + 4 * c4, (const float4*)X + (size_t)(row0 + r) * 32 + c4);
        else
            *(float4*)(sX + r * 128 + 4 * c4) = make_float4(0.f, 0.f, 0.f, 0.f);
    }
    cp_commit_wait();
    __syncthreads();
    // convert to fp16 hi/lo
#pragma unroll
    for (int ii = 0; ii < 8; ii++) {
        int i = tid + ii * 256;
        int r = i >> 5, c4 = i & 31;
        float4 v = *(const float4*)(sX + r * 128 + 4 * c4);
        __half2 h0 = __floats2half2_rn(v.x, v.y);
        __half2 h1 = __floats2half2_rn(v.z, v.w);
        float2 f0 = __half22float2(h0), f1 = __half22float2(h1);
        __half2 l0 = __floats2half2_rn(v.x - f0.x, v.y - f0.y);
        __half2 l1 = __floats2half2_rn(v.z - f1.x, v.w - f1.y);
        uint2 uh, ul;
        uh.x = *(uint32_t*)&h0; uh.y = *(uint32_t*)&h1;
        ul.x = *(uint32_t*)&l0; ul.y = *(uint32_t*)&l1;
        *(uint2*)(sAh + r * LDA + 4 * c4) = uh;
        *(uint2*)(sAl + r * LDA + 4 * c4) = ul;
    }
    __syncthreads();
    // W over the staging area
    for (int i = tid; i < 2304; i += 256) {
        int k = i / 18, j = i % 18;
        cp16(sW + k * LDW1 + 8 * j, (const uint4*)g_w1 + i);
    }
    cp_commit_wait();
    __syncthreads();

    int w = tid >> 5, wr = w >> 1, wc = w & 1;
    const int nf = wc ? 4 : 5;
    const int col0 = wc * 80;

    wmma::fragment<wmma::accumulator, 16, 16, 16, float> c[5];
#pragma unroll
    for (int j = 0; j < 5; j++) wmma::fill_fragment(c[j], 0.f);

    for (int kk = 0; kk < 128; kk += 16) {
        wmma::fragment<wmma::matrix_a, 16, 16, 16, __half, wmma::row_major> ah, al;
        wmma::load_matrix_sync(ah, sAh + (wr * 16) * LDA + kk, LDA);
        wmma::load_matrix_sync(al, sAl + (wr * 16) * LDA + kk, LDA);
#pragma unroll
        for (int j = 0; j < 5; j++) {
            if (j >= nf) break;
            wmma::fragment<wmma::matrix_b, 16, 16, 16, __half, wmma::row_major> bh;
            wmma::load_matrix_sync(bh, sW + kk * LDW1 + col0 + j * 16, LDW1);
            wmma::mma_sync(c[j], ah, bh, c[j]);
            wmma::mma_sync(c[j], al, bh, c[j]);
        }
    }
    __syncthreads();
#pragma unroll
    for (int j = 0; j < 5; j++) {
        if (j >= nf) break;
        wmma::store_matrix_sync(stage + (wr * 16) * ST1 + col0 + j * 16,
                                c[j], ST1, wmma::mem_row_major);
    }
    __syncthreads();

    // h1 -> fp16
    {
        int r = tid >> 2, q = tid & 3;
        int row = row0 + r;
        if (row < NN) {
            const float* sp = stage + r * ST1 + 32 * q;
            uint4* dp = (uint4*)(g_h1h + (size_t)row * 128 + 32 * q);
#pragma unroll
            for (int u = 0; u < 4; u++) {
                float4 a = *(const float4*)(sp + 8 * u);
                float4 b = *(const float4*)(sp + 8 * u + 4);
                __half2 h0 = __floats2half2_rn(a.x, a.y);
                __half2 h1 = __floats2half2_rn(a.z, a.w);
                __half2 h2 = __floats2half2_rn(b.x, b.y);
                __half2 h3 = __floats2half2_rn(b.z, b.w);
                uint4 uu;
                uu.x = *(uint32_t*)&h0; uu.y = *(uint32_t*)&h1;
                uu.z = *(uint32_t*)&h2; uu.w = *(uint32_t*)&h3;
                dp[u] = uu;
            }
        }
    }
    // alphas + global per-head max of as
    if (tid < 64) {
        int row = row0 + tid;
        const float* sp = stage + tid * ST1 + 128;
        float ps[4];
#pragma unroll
        for (int h = 0; h < 4; h++) {
            float a_ = sp[2 * h], d_ = sp[2 * h + 1];
            if (row < NN) {
                g_as1[row * 4 + h] = a_;
                g_ad1[row * 4 + h] = d_;
                ps[h] = a_;
            } else ps[h] = -3.4e38f;
        }
#pragma unroll
        for (int h = 0; h < 4; h++) {
#pragma unroll
            for (int o = 16; o >= 1; o >>= 1)
                ps[h] = fmaxf(ps[h], __shfl_xor_sync(0xffffffffu, ps[h], o));
        }
        if ((tid & 31) == 0) {
#pragma unroll
            for (int h = 0; h < 4; h++) atomicMaxF(&g_mx1[h], ps[h]);
        }
    }
}

// ---------------- GEMM2: [h2 | as2 | ad2] = o1 @ [W2 | W2@P2] -----------------
#define LDW2 88
#define ST2 84
__global__ __launch_bounds__(256)
void k_gemm2_mma() {
    extern __shared__ char raw[];
    __half* sAh = (__half*)raw;
    __half* sAl = sAh + 64 * LDA;
    __half* sW  = (__half*)(raw + 4 * 64 * LDA);
    float* stage = (float*)raw;
    int tid = threadIdx.x;
    int row0 = blockIdx.x * 64;

    // A via cp.async: 64 rows x 16 uint4 per array
#pragma unroll
    for (int ii = 0; ii < 4; ii++) {
        int i = tid + ii * 256;
        int r = i >> 4, c = i & 15;
        if (row0 + r < NN) {
            cp16(sAh + r * LDA + 8 * c, (const uint4*)g_o1h + (size_t)(row0 + r) * 16 + c);
            cp16(sAl + r * LDA + 8 * c, (const uint4*)g_o1l + (size_t)(row0 + r) * 16 + c);
        } else {
            *(uint4*)(sAh + r * LDA + 8 * c) = make_uint4(0, 0, 0, 0);
            *(uint4*)(sAl + r * LDA + 8 * c) = make_uint4(0, 0, 0, 0);
        }
    }
    // W via cp.async
    for (int i = tid; i < 1280; i += 256) {
        int k = i / 10, j = i % 10;
        cp16(sW + k * LDW2 + 8 * j, (const uint4*)g_w2 + i);
    }
    cp_commit_wait();
    __syncthreads();

    int w = tid >> 5, wr = w >> 1, wc = w & 1;
    const int nf = wc ? 2 : 3;
    const int col0 = wc * 48;

    wmma::fragment<wmma::accumulator, 16, 16, 16, float> c[3];
#pragma unroll
    for (int j = 0; j < 3; j++) wmma::fill_fragment(c[j], 0.f);

    for (int kk = 0; kk < 128; kk += 16) {
        wmma::fragment<wmma::matrix_a, 16, 16, 16, __half, wmma::row_major> ah, al;
        wmma::load_matrix_sync(ah, sAh + (wr * 16) * LDA + kk, LDA);
        wmma::load_matrix_sync(al, sAl + (wr * 16) * LDA + kk, LDA);
#pragma unroll
        for (int j = 0; j < 3; j++) {
            if (j >= nf) break;
            wmma::fragment<wmma::matrix_b, 16, 16, 16, __half, wmma::row_major> bh;
            wmma::load_matrix_sync(bh, sW + kk * LDW2 + col0 + j * 16, LDW2);
            wmma::mma_sync(c[j], ah, bh, c[j]);
            wmma::mma_sync(c[j], al, bh, c[j]);
        }
    }
    __syncthreads();
#pragma unroll
    for (int j = 0; j < 3; j++) {
        if (j >= nf) break;
        wmma::store_matrix_sync(stage + (wr * 16) * ST2 + col0 + j * 16,
                                c[j], ST2, wmma::mem_row_major);
    }
    __syncthreads();

    {
        int r = tid >> 2, q = tid & 3;
        int row = row0 + r;
        if (row < NN) {
            const float* sp = stage + r * ST2 + 16 * q;
            uint4* dp = (uint4*)(g_h2h + (size_t)row * 64 + 16 * q);
#pragma unroll
            for (int u = 0; u < 2; u++) {
                float4 a = *(const float4*)(sp + 8 * u);
                float4 b = *(const float4*)(sp + 8 * u + 4);
                __half2 h0 = __floats2half2_rn(a.x, a.y);
                __half2 h1 = __floats2half2_rn(a.z, a.w);
                __half2 h2 = __floats2half2_rn(b.x, b.y);
                __half2 h3 = __floats2half2_rn(b.z, b.w);
                uint4 uu;
                uu.x = *(uint32_t*)&h0; uu.y = *(uint32_t*)&h1;
                uu.z = *(uint32_t*)&h2; uu.w = *(uint32_t*)&h3;
                dp[u] = uu;
            }
        }
    }
    if (tid < 64) {
        int row = row0 + tid;
        float ps;
        if (row < NN) {
            ps = stage[tid * ST2 + 64];
            g_as2[row] = ps;
            g_ad2[row] = stage[tid * ST2 + 65];
        } else ps = -3.4e38f;
#pragma unroll
        for (int o = 16; o >= 1; o >>= 1)
            ps = fmaxf(ps, __shfl_xor_sync(0xffffffffu, ps, o));
        if ((tid & 31) == 0) atomicMaxF(&g_mx2, ps);
    }
}

// ---------------- gather1: 2 edges/warp, depth-2 pipeline ---------------------
__global__ __launch_bounds__(256)
void k_gather1(const float* __restrict__ b1) {
    int n = blockIdx.x * 8 + (threadIdx.x >> 5);
    if (n >= NN) return;
    int lane = threadIdx.x & 31;
    int g = lane >> 4, li = lane & 15;
    int head = li >> 2;
    float adh = g_ad1[4 * n + head];
    int beg = g_off[n], end = g_off[n + 1];

    float mh = lrelu(g_mx1[head] + adh);

    float acc[8];
#pragma unroll
    for (int q = 0; q < 8; q++) acc[q] = 0.f;
    float den = 0.f;

    int j0 = beg + g;
    float aA = 0.f, aB = 0.f;
    uint4 uA = make_uint4(0, 0, 0, 0), uB = make_uint4(0, 0, 0, 0);
    if (j0 < end) {
        int s = g_srcidx[j0];
        aA = g_as1[4 * s + head];
        uA = *(const uint4*)(g_h1h + (size_t)s * 128 + 8 * li);
    }
    if (j0 + 2 < end) {
        int s = g_srcidx[j0 + 2];
        aB = g_as1[4 * s + head];
        uB = *(const uint4*)(g_h1h + (size_t)s * 128 + 8 * li);
    }
    for (int j = j0; j < end; j += 2) {
        float aC = 0.f; uint4 uC = make_uint4(0, 0, 0, 0);
        if (j + 4 < end) {
            int s = g_srcidx[j + 4];
            aC = g_as1[4 * s + head];
            uC = *(const uint4*)(g_h1h + (size_t)s * 128 + 8 * li);
        }
        float w = __expf(lrelu(aA + adh) - mh);
        den += w;
        const __half2* hp = (const __half2*)&uA;
#pragma unroll
        for (int q = 0; q < 4; q++) {
            float2 f = __half22float2(hp[q]);
            acc[2 * q] += w * f.x;
            acc[2 * q + 1] += w * f.y;
        }
        aA = aB; uA = uB;
        aB = aC; uB = uC;
    }
    den += __shfl_xor_sync(0xffffffffu, den, 16);
#pragma unroll
    for (int q = 0; q < 8; q++) acc[q] += __shfl_xor_sync(0xffffffffu, acc[q], 16);

    if (g == 0) {
        float inv = 1.f / (den + 1e-16f);
        float4 b0 = *(const float4*)(b1 + 8 * li);
        float4 b4 = *(const float4*)(b1 + 8 * li + 4);
        float v[8];
        v[0] = fmaxf(acc[0] * inv + b0.x, 0.f); v[1] = fmaxf(acc[1] * inv + b0.y, 0.f);
        v[2] = fmaxf(acc[2] * inv + b0.z, 0.f); v[3] = fmaxf(acc[3] * inv + b0.w, 0.f);
        v[4] = fmaxf(acc[4] * inv + b4.x, 0.f); v[5] = fmaxf(acc[5] * inv + b4.y, 0.f);
        v[6] = fmaxf(acc[6] * inv + b4.z, 0.f); v[7] = fmaxf(acc[7] * inv + b4.w, 0.f);
        uint4 uh, ul;
        uint32_t* uhp = (uint32_t*)&uh;
        uint32_t* ulp = (uint32_t*)&ul;
#pragma unroll
        for (int q = 0; q < 4; q++) {
            __half2 h = __floats2half2_rn(v[2 * q], v[2 * q + 1]);
            float2 f = __half22float2(h);
            __half2 l = __floats2half2_rn(v[2 * q] - f.x, v[2 * q + 1] - f.y);
            uhp[q] = *(uint32_t*)&h;
            ulp[q] = *(uint32_t*)&l;
        }
        *(uint4*)(g_o1h + (size_t)n * 128 + 8 * li) = uh;
        *(uint4*)(g_o1l + (size_t)n * 128 + 8 * li) = ul;
    }
}

// ---------------- gather2: 4 edges/warp, depth-2 pipeline ---------------------
__global__ __launch_bounds__(256)
void k_gather2(const float* __restrict__ b2, float* __restrict__ out) {
    int n = blockIdx.x * 8 + (threadIdx.x >> 5);
    if (n >= NN) return;
    int lane = threadIdx.x & 31;
    int g = lane >> 3, li = lane & 7;
    float adh = g_ad2[n];
    int beg = g_off[n], end = g_off[n + 1];

    float mh = lrelu(g_mx2 + adh);

    float acc[8];
#pragma unroll
    for (int q = 0; q < 8; q++) acc[q] = 0.f;
    float den = 0.f;

    int j0 = beg + g;
    float aA = 0.f, aB = 0.f;
    uint4 uA = make_uint4(0, 0, 0, 0), uB = make_uint4(0, 0, 0, 0);
    if (j0 < end) {
        int s = g_srcidx[j0];
        aA = g_as2[s];
        uA = *(const uint4*)(g_h2h + (size_t)s * 64 + 8 * li);
    }
    if (j0 + 4 < end) {
        int s = g_srcidx[j0 + 4];
        aB = g_as2[s];
        uB = *(const uint4*)(g_h2h + (size_t)s * 64 + 8 * li);
    }
    for (int j = j0; j < end; j += 4) {
        float aC = 0.f; uint4 uC = make_uint4(0, 0, 0, 0);
        if (j + 8 < end) {
            int s = g_srcidx[j + 8];
            aC = g_as2[s];
            uC = *(const uint4*)(g_h2h + (size_t)s * 64 + 8 * li);
        }
        float w = __expf(lrelu(aA + adh) - mh);
        den += w;
        const __half2* hp = (const __half2*)&uA;
#pragma unroll
        for (int q = 0; q < 4; q++) {
            float2 f = __half22float2(hp[q]);
            acc[2 * q] += w * f.x;
            acc[2 * q + 1] += w * f.y;
        }
        aA = aB; uA = uB;
        aB = aC; uB = uC;
    }
    den += __shfl_xor_sync(0xffffffffu, den, 8);
    den += __shfl_xor_sync(0xffffffffu, den, 16);
#pragma unroll
    for (int q = 0; q < 8; q++) {
        acc[q] += __shfl_xor_sync(0xffffffffu, acc[q], 8);
        acc[q] += __shfl_xor_sync(0xffffffffu, acc[q], 16);
    }

    if (g == 0) {
        float inv = 1.f / (den + 1e-16f);
        float4 b0 = *(const float4*)(b2 + 8 * li);
        float4 b4 = *(const float4*)(b2 + 8 * li + 4);
        float* op = out + (size_t)n * 64 + 8 * li;
        *(float4*)op = make_float4(acc[0] * inv + b0.x, acc[1] * inv + b0.y,
                                   acc[2] * inv + b0.z, acc[3] * inv + b0.w);
        *(float4*)(op + 4) = make_float4(acc[4] * inv + b4.x, acc[5] * inv + b4.y,
                                         acc[6] * inv + b4.z, acc[7] * inv + b4.w);
    }
}

// ---------------- launch ------------------------------------------------------
extern "C" void kernel_launch(void* const* d_in, const int* in_sizes, int n_in,
                              void* d_out, int out_size) {
    const float* x   = (const float*)d_in[0];
    const int*   ei  = (const int*)d_in[1];
    const float* W1  = (const float*)d_in[2];
    const float* as1 = (const float*)d_in[3];
    const float* ad1 = (const float*)d_in[4];
    const float* b1  = (const float*)d_in[5];
    const float* W2  = (const float*)d_in[6];
    const float* as2 = (const float*)d_in[7];
    const float* ad2 = (const float*)d_in[8];
    const float* b2  = (const float*)d_in[9];
    float* out = (float*)d_out;

    const int smem1 = 4 * 64 * LDA + 2 * 128 * LDW1;   // 73728
    const int smem2 = 4 * 64 * LDA + 2 * 128 * LDW2;   // 57344
    static cudaStream_t s_side = nullptr;
    static cudaEvent_t ev0 = nullptr, evC = nullptr, evS = nullptr;
    if (!s_side) {
        cudaFuncSetAttribute(k_gemm1_mma, cudaFuncAttributeMaxDynamicSharedMemorySize, smem1);
        cudaFuncSetAttribute(k_gemm2_mma, cudaFuncAttributeMaxDynamicSharedMemorySize, smem2);
        cudaStreamCreateWithFlags(&s_side, cudaStreamNonBlocking);
        cudaEventCreateWithFlags(&ev0, cudaEventDisableTiming);
        cudaEventCreateWithFlags(&evC, cudaEventDisableTiming);
        cudaEventCreateWithFlags(&evS, cudaEventDisableTiming);
    }

    // fork at t=0: hist on side (needs only ei)
    cudaEventRecord(ev0, 0);
    cudaStreamWaitEvent(s_side, ev0, 0);
    k_hist<<<HIST_BLKS, 256, 0, s_side>>>(ei);

    // main: convw + reset (W, blkst, mx)
    k_convw<<<CONV_BLKS + 1, 256>>>(W1, W2, as1, ad1, as2, ad2);
    cudaEventRecord(evC, 0);

    // side: scan (needs hist in side order + reset via evC), fill
    cudaStreamWaitEvent(s_side, evC, 0);
    k_scan<<<NBLK, 256, 0, s_side>>>();
    k_fill<<<(NE / 4 + 255) / 256, 256, 0, s_side>>>(ei);
    cudaEventRecord(evS, s_side);

    // main: gemm1 (needs convw) runs concurrent with side CSR chain
    k_gemm1_mma<<<NP / 64, 256, smem1>>>(x);

    // join: gather1 needs gemm1 (main) + fill (side)
    cudaStreamWaitEvent(0, evS, 0);
    k_gather1<<<(NN + 7) / 8, 256>>>(b1);

    // layer 2 (serial chain)
    k_gemm2_mma<<<NP / 64, 256, smem2>>>();
    k_gather2<<<(NN + 7) / 8, 256>>>(b2, out);
}